// round 9
// baseline (speedup 1.0000x reference)
#include <cuda_runtime.h>
#include <cuda_bf16.h>

#define BB 4
#define SS 2048
#define EE 1024

typedef __nv_bfloat16 bf16;

// ---------------------------------------------------------------------------
// Scratch (device globals — no allocation allowed)
// ---------------------------------------------------------------------------
__device__ float g_sc[(size_t)BB * SS * SS];
__device__ float g_m[BB * SS], g_inv[BB * SS];
__device__ bf16 g_xh[(size_t)BB * SS * EE], g_xl[(size_t)BB * SS * EE];
__device__ bf16 g_Wh[3 * (size_t)EE * EE], g_Wl[3 * (size_t)EE * EE];
__device__ bf16 g_qh[(size_t)BB * SS * EE], g_ql[(size_t)BB * SS * EE];
__device__ bf16 g_kh[(size_t)BB * SS * EE], g_kl[(size_t)BB * SS * EE];
__device__ bf16 g_vh[(size_t)BB * SS * EE], g_vl[(size_t)BB * SS * EE];
__device__ bf16 g_vTh[(size_t)BB * EE * SS], g_vTl[(size_t)BB * EE * SS];

// ---------------------------------------------------------------------------
// PTX helpers (baseline sm_80+ features only — plain sm_103 target)
// ---------------------------------------------------------------------------
__device__ __forceinline__ unsigned smem_u32(const void* p) {
    unsigned a;
    asm("{ .reg .u64 t; cvta.to.shared.u64 t, %1; cvt.u32.u64 %0, t; }"
        : "=r"(a) : "l"(p));
    return a;
}
__device__ __forceinline__ void cp16(unsigned dst, const void* src) {
    asm volatile("cp.async.cg.shared.global [%0], [%1], 16;"
                 :: "r"(dst), "l"(src) : "memory");
}
__device__ __forceinline__ void cp_commit() {
    asm volatile("cp.async.commit_group;" ::: "memory");
}
__device__ __forceinline__ void cp_wait1() {
    asm volatile("cp.async.wait_group 1;" ::: "memory");
}
__device__ __forceinline__ void cp_wait0() {
    asm volatile("cp.async.wait_group 0;" ::: "memory");
}
__device__ __forceinline__ void ldsm4(unsigned& r0, unsigned& r1, unsigned& r2,
                                      unsigned& r3, unsigned addr) {
    asm volatile("ldmatrix.sync.aligned.m8n8.x4.shared.b16 {%0,%1,%2,%3}, [%4];"
                 : "=r"(r0), "=r"(r1), "=r"(r2), "=r"(r3) : "r"(addr));
}
__device__ __forceinline__ void mma16816(float* d, const unsigned* a,
                                         unsigned b0, unsigned b1) {
    asm volatile(
        "mma.sync.aligned.m16n8k16.row.col.f32.bf16.bf16.f32 "
        "{%0,%1,%2,%3}, {%4,%5,%6,%7}, {%8,%9}, {%0,%1,%2,%3};"
        : "+f"(d[0]), "+f"(d[1]), "+f"(d[2]), "+f"(d[3])
        : "r"(a[0]), "r"(a[1]), "r"(a[2]), "r"(a[3]), "r"(b0), "r"(b1));
}

// ---------------------------------------------------------------------------
// Tile layout: 128 rows x 32 bf16 = 64B rows, XOR-swizzled 16B units.
// Per stage: 4 tiles [Ah, Al, Bh, Bl]. 3 stages = 96KB -> 2 CTAs/SM.
// ---------------------------------------------------------------------------
#define TILE_B 8192
#define NSTAGE 3
#define SMEM_BYTES (NSTAGE * 4 * TILE_B)    // 98304
#define SWOFF(row, c) ((row) * 64 + (((c) ^ (((row) >> 1) & 3)) << 4))

// ===========================================================================
// 128-thread path (qkv, scores): 2x2 warps of 64x64 — MMA:LDSM = 6:1
// ===========================================================================
__device__ __forceinline__ void compute_tiles64(unsigned smBase, int buf,
                                                int wm, int wn, int lane,
                                                float acc[4][8][4])
{
    const unsigned tb = smBase + buf * (4 * TILE_B);
    const int lrow = lane & 15;
    const int lcu = lane >> 4;
    #pragma unroll
    for (int ks = 0; ks < 2; ks++) {
        const int cu = ks * 2 + lcu;
        unsigned ah[4][4], al[4][4], bh[4][4], bl[4][4];
        #pragma unroll
        for (int mi = 0; mi < 4; mi++) {
            int row = wm * 64 + mi * 16 + lrow;
            unsigned off = SWOFF(row, cu);
            ldsm4(ah[mi][0], ah[mi][1], ah[mi][2], ah[mi][3], tb + 0 * TILE_B + off);
            ldsm4(al[mi][0], al[mi][1], al[mi][2], al[mi][3], tb + 1 * TILE_B + off);
        }
        #pragma unroll
        for (int nj = 0; nj < 4; nj++) {
            int row = wn * 64 + nj * 16 + lrow;
            unsigned off = SWOFF(row, cu);
            ldsm4(bh[nj][0], bh[nj][1], bh[nj][2], bh[nj][3], tb + 2 * TILE_B + off);
            ldsm4(bl[nj][0], bl[nj][1], bl[nj][2], bl[nj][3], tb + 3 * TILE_B + off);
        }
        // pass 1: Ah*Bh
        #pragma unroll
        for (int mi = 0; mi < 4; mi++)
            #pragma unroll
            for (int nj = 0; nj < 4; nj++) {
                mma16816(acc[mi][2 * nj],     ah[mi], bh[nj][0], bh[nj][2]);
                mma16816(acc[mi][2 * nj + 1], ah[mi], bh[nj][1], bh[nj][3]);
            }
        // pass 2: Al*Bh
        #pragma unroll
        for (int mi = 0; mi < 4; mi++)
            #pragma unroll
            for (int nj = 0; nj < 4; nj++) {
                mma16816(acc[mi][2 * nj],     al[mi], bh[nj][0], bh[nj][2]);
                mma16816(acc[mi][2 * nj + 1], al[mi], bh[nj][1], bh[nj][3]);
            }
        // pass 3: Ah*Bl
        #pragma unroll
        for (int mi = 0; mi < 4; mi++)
            #pragma unroll
            for (int nj = 0; nj < 4; nj++) {
                mma16816(acc[mi][2 * nj],     ah[mi], bl[nj][0], bl[nj][2]);
                mma16816(acc[mi][2 * nj + 1], ah[mi], bl[nj][1], bl[nj][3]);
            }
    }
}

// 128-thread cp.async loader for all 4 bf16 tiles
__device__ __forceinline__ void load_tiles128(unsigned smBase, int buf,
    const bf16* Ah, const bf16* Al, int lda,
    const bf16* Bh, const bf16* Bl, int ldb,
    int rowBase, int colBase, int kt, int tid)
{
    const unsigned dstb = smBase + buf * (4 * TILE_B);
    const char* srcA_h = (const char*)(Ah + (size_t)rowBase * lda + kt);
    const char* srcA_l = (const char*)(Al + (size_t)rowBase * lda + kt);
    const char* srcB_h = (const char*)(Bh + (size_t)colBase * ldb + kt);
    const char* srcB_l = (const char*)(Bl + (size_t)colBase * ldb + kt);
    const size_t strA = (size_t)lda * 2, strB = (size_t)ldb * 2;
    #pragma unroll
    for (int i = 0; i < 16; i++) {
        const int tile = i >> 2;
        int within = tid + (i & 3) * 128;
        int row = within >> 2, c = within & 3;
        const char* src = (tile == 0) ? srcA_h + row * strA + c * 16
                        : (tile == 1) ? srcA_l + row * strA + c * 16
                        : (tile == 2) ? srcB_h + row * strB + c * 16
                                      : srcB_l + row * strB + c * 16;
        cp16(dstb + tile * TILE_B + SWOFF(row, c), src);
    }
}

__device__ __forceinline__ void gemm_mainloop128(
    const bf16* __restrict__ Ah, const bf16* __restrict__ Al, int lda,
    const bf16* __restrict__ Bh, const bf16* __restrict__ Bl, int ldb,
    int kEnd, int rowBase, int colBase, unsigned smBase, float acc[4][8][4])
{
    const int tid = threadIdx.x;
    const int lane = tid & 31, wid = tid >> 5;
    const int wm = wid & 1, wn = wid >> 1;
    const int kTiles = kEnd >> 5;

    load_tiles128(smBase, 0, Ah, Al, lda, Bh, Bl, ldb, rowBase, colBase, 0, tid);
    cp_commit();
    if (kTiles > 1) {
        load_tiles128(smBase, 1, Ah, Al, lda, Bh, Bl, ldb, rowBase, colBase, 32, tid);
        cp_commit();
    }

    int buf = 0;
    for (int it = 0; it < kTiles; ++it) {
        if (it + 1 < kTiles) cp_wait1(); else cp_wait0();
        __syncthreads();
        if (it + 2 < kTiles) {
            int nb = buf + 2; if (nb >= NSTAGE) nb -= NSTAGE;
            load_tiles128(smBase, nb, Ah, Al, lda, Bh, Bl, ldb,
                          rowBase, colBase, (it + 2) << 5, tid);
            cp_commit();
        }
        compute_tiles64(smBase, buf, wm, wn, lane, acc);
        if (++buf == NSTAGE) buf = 0;
    }
}

// ===========================================================================
// 256-thread path (av only): warps 4x2 of 32x64 (score-prefetch regs fit)
// ===========================================================================
__device__ __forceinline__ void compute_tiles(unsigned smBase, int buf,
                                              int wm, int wn, int lane,
                                              float acc[2][8][4])
{
    const unsigned tb = smBase + buf * (4 * TILE_B);
    const int lrow = lane & 15;
    const int lcu = lane >> 4;
    #pragma unroll
    for (int ks = 0; ks < 2; ks++) {
        const int cu = ks * 2 + lcu;
        unsigned ah[2][4], al[2][4], bh[4][4], bl[4][4];
        #pragma unroll
        for (int mi = 0; mi < 2; mi++) {
            int row = wm * 32 + mi * 16 + lrow;
            unsigned off = SWOFF(row, cu);
            ldsm4(ah[mi][0], ah[mi][1], ah[mi][2], ah[mi][3], tb + 0 * TILE_B + off);
            ldsm4(al[mi][0], al[mi][1], al[mi][2], al[mi][3], tb + 1 * TILE_B + off);
        }
        #pragma unroll
        for (int nj = 0; nj < 4; nj++) {
            int row = wn * 64 + nj * 16 + lrow;
            unsigned off = SWOFF(row, cu);
            ldsm4(bh[nj][0], bh[nj][1], bh[nj][2], bh[nj][3], tb + 2 * TILE_B + off);
            ldsm4(bl[nj][0], bl[nj][1], bl[nj][2], bl[nj][3], tb + 3 * TILE_B + off);
        }
        #pragma unroll
        for (int mi = 0; mi < 2; mi++)
            #pragma unroll
            for (int nj = 0; nj < 4; nj++) {
                mma16816(acc[mi][2 * nj],     ah[mi], bh[nj][0], bh[nj][2]);
                mma16816(acc[mi][2 * nj + 1], ah[mi], bh[nj][1], bh[nj][3]);
            }
        #pragma unroll
        for (int mi = 0; mi < 2; mi++)
            #pragma unroll
            for (int nj = 0; nj < 4; nj++) {
                mma16816(acc[mi][2 * nj],     al[mi], bh[nj][0], bh[nj][2]);
                mma16816(acc[mi][2 * nj + 1], al[mi], bh[nj][1], bh[nj][3]);
            }
        #pragma unroll
        for (int mi = 0; mi < 2; mi++)
            #pragma unroll
            for (int nj = 0; nj < 4; nj++) {
                mma16816(acc[mi][2 * nj],     ah[mi], bl[nj][0], bl[nj][2]);
                mma16816(acc[mi][2 * nj + 1], ah[mi], bl[nj][1], bl[nj][3]);
            }
    }
}

// ---------------------------------------------------------------------------
// Stage 0: one merged hi/lo split for x, Wq, Wk, Wv
// ---------------------------------------------------------------------------
__global__ void split_all(const float* __restrict__ x,
                          const float* __restrict__ Wq,
                          const float* __restrict__ Wk,
                          const float* __restrict__ Wv)
{
    const size_t NX4 = (size_t)BB * SS * EE / 4;
    const size_t NW4 = (size_t)EE * EE / 4;
    size_t i4 = (size_t)blockIdx.x * 256 + threadIdx.x;
    const float* src;
    bf16 *dh, *dl;
    size_t off;
    if (i4 < NX4) {
        src = x; dh = g_xh; dl = g_xl; off = i4 * 4;
    } else {
        size_t j = i4 - NX4;
        int w = (int)(j / NW4);
        off = (j - (size_t)w * NW4) * 4;
        src = (w == 0) ? Wq : (w == 1) ? Wk : Wv;
        dh = g_Wh + (size_t)w * EE * EE;
        dl = g_Wl + (size_t)w * EE * EE;
    }
    float4 v = *(const float4*)(src + off);
    bf16 h0 = __float2bfloat16(v.x), h1 = __float2bfloat16(v.y);
    bf16 h2 = __float2bfloat16(v.z), h3 = __float2bfloat16(v.w);
    bf16 l0 = __float2bfloat16(v.x - __bfloat162float(h0));
    bf16 l1 = __float2bfloat16(v.y - __bfloat162float(h1));
    bf16 l2 = __float2bfloat16(v.z - __bfloat162float(h2));
    bf16 l3 = __float2bfloat16(v.w - __bfloat162float(h3));
    *(__nv_bfloat162*)(dh + off)     = __halves2bfloat162(h0, h1);
    *(__nv_bfloat162*)(dh + off + 2) = __halves2bfloat162(h2, h3);
    *(__nv_bfloat162*)(dl + off)     = __halves2bfloat162(l0, l1);
    *(__nv_bfloat162*)(dl + off + 2) = __halves2bfloat162(l2, l3);
}

// ---------------------------------------------------------------------------
// Stage 1: QKV projections. grid (8, 64, 3), 128 threads
// ---------------------------------------------------------------------------
__global__ void __launch_bounds__(128, 2) qkv_gemm(
    const float* __restrict__ bq, const float* __restrict__ bk,
    const float* __restrict__ bv)
{
    extern __shared__ char smc[];
    unsigned smBase = smem_u32(smc);
    const int tid = threadIdx.x, lane = tid & 31, wid = tid >> 5;
    const int wm = wid & 1, wn = wid >> 1;
    const int z = blockIdx.z;
    const int rowBase = blockIdx.y * 128, colBase = blockIdx.x * 128;

    const bf16* Bh = g_Wh + (size_t)z * EE * EE;
    const bf16* Bl = g_Wl + (size_t)z * EE * EE;
    const float* bias = (z == 0) ? bq : (z == 1) ? bk : bv;
    bf16* oh = (z == 0) ? g_qh : (z == 1) ? g_kh : g_vh;
    bf16* ol = (z == 0) ? g_ql : (z == 1) ? g_kl : g_vl;
    const float alpha = (z == 0) ? 0.03125f : 1.0f;

    float acc[4][8][4] = {};
    gemm_mainloop128(g_xh, g_xl, EE, Bh, Bl, EE, EE, rowBase, colBase, smBase, acc);

    #pragma unroll
    for (int mi = 0; mi < 4; mi++)
        #pragma unroll
        for (int ni = 0; ni < 8; ni++) {
            int col = colBase + wn * 64 + ni * 8 + (lane & 3) * 2;
            float b0 = bias[col], b1 = bias[col + 1];
            #pragma unroll
            for (int h = 0; h < 2; h++) {
                int row = rowBase + wm * 64 + mi * 16 + (lane >> 2) + h * 8;
                float y0 = (acc[mi][ni][2 * h]     + b0) * alpha;
                float y1 = (acc[mi][ni][2 * h + 1] + b1) * alpha;
                bf16 h0 = __float2bfloat16(y0), h1 = __float2bfloat16(y1);
                bf16 l0 = __float2bfloat16(y0 - __bfloat162float(h0));
                bf16 l1 = __float2bfloat16(y1 - __bfloat162float(h1));
                size_t off = (size_t)row * EE + col;
                *(__nv_bfloat162*)(oh + off) = __halves2bfloat162(h0, h1);
                *(__nv_bfloat162*)(ol + off) = __halves2bfloat162(l0, l1);
            }
        }
}

// ---------------------------------------------------------------------------
// Stage 2: scores = q_scaled @ k^T. Compact triangular grid (136,1,4), 128 thr
// ---------------------------------------------------------------------------
__global__ void __launch_bounds__(128, 2) scores_gemm()
{
    extern __shared__ char smc[];
    unsigned smBase = smem_u32(smc);
    const int tid = threadIdx.x, lane = tid & 31, wid = tid >> 5;
    const int wm = wid & 1, wn = wid >> 1;
    const int z = blockIdx.z;

    int idx = blockIdx.x;
    int by = (int)((sqrtf(8.0f * idx + 1.0f) - 1.0f) * 0.5f);
    while ((by + 1) * (by + 2) / 2 <= idx) by++;
    while (by * (by + 1) / 2 > idx) by--;
    int bx = idx - by * (by + 1) / 2;

    const int rowBase = by * 128, colBase = bx * 128;

    float acc[4][8][4] = {};
    gemm_mainloop128(g_qh + (size_t)z * SS * EE, g_ql + (size_t)z * SS * EE, EE,
                     g_kh + (size_t)z * SS * EE, g_kl + (size_t)z * SS * EE, EE,
                     EE, rowBase, colBase, smBase, acc);

    float* out = g_sc + (size_t)z * SS * SS;
    #pragma unroll
    for (int mi = 0; mi < 4; mi++)
        #pragma unroll
        for (int ni = 0; ni < 8; ni++) {
            int col = colBase + wn * 64 + ni * 8 + (lane & 3) * 2;
            #pragma unroll
            for (int h = 0; h < 2; h++) {
                int row = rowBase + wm * 64 + mi * 16 + (lane >> 2) + h * 8;
                *(float2*)(out + (size_t)row * SS + col) =
                    make_float2(acc[mi][ni][2 * h], acc[mi][ni][2 * h + 1]);
            }
        }
}

// ---------------------------------------------------------------------------
// Stage 2b: per-row softmax stats (max, 1/sumexp). grid B*S
// ---------------------------------------------------------------------------
__global__ void stats_kernel()
{
    const int rowg = blockIdx.x;
    const int b = rowg >> 11;
    const int i = rowg & (SS - 1);
    const float* p = g_sc + (size_t)b * SS * SS + (size_t)i * SS;
    const int L = i + 1;

    __shared__ float red[8], red2[8];
    const int t = threadIdx.x, lane = t & 31, w = t >> 5;

    float m = -1e30f;
    for (int j = t; j < L; j += 256) m = fmaxf(m, p[j]);
    #pragma unroll
    for (int o = 16; o; o >>= 1) m = fmaxf(m, __shfl_xor_sync(~0u, m, o));
    if (lane == 0) red[w] = m;
    __syncthreads();
    m = red[0];
    #pragma unroll
    for (int ww = 1; ww < 8; ww++) m = fmaxf(m, red[ww]);

    float s = 0.0f;
    for (int j = t; j < L; j += 256) s += __expf(p[j] - m);
    #pragma unroll
    for (int o = 16; o; o >>= 1) s += __shfl_xor_sync(~0u, s, o);
    if (lane == 0) red2[w] = s;
    __syncthreads();
    s = red2[0];
    #pragma unroll
    for (int ww = 1; ww < 8; ww++) s += red2[ww];

    if (t == 0) {
        g_m[rowg] = m;
        g_inv[rowg] = 1.0f / s;
    }
}

// ---------------------------------------------------------------------------
// Stage 3: out = P @ vT with fused softmax. grid (8, 16, 4), 256 threads
// ---------------------------------------------------------------------------
__global__ void __launch_bounds__(256, 2) av_gemm(float* __restrict__ gout)
{
    extern __shared__ char smc[];
    unsigned smBase = smem_u32(smc);
    const int tid = threadIdx.x, lane = tid & 31, wid = tid >> 5;
    const int wm = wid & 3, wn = wid >> 2;
    const int z = blockIdx.z;
    const int by = 15 - blockIdx.y;            // long CTAs first
    const int rowBase = by * 128, colBase = blockIdx.x * 128;
    const int kTiles = (by + 1) * 4;

    const bf16* Bh = g_vTh + (size_t)z * EE * SS;
    const bf16* Bl = g_vTl + (size_t)z * EE * SS;
    const float* sc = g_sc + (size_t)z * SS * SS;

    const int r = tid >> 1, ch = (tid & 1) * 16;
    const int grow = rowBase + r;
    const float rm = g_m[z * SS + grow];
    const float rinv = g_inv[z * SS + grow];
    const float* srow = sc + (size_t)grow * SS + ch;

    auto load_B = [&](int buf, int kt) {
        const unsigned dstb = smBase + buf * (4 * TILE_B);
        const char* sBh = (const char*)(Bh + (size_t)colBase * SS + kt);
        const char* sBl = (const char*)(Bl + (size_t)colBase * SS + kt);
        const size_t str = (size_t)SS * 2;
        #pragma unroll
        for (int i = 0; i < 4; i++) {
            const int tile = 2 + (i >> 1);
            int within = tid + (i & 1) * 256;
            int row = within >> 2, c = within & 3;
            const char* src = (tile == 2) ? sBh + row * str + c * 16
                                          : sBl + row * str + c * 16;
            cp16(dstb + tile * TILE_B + SWOFF(row, c), src);
        }
    };
    float4 sreg[4];
    auto ldg_A = [&](int kt) {
        const float* s0 = srow + kt;
        #pragma unroll
        for (int j = 0; j < 4; j++) sreg[j] = *(const float4*)(s0 + j * 4);
    };
    auto sts_A = [&](int buf, int kt) {
        char* base = smc + buf * (4 * TILE_B);
        const int sw = ((r >> 1) & 3);
        #pragma unroll
        for (int j = 0; j < 4; j++) {
            float sv[4] = {sreg[j].x, sreg[j].y, sreg[j].z, sreg[j].w};
            float pv[4];
            #pragma unroll
            for (int e = 0; e < 4; e++) {
                int gcol = kt + ch + j * 4 + e;
                pv[e] = (gcol <= grow) ? __expf(sv[e] - rm) * rinv : 0.0f;
            }
            bf16 h0 = __float2bfloat16(pv[0]), h1 = __float2bfloat16(pv[1]);
            bf16 h2 = __float2bfloat16(pv[2]), h3 = __float2bfloat16(pv[3]);
            bf16 l0 = __float2bfloat16(pv[0] - __bfloat162float(h0));
            bf16 l1 = __float2bfloat16(pv[1] - __bfloat162float(h1));
            bf16 l2 = __float2bfloat16(pv[2] - __bfloat162float(h2));
            bf16 l3 = __float2bfloat16(pv[3] - __bfloat162float(h3));
            int ccb = ch + j * 4;
            int unit = ccb >> 3;
            int boff = r * 64 + ((unit ^ sw) << 4) + (ccb & 7) * 2;
            *(__nv_bfloat162*)(base + 0 * TILE_B + boff)     = __halves2bfloat162(h0, h1);
            *(__nv_bfloat162*)(base + 0 * TILE_B + boff + 4) = __halves2bfloat162(h2, h3);
            *(__nv_bfloat162*)(base + 1 * TILE_B + boff)     = __halves2bfloat162(l0, l1);
            *(__nv_bfloat162*)(base + 1 * TILE_B + boff + 4) = __halves2bfloat162(l2, l3);
        }
    };

    float acc[2][8][4] = {};

    load_B(0, 0);
    cp_commit();
    ldg_A(0);
    if (kTiles > 1) {
        load_B(1, 32);
        cp_commit();
    }

    int buf = 0;
    for (int it = 0; it < kTiles; ++it) {
        sts_A(buf, it << 5);
        if (it + 1 < kTiles) cp_wait1(); else cp_wait0();
        __syncthreads();
        if (it + 2 < kTiles) {
            int nb = buf + 2; if (nb >= NSTAGE) nb -= NSTAGE;
            load_B(nb, (it + 2) << 5);
            cp_commit();
        }
        if (it + 1 < kTiles) ldg_A((it + 1) << 5);
        compute_tiles(smBase, buf, wm, wn, lane, acc);
        if (++buf == NSTAGE) buf = 0;
    }

    float* out = gout + (size_t)z * SS * EE;
    #pragma unroll
    for (int mi = 0; mi < 2; mi++)
        #pragma unroll
        for (int ni = 0; ni < 8; ni++) {
            int col = colBase + wn * 64 + ni * 8 + (lane & 3) * 2;
            #pragma unroll
            for (int h = 0; h < 2; h++) {
                int row = rowBase + wm * 32 + mi * 16 + (lane >> 2) + h * 8;
                *(float2*)(out + (size_t)row * EE + col) =
                    make_float2(acc[mi][ni][2 * h], acc[mi][ni][2 * h + 1]);
            }
        }
}

// ---------------------------------------------------------------------------
// Transpose v (per batch): [S, E] -> [E, S], hi and lo
// ---------------------------------------------------------------------------
__global__ void transpose_v()
{
    __shared__ bf16 th[32][33], tl[32][33];
    const int z = blockIdx.z;
    const int s0 = blockIdx.x * 32, e0 = blockIdx.y * 32;
    const int tx = threadIdx.x, ty = threadIdx.y;
    #pragma unroll
    for (int j = 0; j < 32; j += 8) {
        size_t src = ((size_t)z * SS + s0 + ty + j) * EE + e0 + tx;
        th[ty + j][tx] = g_vh[src];
        tl[ty + j][tx] = g_vl[src];
    }
    __syncthreads();
    #pragma unroll
    for (int j = 0; j < 32; j += 8) {
        size_t dst = ((size_t)z * EE + e0 + ty + j) * SS + s0 + tx;
        g_vTh[dst] = th[tx][ty + j];
        g_vTl[dst] = tl[tx][ty + j];
    }
}

// ---------------------------------------------------------------------------
// Launch
// ---------------------------------------------------------------------------
extern "C" void kernel_launch(void* const* d_in, const int* in_sizes, int n_in,
                              void* d_out, int out_size)
{
    const float* x  = (const float*)d_in[0];
    const float* Wq = (const float*)d_in[2];
    const float* bq = (const float*)d_in[3];
    const float* Wk = (const float*)d_in[4];
    const float* bk = (const float*)d_in[5];
    const float* Wv = (const float*)d_in[6];
    const float* bv = (const float*)d_in[7];
    float* out = (float*)d_out;

    static bool attr_done = false;
    if (!attr_done) {
        cudaFuncSetAttribute(qkv_gemm,    cudaFuncAttributeMaxDynamicSharedMemorySize, SMEM_BYTES);
        cudaFuncSetAttribute(scores_gemm, cudaFuncAttributeMaxDynamicSharedMemorySize, SMEM_BYTES);
        cudaFuncSetAttribute(av_gemm,     cudaFuncAttributeMaxDynamicSharedMemorySize, SMEM_BYTES);
        attr_done = true;
    }

    const int splitBlocks = (BB * SS * EE / 4 + 3 * (EE * EE / 4)) / 256;
    split_all<<<splitBlocks, 256>>>(x, Wq, Wk, Wv);

    qkv_gemm<<<dim3(EE / 128, (BB * SS) / 128, 3), 128, SMEM_BYTES>>>(bq, bk, bv);

    transpose_v<<<dim3(SS / 32, EE / 32, BB), dim3(32, 8)>>>();

    scores_gemm<<<dim3(136, 1, BB), 128, SMEM_BYTES>>>();

    stats_kernel<<<BB * SS, 256>>>();

    av_gemm<<<dim3(EE / 128, SS / 128, BB), 256, SMEM_BYTES>>>(out);
}

// round 10
// speedup vs baseline: 1.4693x; 1.4693x over previous
#include <cuda_runtime.h>
#include <cuda_fp16.h>

#define BB 4
#define SS 2048
#define EE 1024

typedef __half fp16;

// ---------------------------------------------------------------------------
// Scratch (device globals — no allocation allowed)
// ---------------------------------------------------------------------------
__device__ float g_sc[(size_t)BB * SS * SS];
__device__ float g_m[BB * SS], g_inv[BB * SS];
__device__ fp16 g_xh[(size_t)BB * SS * EE], g_xl[(size_t)BB * SS * EE];
__device__ fp16 g_Wf[3 * (size_t)EE * EE];
__device__ fp16 g_qh[(size_t)BB * SS * EE], g_ql[(size_t)BB * SS * EE];
__device__ fp16 g_k[(size_t)BB * SS * EE];
__device__ fp16 g_v[(size_t)BB * SS * EE];
__device__ fp16 g_vT[(size_t)BB * EE * SS];

// ---------------------------------------------------------------------------
// PTX helpers (baseline sm_80+ features only — plain sm_103 target)
// ---------------------------------------------------------------------------
__device__ __forceinline__ unsigned smem_u32(const void* p) {
    unsigned a;
    asm("{ .reg .u64 t; cvta.to.shared.u64 t, %1; cvt.u32.u64 %0, t; }"
        : "=r"(a) : "l"(p));
    return a;
}
__device__ __forceinline__ void cp16(unsigned dst, const void* src) {
    asm volatile("cp.async.cg.shared.global [%0], [%1], 16;"
                 :: "r"(dst), "l"(src) : "memory");
}
__device__ __forceinline__ void cp_commit() {
    asm volatile("cp.async.commit_group;" ::: "memory");
}
__device__ __forceinline__ void cp_wait1() {
    asm volatile("cp.async.wait_group 1;" ::: "memory");
}
__device__ __forceinline__ void cp_wait0() {
    asm volatile("cp.async.wait_group 0;" ::: "memory");
}
__device__ __forceinline__ void ldsm4(unsigned& r0, unsigned& r1, unsigned& r2,
                                      unsigned& r3, unsigned addr) {
    asm volatile("ldmatrix.sync.aligned.m8n8.x4.shared.b16 {%0,%1,%2,%3}, [%4];"
                 : "=r"(r0), "=r"(r1), "=r"(r2), "=r"(r3) : "r"(addr));
}
__device__ __forceinline__ void mma16816(float* d, const unsigned* a,
                                         unsigned b0, unsigned b1) {
    asm volatile(
        "mma.sync.aligned.m16n8k16.row.col.f32.f16.f16.f32 "
        "{%0,%1,%2,%3}, {%4,%5,%6,%7}, {%8,%9}, {%0,%1,%2,%3};"
        : "+f"(d[0]), "+f"(d[1]), "+f"(d[2]), "+f"(d[3])
        : "r"(a[0]), "r"(a[1]), "r"(a[2]), "r"(a[3]), "r"(b0), "r"(b1));
}

// ---------------------------------------------------------------------------
// Tile layout: 128 rows x 32 fp16 = 64B rows, XOR-swizzled 16B units.
// Per stage: 3 tiles [Ah, Al, B]. 3 stages = 72KB -> 2 CTAs/SM.
// ---------------------------------------------------------------------------
#define TILE_B 8192
#define STAGE_B (3 * TILE_B)
#define NSTAGE 3
#define SMEM_BYTES (NSTAGE * STAGE_B)       // 73728
#define SWOFF(row, c) ((row) * 64 + (((c) ^ (((row) >> 1) & 3)) << 4))

// 2-pass compute on one buffered k-tile: acc += Ah*B + Al*B
__device__ __forceinline__ void compute_tiles(unsigned smBase, int buf,
                                              int wm, int wn, int lane,
                                              float acc[2][8][4])
{
    const unsigned tb = smBase + buf * STAGE_B;
    const int lrow = lane & 15;
    const int lcu = lane >> 4;
    #pragma unroll
    for (int ks = 0; ks < 2; ks++) {
        const int cu = ks * 2 + lcu;
        unsigned ah[2][4], al[2][4], b[4][4];
        #pragma unroll
        for (int mi = 0; mi < 2; mi++) {
            int row = wm * 32 + mi * 16 + lrow;
            unsigned off = SWOFF(row, cu);
            ldsm4(ah[mi][0], ah[mi][1], ah[mi][2], ah[mi][3], tb + 0 * TILE_B + off);
            ldsm4(al[mi][0], al[mi][1], al[mi][2], al[mi][3], tb + 1 * TILE_B + off);
        }
        #pragma unroll
        for (int nj = 0; nj < 4; nj++) {
            int row = wn * 64 + nj * 16 + lrow;
            unsigned off = SWOFF(row, cu);
            ldsm4(b[nj][0], b[nj][1], b[nj][2], b[nj][3], tb + 2 * TILE_B + off);
        }
        // pass 1: Ah * B
        #pragma unroll
        for (int mi = 0; mi < 2; mi++)
            #pragma unroll
            for (int nj = 0; nj < 4; nj++) {
                mma16816(acc[mi][2 * nj],     ah[mi], b[nj][0], b[nj][2]);
                mma16816(acc[mi][2 * nj + 1], ah[mi], b[nj][1], b[nj][3]);
            }
        // pass 2: Al * B
        #pragma unroll
        for (int mi = 0; mi < 2; mi++)
            #pragma unroll
            for (int nj = 0; nj < 4; nj++) {
                mma16816(acc[mi][2 * nj],     al[mi], b[nj][0], b[nj][2]);
                mma16816(acc[mi][2 * nj + 1], al[mi], b[nj][1], b[nj][3]);
            }
    }
}

// cp.async loader for 3 fp16 tiles (Ah, Al, B), 256 threads
__device__ __forceinline__ void load_tiles3(unsigned smBase, int buf,
    const fp16* Ah, const fp16* Al, int lda,
    const fp16* B, int ldb,
    int rowBase, int colBase, int kt, int tid)
{
    const unsigned dstb = smBase + buf * STAGE_B;
    const char* srcA_h = (const char*)(Ah + (size_t)rowBase * lda + kt);
    const char* srcA_l = (const char*)(Al + (size_t)rowBase * lda + kt);
    const char* srcB   = (const char*)(B + (size_t)colBase * ldb + kt);
    const size_t strA = (size_t)lda * 2, strB = (size_t)ldb * 2;
    #pragma unroll
    for (int i = 0; i < 6; i++) {
        const int tile = i >> 1;
        int within = tid + (i & 1) * 256;
        int row = within >> 2, c = within & 3;
        const char* src = (tile == 0) ? srcA_h + row * strA + c * 16
                        : (tile == 1) ? srcA_l + row * strA + c * 16
                                      : srcB   + row * strB + c * 16;
        cp16(dstb + tile * TILE_B + SWOFF(row, c), src);
    }
}

// fp16 2-pass GEMM mainloop: 3-stage pipeline, ONE barrier per k-iter
__device__ __forceinline__ void gemm_mainloop(
    const fp16* __restrict__ Ah, const fp16* __restrict__ Al, int lda,
    const fp16* __restrict__ B, int ldb,
    int kEnd, int rowBase, int colBase, unsigned smBase, float acc[2][8][4])
{
    const int tid = threadIdx.x;
    const int lane = tid & 31, wid = tid >> 5;
    const int wm = wid & 3, wn = wid >> 2;
    const int kTiles = kEnd >> 5;

    load_tiles3(smBase, 0, Ah, Al, lda, B, ldb, rowBase, colBase, 0, tid);
    cp_commit();
    if (kTiles > 1) {
        load_tiles3(smBase, 1, Ah, Al, lda, B, ldb, rowBase, colBase, 32, tid);
        cp_commit();
    }

    int buf = 0;
    for (int it = 0; it < kTiles; ++it) {
        if (it + 1 < kTiles) cp_wait1(); else cp_wait0();
        __syncthreads();
        if (it + 2 < kTiles) {
            int nb = buf + 2; if (nb >= NSTAGE) nb -= NSTAGE;
            load_tiles3(smBase, nb, Ah, Al, lda, B, ldb,
                        rowBase, colBase, (it + 2) << 5, tid);
            cp_commit();
        }
        compute_tiles(smBase, buf, wm, wn, lane, acc);
        if (++buf == NSTAGE) buf = 0;
    }
}

// ---------------------------------------------------------------------------
// Stage 0: split x into fp16 hi/lo; round Wq/Wk/Wv to single fp16
// ---------------------------------------------------------------------------
__global__ void split_all(const float* __restrict__ x,
                          const float* __restrict__ Wq,
                          const float* __restrict__ Wk,
                          const float* __restrict__ Wv)
{
    const size_t NX4 = (size_t)BB * SS * EE / 4;
    const size_t NW4 = (size_t)EE * EE / 4;
    size_t i4 = (size_t)blockIdx.x * 256 + threadIdx.x;
    if (i4 < NX4) {
        size_t off = i4 * 4;
        float4 v = *(const float4*)(x + off);
        fp16 h0 = __float2half(v.x), h1 = __float2half(v.y);
        fp16 h2 = __float2half(v.z), h3 = __float2half(v.w);
        fp16 l0 = __float2half(v.x - __half2float(h0));
        fp16 l1 = __float2half(v.y - __half2float(h1));
        fp16 l2 = __float2half(v.z - __half2float(h2));
        fp16 l3 = __float2half(v.w - __half2float(h3));
        *(__half2*)(g_xh + off)     = __halves2half2(h0, h1);
        *(__half2*)(g_xh + off + 2) = __halves2half2(h2, h3);
        *(__half2*)(g_xl + off)     = __halves2half2(l0, l1);
        *(__half2*)(g_xl + off + 2) = __halves2half2(l2, l3);
    } else {
        size_t j = i4 - NX4;
        int w = (int)(j / NW4);
        size_t off = (j - (size_t)w * NW4) * 4;
        const float* src = (w == 0) ? Wq : (w == 1) ? Wk : Wv;
        fp16* dst = g_Wf + (size_t)w * EE * EE + off;
        float4 v = *(const float4*)(src + off);
        *(__half2*)(dst)     = __halves2half2(__float2half(v.x), __float2half(v.y));
        *(__half2*)(dst + 2) = __halves2half2(__float2half(v.z), __float2half(v.w));
    }
}

// ---------------------------------------------------------------------------
// Stage 1: QKV projections. grid (8, 64, 3), 256 threads
// q (z=0): hi/lo fp16, pre-scaled 1/32. k, v: single fp16.
// ---------------------------------------------------------------------------
__global__ void __launch_bounds__(256, 2) qkv_gemm(
    const float* __restrict__ bq, const float* __restrict__ bk,
    const float* __restrict__ bv)
{
    extern __shared__ char smc[];
    unsigned smBase = smem_u32(smc);
    const int tid = threadIdx.x, lane = tid & 31, wid = tid >> 5;
    const int wm = wid & 3, wn = wid >> 2;
    const int z = blockIdx.z;
    const int rowBase = blockIdx.y * 128, colBase = blockIdx.x * 128;

    const fp16* Bf = g_Wf + (size_t)z * EE * EE;
    const float* bias = (z == 0) ? bq : (z == 1) ? bk : bv;
    fp16* oh = (z == 0) ? g_qh : (z == 1) ? g_k : g_v;
    fp16* ol = (z == 0) ? g_ql : nullptr;
    const float alpha = (z == 0) ? 0.03125f : 1.0f;

    float acc[2][8][4] = {};
    gemm_mainloop(g_xh, g_xl, EE, Bf, EE, EE, rowBase, colBase, smBase, acc);

    #pragma unroll
    for (int mi = 0; mi < 2; mi++)
        #pragma unroll
        for (int ni = 0; ni < 8; ni++) {
            int col = colBase + wn * 64 + ni * 8 + (lane & 3) * 2;
            float b0 = bias[col], b1 = bias[col + 1];
            #pragma unroll
            for (int h = 0; h < 2; h++) {
                int row = rowBase + wm * 32 + mi * 16 + (lane >> 2) + h * 8;
                float y0 = (acc[mi][ni][2 * h]     + b0) * alpha;
                float y1 = (acc[mi][ni][2 * h + 1] + b1) * alpha;
                fp16 h0 = __float2half(y0), h1 = __float2half(y1);
                size_t off = (size_t)row * EE + col;
                *(__half2*)(oh + off) = __halves2half2(h0, h1);
                if (ol) {
                    fp16 l0 = __float2half(y0 - __half2float(h0));
                    fp16 l1 = __float2half(y1 - __half2float(h1));
                    *(__half2*)(ol + off) = __halves2half2(l0, l1);
                }
            }
        }
}

// ---------------------------------------------------------------------------
// Stage 2: scores = q_scaled @ k^T. Compact triangular grid (136,1,4)
// ---------------------------------------------------------------------------
__global__ void __launch_bounds__(256, 2) scores_gemm()
{
    extern __shared__ char smc[];
    unsigned smBase = smem_u32(smc);
    const int tid = threadIdx.x, lane = tid & 31, wid = tid >> 5;
    const int wm = wid & 3, wn = wid >> 2;
    const int z = blockIdx.z;

    int idx = blockIdx.x;
    int by = (int)((sqrtf(8.0f * idx + 1.0f) - 1.0f) * 0.5f);
    while ((by + 1) * (by + 2) / 2 <= idx) by++;
    while (by * (by + 1) / 2 > idx) by--;
    int bx = idx - by * (by + 1) / 2;

    const int rowBase = by * 128, colBase = bx * 128;

    float acc[2][8][4] = {};
    gemm_mainloop(g_qh + (size_t)z * SS * EE, g_ql + (size_t)z * SS * EE, EE,
                  g_k + (size_t)z * SS * EE, EE,
                  EE, rowBase, colBase, smBase, acc);

    float* out = g_sc + (size_t)z * SS * SS;
    #pragma unroll
    for (int mi = 0; mi < 2; mi++)
        #pragma unroll
        for (int ni = 0; ni < 8; ni++) {
            int col = colBase + wn * 64 + ni * 8 + (lane & 3) * 2;
            #pragma unroll
            for (int h = 0; h < 2; h++) {
                int row = rowBase + wm * 32 + mi * 16 + (lane >> 2) + h * 8;
                *(float2*)(out + (size_t)row * SS + col) =
                    make_float2(acc[mi][ni][2 * h], acc[mi][ni][2 * h + 1]);
            }
        }
}

// ---------------------------------------------------------------------------
// Stage 2b: per-row softmax stats (max, 1/sumexp). grid B*S
// ---------------------------------------------------------------------------
__global__ void stats_kernel()
{
    const int rowg = blockIdx.x;
    const int b = rowg >> 11;
    const int i = rowg & (SS - 1);
    const float* p = g_sc + (size_t)b * SS * SS + (size_t)i * SS;
    const int L = i + 1;

    __shared__ float red[8], red2[8];
    const int t = threadIdx.x, lane = t & 31, w = t >> 5;

    float m = -1e30f;
    for (int j = t; j < L; j += 256) m = fmaxf(m, p[j]);
    #pragma unroll
    for (int o = 16; o; o >>= 1) m = fmaxf(m, __shfl_xor_sync(~0u, m, o));
    if (lane == 0) red[w] = m;
    __syncthreads();
    m = red[0];
    #pragma unroll
    for (int ww = 1; ww < 8; ww++) m = fmaxf(m, red[ww]);

    float s = 0.0f;
    for (int j = t; j < L; j += 256) s += __expf(p[j] - m);
    #pragma unroll
    for (int o = 16; o; o >>= 1) s += __shfl_xor_sync(~0u, s, o);
    if (lane == 0) red2[w] = s;
    __syncthreads();
    s = red2[0];
    #pragma unroll
    for (int ww = 1; ww < 8; ww++) s += red2[ww];

    if (t == 0) {
        g_m[rowg] = m;
        g_inv[rowg] = 1.0f / s;
    }
}

// ---------------------------------------------------------------------------
// Stage 3: out = P @ vT with fused softmax. grid (8, 16, 4), 256 threads
// P split to fp16 hi/lo in registers -> smem tiles 0/1; vT single -> tile 2.
// ---------------------------------------------------------------------------
__global__ void __launch_bounds__(256, 2) av_gemm(float* __restrict__ gout)
{
    extern __shared__ char smc[];
    unsigned smBase = smem_u32(smc);
    const int tid = threadIdx.x, lane = tid & 31, wid = tid >> 5;
    const int wm = wid & 3, wn = wid >> 2;
    const int z = blockIdx.z;
    const int by = 15 - blockIdx.y;            // long CTAs first
    const int rowBase = by * 128, colBase = blockIdx.x * 128;
    const int kTiles = (by + 1) * 4;

    const fp16* Bv = g_vT + (size_t)z * EE * SS;
    const float* sc = g_sc + (size_t)z * SS * SS;

    const int r = tid >> 1, ch = (tid & 1) * 16;
    const int grow = rowBase + r;
    const float rm = g_m[z * SS + grow];
    const float rinv = g_inv[z * SS + grow];
    const float* srow = sc + (size_t)grow * SS + ch;

    auto load_B = [&](int buf, int kt) {
        const unsigned dstb = smBase + buf * STAGE_B;
        const char* sB = (const char*)(Bv + (size_t)colBase * SS + kt);
        const size_t str = (size_t)SS * 2;
        #pragma unroll
        for (int i = 0; i < 2; i++) {
            int within = tid + i * 256;
            int row = within >> 2, c = within & 3;
            cp16(dstb + 2 * TILE_B + SWOFF(row, c), sB + row * str + c * 16);
        }
    };
    float4 sreg[4];
    auto ldg_A = [&](int kt) {
        const float* s0 = srow + kt;
        #pragma unroll
        for (int j = 0; j < 4; j++) sreg[j] = *(const float4*)(s0 + j * 4);
    };
    auto sts_A = [&](int buf, int kt) {
        char* base = smc + buf * STAGE_B;
        const int sw = ((r >> 1) & 3);
        #pragma unroll
        for (int j = 0; j < 4; j++) {
            float sv[4] = {sreg[j].x, sreg[j].y, sreg[j].z, sreg[j].w};
            float pv[4];
            #pragma unroll
            for (int e = 0; e < 4; e++) {
                int gcol = kt + ch + j * 4 + e;
                pv[e] = (gcol <= grow) ? __expf(sv[e] - rm) * rinv : 0.0f;
            }
            fp16 h0 = __float2half(pv[0]), h1 = __float2half(pv[1]);
            fp16 h2 = __float2half(pv[2]), h3 = __float2half(pv[3]);
            fp16 l0 = __float2half(pv[0] - __half2float(h0));
            fp16 l1 = __float2half(pv[1] - __half2float(h1));
            fp16 l2 = __float2half(pv[2] - __half2float(h2));
            fp16 l3 = __float2half(pv[3] - __half2float(h3));
            int ccb = ch + j * 4;
            int unit = ccb >> 3;
            int boff = r * 64 + ((unit ^ sw) << 4) + (ccb & 7) * 2;
            *(__half2*)(base + 0 * TILE_B + boff)     = __halves2half2(h0, h1);
            *(__half2*)(base + 0 * TILE_B + boff + 4) = __halves2half2(h2, h3);
            *(__half2*)(base + 1 * TILE_B + boff)     = __halves2half2(l0, l1);
            *(__half2*)(base + 1 * TILE_B + boff + 4) = __halves2half2(l2, l3);
        }
    };

    float acc[2][8][4] = {};

    load_B(0, 0);
    cp_commit();
    ldg_A(0);
    if (kTiles > 1) {
        load_B(1, 32);
        cp_commit();
    }

    int buf = 0;
    for (int it = 0; it < kTiles; ++it) {
        sts_A(buf, it << 5);
        if (it + 1 < kTiles) cp_wait1(); else cp_wait0();
        __syncthreads();
        if (it + 2 < kTiles) {
            int nb = buf + 2; if (nb >= NSTAGE) nb -= NSTAGE;
            load_B(nb, (it + 2) << 5);
            cp_commit();
        }
        if (it + 1 < kTiles) ldg_A((it + 1) << 5);
        compute_tiles(smBase, buf, wm, wn, lane, acc);
        if (++buf == NSTAGE) buf = 0;
    }

    float* out = gout + (size_t)z * SS * EE;
    #pragma unroll
    for (int mi = 0; mi < 2; mi++)
        #pragma unroll
        for (int ni = 0; ni < 8; ni++) {
            int col = colBase + wn * 64 + ni * 8 + (lane & 3) * 2;
            #pragma unroll
            for (int h = 0; h < 2; h++) {
                int row = rowBase + wm * 32 + mi * 16 + (lane >> 2) + h * 8;
                *(float2*)(out + (size_t)row * EE + col) =
                    make_float2(acc[mi][ni][2 * h], acc[mi][ni][2 * h + 1]);
            }
        }
}

// ---------------------------------------------------------------------------
// Transpose v (per batch): [S, E] -> [E, S]
// ---------------------------------------------------------------------------
__global__ void transpose_v()
{
    __shared__ fp16 th[32][33];
    const int z = blockIdx.z;
    const int s0 = blockIdx.x * 32, e0 = blockIdx.y * 32;
    const int tx = threadIdx.x, ty = threadIdx.y;
    #pragma unroll
    for (int j = 0; j < 32; j += 8) {
        size_t src = ((size_t)z * SS + s0 + ty + j) * EE + e0 + tx;
        th[ty + j][tx] = g_v[src];
    }
    __syncthreads();
    #pragma unroll
    for (int j = 0; j < 32; j += 8) {
        size_t dst = ((size_t)z * EE + e0 + ty + j) * SS + s0 + tx;
        g_vT[dst] = th[tx][ty + j];
    }
}

// ---------------------------------------------------------------------------
// Launch
// ---------------------------------------------------------------------------
extern "C" void kernel_launch(void* const* d_in, const int* in_sizes, int n_in,
                              void* d_out, int out_size)
{
    const float* x  = (const float*)d_in[0];
    const float* Wq = (const float*)d_in[2];
    const float* bq = (const float*)d_in[3];
    const float* Wk = (const float*)d_in[4];
    const float* bk = (const float*)d_in[5];
    const float* Wv = (const float*)d_in[6];
    const float* bv = (const float*)d_in[7];
    float* out = (float*)d_out;

    static bool attr_done = false;
    if (!attr_done) {
        cudaFuncSetAttribute(qkv_gemm,    cudaFuncAttributeMaxDynamicSharedMemorySize, SMEM_BYTES);
        cudaFuncSetAttribute(scores_gemm, cudaFuncAttributeMaxDynamicSharedMemorySize, SMEM_BYTES);
        cudaFuncSetAttribute(av_gemm,     cudaFuncAttributeMaxDynamicSharedMemorySize, SMEM_BYTES);
        attr_done = true;
    }

    const int splitBlocks = (BB * SS * EE / 4 + 3 * (EE * EE / 4)) / 256;
    split_all<<<splitBlocks, 256>>>(x, Wq, Wk, Wv);

    qkv_gemm<<<dim3(EE / 128, (BB * SS) / 128, 3), 256, SMEM_BYTES>>>(bq, bk, bv);

    transpose_v<<<dim3(SS / 32, EE / 32, BB), dim3(32, 8)>>>();

    scores_gemm<<<dim3(136, 1, BB), 256, SMEM_BYTES>>>();

    stats_kernel<<<BB * SS, 256>>>();

    av_gemm<<<dim3(EE / 128, SS / 128, BB), 256, SMEM_BYTES>>>(out);
}

// round 11
// speedup vs baseline: 2.0490x; 1.3945x over previous
#include <cuda_runtime.h>
#include <cuda_fp16.h>

#define BB 4
#define SS 2048
#define EE 1024

typedef __half fp16;

// ---------------------------------------------------------------------------
// Scratch (device globals — no allocation allowed)
// ---------------------------------------------------------------------------
__device__ float g_sc[(size_t)BB * SS * SS];
__device__ float g_m[BB * SS], g_inv[BB * SS];
__device__ fp16 g_x[(size_t)BB * SS * EE];
__device__ fp16 g_Wf[3 * (size_t)EE * EE];
__device__ fp16 g_qh[(size_t)BB * SS * EE], g_ql[(size_t)BB * SS * EE];
__device__ fp16 g_k[(size_t)BB * SS * EE];
__device__ fp16 g_v[(size_t)BB * SS * EE];
__device__ fp16 g_vT[(size_t)BB * EE * SS];

// ---------------------------------------------------------------------------
// PTX helpers (baseline sm_80+ features only — plain sm_103 target)
// ---------------------------------------------------------------------------
__device__ __forceinline__ unsigned smem_u32(const void* p) {
    unsigned a;
    asm("{ .reg .u64 t; cvta.to.shared.u64 t, %1; cvt.u32.u64 %0, t; }"
        : "=r"(a) : "l"(p));
    return a;
}
__device__ __forceinline__ void cp16(unsigned dst, const void* src) {
    asm volatile("cp.async.cg.shared.global [%0], [%1], 16;"
                 :: "r"(dst), "l"(src) : "memory");
}
__device__ __forceinline__ void cp_commit() {
    asm volatile("cp.async.commit_group;" ::: "memory");
}
__device__ __forceinline__ void cp_wait1() {
    asm volatile("cp.async.wait_group 1;" ::: "memory");
}
__device__ __forceinline__ void cp_wait0() {
    asm volatile("cp.async.wait_group 0;" ::: "memory");
}
__device__ __forceinline__ void ldsm4(unsigned& r0, unsigned& r1, unsigned& r2,
                                      unsigned& r3, unsigned addr) {
    asm volatile("ldmatrix.sync.aligned.m8n8.x4.shared.b16 {%0,%1,%2,%3}, [%4];"
                 : "=r"(r0), "=r"(r1), "=r"(r2), "=r"(r3) : "r"(addr));
}
__device__ __forceinline__ void mma16816(float* d, const unsigned* a,
                                         unsigned b0, unsigned b1) {
    asm volatile(
        "mma.sync.aligned.m16n8k16.row.col.f32.f16.f16.f32 "
        "{%0,%1,%2,%3}, {%4,%5,%6,%7}, {%8,%9}, {%0,%1,%2,%3};"
        : "+f"(d[0]), "+f"(d[1]), "+f"(d[2]), "+f"(d[3])
        : "r"(a[0]), "r"(a[1]), "r"(a[2]), "r"(a[3]), "r"(b0), "r"(b1));
}

// ---------------------------------------------------------------------------
// Tile: 128 rows x 32 fp16 = 64B rows, XOR-swizzled 16B units.
// 1-pass stages: 2 tiles [A, B]   -> 16KB/stage, 3 stages = 48KB
// 2-pass stages: 3 tiles [Ah,Al,B]-> 24KB/stage, 3 stages = 72KB
// ---------------------------------------------------------------------------
#define TILE_B 8192
#define NSTAGE 3
#define STAGE1 (2 * TILE_B)
#define STAGE2 (3 * TILE_B)
#define SMEM1 (NSTAGE * STAGE1)             // 49152
#define SMEM2 (NSTAGE * STAGE2)             // 73728
#define SWOFF(row, c) ((row) * 64 + (((c) ^ (((row) >> 1) & 3)) << 4))

// ---- 1-pass compute: acc += A * B --------------------------------------
__device__ __forceinline__ void compute_1p(unsigned smBase, int buf,
                                           int wm, int wn, int lane,
                                           float acc[2][8][4])
{
    const unsigned tb = smBase + buf * STAGE1;
    const int lrow = lane & 15;
    const int lcu = lane >> 4;
    #pragma unroll
    for (int ks = 0; ks < 2; ks++) {
        const int cu = ks * 2 + lcu;
        unsigned a[2][4], b[4][4];
        #pragma unroll
        for (int mi = 0; mi < 2; mi++) {
            int row = wm * 32 + mi * 16 + lrow;
            ldsm4(a[mi][0], a[mi][1], a[mi][2], a[mi][3],
                  tb + SWOFF(row, cu));
        }
        #pragma unroll
        for (int nj = 0; nj < 4; nj++) {
            int row = wn * 64 + nj * 16 + lrow;
            ldsm4(b[nj][0], b[nj][1], b[nj][2], b[nj][3],
                  tb + TILE_B + SWOFF(row, cu));
        }
        #pragma unroll
        for (int mi = 0; mi < 2; mi++)
            #pragma unroll
            for (int nj = 0; nj < 4; nj++) {
                mma16816(acc[mi][2 * nj],     a[mi], b[nj][0], b[nj][2]);
                mma16816(acc[mi][2 * nj + 1], a[mi], b[nj][1], b[nj][3]);
            }
    }
}

// ---- 2-pass compute: acc += Ah*B + Al*B ---------------------------------
__device__ __forceinline__ void compute_2p(unsigned smBase, int buf,
                                           int wm, int wn, int lane,
                                           float acc[2][8][4])
{
    const unsigned tb = smBase + buf * STAGE2;
    const int lrow = lane & 15;
    const int lcu = lane >> 4;
    #pragma unroll
    for (int ks = 0; ks < 2; ks++) {
        const int cu = ks * 2 + lcu;
        unsigned ah[2][4], al[2][4], b[4][4];
        #pragma unroll
        for (int mi = 0; mi < 2; mi++) {
            int row = wm * 32 + mi * 16 + lrow;
            unsigned off = SWOFF(row, cu);
            ldsm4(ah[mi][0], ah[mi][1], ah[mi][2], ah[mi][3], tb + off);
            ldsm4(al[mi][0], al[mi][1], al[mi][2], al[mi][3], tb + TILE_B + off);
        }
        #pragma unroll
        for (int nj = 0; nj < 4; nj++) {
            int row = wn * 64 + nj * 16 + lrow;
            ldsm4(b[nj][0], b[nj][1], b[nj][2], b[nj][3],
                  tb + 2 * TILE_B + SWOFF(row, cu));
        }
        #pragma unroll
        for (int mi = 0; mi < 2; mi++)
            #pragma unroll
            for (int nj = 0; nj < 4; nj++) {
                mma16816(acc[mi][2 * nj],     ah[mi], b[nj][0], b[nj][2]);
                mma16816(acc[mi][2 * nj + 1], ah[mi], b[nj][1], b[nj][3]);
            }
        #pragma unroll
        for (int mi = 0; mi < 2; mi++)
            #pragma unroll
            for (int nj = 0; nj < 4; nj++) {
                mma16816(acc[mi][2 * nj],     al[mi], b[nj][0], b[nj][2]);
                mma16816(acc[mi][2 * nj + 1], al[mi], b[nj][1], b[nj][3]);
            }
    }
}

// ---- loaders -------------------------------------------------------------
__device__ __forceinline__ void load_1p(unsigned smBase, int buf,
    const fp16* A, int lda, const fp16* B, int ldb,
    int rowBase, int colBase, int kt, int tid)
{
    const unsigned dstb = smBase + buf * STAGE1;
    const char* srcA = (const char*)(A + (size_t)rowBase * lda + kt);
    const char* srcB = (const char*)(B + (size_t)colBase * ldb + kt);
    const size_t strA = (size_t)lda * 2, strB = (size_t)ldb * 2;
    #pragma unroll
    for (int i = 0; i < 4; i++) {
        const int tile = i >> 1;
        int within = tid + (i & 1) * 256;
        int row = within >> 2, c = within & 3;
        const char* src = (tile == 0) ? srcA + row * strA + c * 16
                                      : srcB + row * strB + c * 16;
        cp16(dstb + tile * TILE_B + SWOFF(row, c), src);
    }
}

__device__ __forceinline__ void load_2p(unsigned smBase, int buf,
    const fp16* Ah, const fp16* Al, int lda, const fp16* B, int ldb,
    int rowBase, int colBase, int kt, int tid)
{
    const unsigned dstb = smBase + buf * STAGE2;
    const char* srcA_h = (const char*)(Ah + (size_t)rowBase * lda + kt);
    const char* srcA_l = (const char*)(Al + (size_t)rowBase * lda + kt);
    const char* srcB   = (const char*)(B + (size_t)colBase * ldb + kt);
    const size_t strA = (size_t)lda * 2, strB = (size_t)ldb * 2;
    #pragma unroll
    for (int i = 0; i < 6; i++) {
        const int tile = i >> 1;
        int within = tid + (i & 1) * 256;
        int row = within >> 2, c = within & 3;
        const char* src = (tile == 0) ? srcA_h + row * strA + c * 16
                        : (tile == 1) ? srcA_l + row * strA + c * 16
                                      : srcB   + row * strB + c * 16;
        cp16(dstb + tile * TILE_B + SWOFF(row, c), src);
    }
}

// ---- mainloops -----------------------------------------------------------
__device__ __forceinline__ void mainloop_1p(
    const fp16* __restrict__ A, int lda, const fp16* __restrict__ B, int ldb,
    int kEnd, int rowBase, int colBase, unsigned smBase, float acc[2][8][4])
{
    const int tid = threadIdx.x;
    const int lane = tid & 31, wid = tid >> 5;
    const int wm = wid & 3, wn = wid >> 2;
    const int kTiles = kEnd >> 5;

    load_1p(smBase, 0, A, lda, B, ldb, rowBase, colBase, 0, tid);
    cp_commit();
    if (kTiles > 1) {
        load_1p(smBase, 1, A, lda, B, ldb, rowBase, colBase, 32, tid);
        cp_commit();
    }
    int buf = 0;
    for (int it = 0; it < kTiles; ++it) {
        if (it + 1 < kTiles) cp_wait1(); else cp_wait0();
        __syncthreads();
        if (it + 2 < kTiles) {
            int nb = buf + 2; if (nb >= NSTAGE) nb -= NSTAGE;
            load_1p(smBase, nb, A, lda, B, ldb, rowBase, colBase,
                    (it + 2) << 5, tid);
            cp_commit();
        }
        compute_1p(smBase, buf, wm, wn, lane, acc);
        if (++buf == NSTAGE) buf = 0;
    }
}

__device__ __forceinline__ void mainloop_2p(
    const fp16* __restrict__ Ah, const fp16* __restrict__ Al, int lda,
    const fp16* __restrict__ B, int ldb,
    int kEnd, int rowBase, int colBase, unsigned smBase, float acc[2][8][4])
{
    const int tid = threadIdx.x;
    const int lane = tid & 31, wid = tid >> 5;
    const int wm = wid & 3, wn = wid >> 2;
    const int kTiles = kEnd >> 5;

    load_2p(smBase, 0, Ah, Al, lda, B, ldb, rowBase, colBase, 0, tid);
    cp_commit();
    if (kTiles > 1) {
        load_2p(smBase, 1, Ah, Al, lda, B, ldb, rowBase, colBase, 32, tid);
        cp_commit();
    }
    int buf = 0;
    for (int it = 0; it < kTiles; ++it) {
        if (it + 1 < kTiles) cp_wait1(); else cp_wait0();
        __syncthreads();
        if (it + 2 < kTiles) {
            int nb = buf + 2; if (nb >= NSTAGE) nb -= NSTAGE;
            load_2p(smBase, nb, Ah, Al, lda, B, ldb, rowBase, colBase,
                    (it + 2) << 5, tid);
            cp_commit();
        }
        compute_2p(smBase, buf, wm, wn, lane, acc);
        if (++buf == NSTAGE) buf = 0;
    }
}

// ---------------------------------------------------------------------------
// Stage 0: round x and Wq/Wk/Wv to fp16
// ---------------------------------------------------------------------------
__global__ void split_all(const float* __restrict__ x,
                          const float* __restrict__ Wq,
                          const float* __restrict__ Wk,
                          const float* __restrict__ Wv)
{
    const size_t NX4 = (size_t)BB * SS * EE / 4;
    const size_t NW4 = (size_t)EE * EE / 4;
    size_t i4 = (size_t)blockIdx.x * 256 + threadIdx.x;
    const float* src;
    fp16* dst;
    size_t off;
    if (i4 < NX4) {
        off = i4 * 4;
        src = x;
        dst = g_x + off;
    } else {
        size_t j = i4 - NX4;
        int w = (int)(j / NW4);
        off = (j - (size_t)w * NW4) * 4;
        src = (w == 0) ? Wq : (w == 1) ? Wk : Wv;
        dst = g_Wf + (size_t)w * EE * EE + off;
    }
    float4 v = *(const float4*)(src + off);
    *(__half2*)(dst)     = __halves2half2(__float2half(v.x), __float2half(v.y));
    *(__half2*)(dst + 2) = __halves2half2(__float2half(v.z), __float2half(v.w));
}

// ---------------------------------------------------------------------------
// Stage 1: QKV projections, single-pass fp16. grid (8, 64, 3)
// q: output split hi/lo, pre-scaled 1/32. k, v: single fp16.
// ---------------------------------------------------------------------------
__global__ void __launch_bounds__(256, 2) qkv_gemm(
    const float* __restrict__ bq, const float* __restrict__ bk,
    const float* __restrict__ bv)
{
    extern __shared__ char smc[];
    unsigned smBase = smem_u32(smc);
    const int tid = threadIdx.x, lane = tid & 31, wid = tid >> 5;
    const int wm = wid & 3, wn = wid >> 2;
    const int z = blockIdx.z;
    const int rowBase = blockIdx.y * 128, colBase = blockIdx.x * 128;

    const fp16* Bf = g_Wf + (size_t)z * EE * EE;
    const float* bias = (z == 0) ? bq : (z == 1) ? bk : bv;
    fp16* oh = (z == 0) ? g_qh : (z == 1) ? g_k : g_v;
    fp16* ol = (z == 0) ? g_ql : nullptr;
    const float alpha = (z == 0) ? 0.03125f : 1.0f;

    float acc[2][8][4] = {};
    mainloop_1p(g_x, EE, Bf, EE, EE, rowBase, colBase, smBase, acc);

    #pragma unroll
    for (int mi = 0; mi < 2; mi++)
        #pragma unroll
        for (int ni = 0; ni < 8; ni++) {
            int col = colBase + wn * 64 + ni * 8 + (lane & 3) * 2;
            float b0 = bias[col], b1 = bias[col + 1];
            #pragma unroll
            for (int h = 0; h < 2; h++) {
                int row = rowBase + wm * 32 + mi * 16 + (lane >> 2) + h * 8;
                float y0 = (acc[mi][ni][2 * h]     + b0) * alpha;
                float y1 = (acc[mi][ni][2 * h + 1] + b1) * alpha;
                fp16 h0 = __float2half(y0), h1 = __float2half(y1);
                size_t off = (size_t)row * EE + col;
                *(__half2*)(oh + off) = __halves2half2(h0, h1);
                if (ol) {
                    fp16 l0 = __float2half(y0 - __half2float(h0));
                    fp16 l1 = __float2half(y1 - __half2float(h1));
                    *(__half2*)(ol + off) = __halves2half2(l0, l1);
                }
            }
        }
}

// ---------------------------------------------------------------------------
// Stage 2: scores = q_scaled @ k^T, 2-pass (q hi/lo). grid (136, 1, 4)
// ---------------------------------------------------------------------------
__global__ void __launch_bounds__(256, 2) scores_gemm()
{
    extern __shared__ char smc[];
    unsigned smBase = smem_u32(smc);
    const int tid = threadIdx.x, lane = tid & 31, wid = tid >> 5;
    const int wm = wid & 3, wn = wid >> 2;
    const int z = blockIdx.z;

    int idx = blockIdx.x;
    int by = (int)((sqrtf(8.0f * idx + 1.0f) - 1.0f) * 0.5f);
    while ((by + 1) * (by + 2) / 2 <= idx) by++;
    while (by * (by + 1) / 2 > idx) by--;
    int bx = idx - by * (by + 1) / 2;

    const int rowBase = by * 128, colBase = bx * 128;

    float acc[2][8][4] = {};
    mainloop_2p(g_qh + (size_t)z * SS * EE, g_ql + (size_t)z * SS * EE, EE,
                g_k + (size_t)z * SS * EE, EE,
                EE, rowBase, colBase, smBase, acc);

    float* out = g_sc + (size_t)z * SS * SS;
    #pragma unroll
    for (int mi = 0; mi < 2; mi++)
        #pragma unroll
        for (int ni = 0; ni < 8; ni++) {
            int col = colBase + wn * 64 + ni * 8 + (lane & 3) * 2;
            #pragma unroll
            for (int h = 0; h < 2; h++) {
                int row = rowBase + wm * 32 + mi * 16 + (lane >> 2) + h * 8;
                *(float2*)(out + (size_t)row * SS + col) =
                    make_float2(acc[mi][ni][2 * h], acc[mi][ni][2 * h + 1]);
            }
        }
}

// ---------------------------------------------------------------------------
// Stage 2b: per-row softmax stats (max, 1/sumexp). grid B*S
// ---------------------------------------------------------------------------
__global__ void stats_kernel()
{
    const int rowg = blockIdx.x;
    const int b = rowg >> 11;
    const int i = rowg & (SS - 1);
    const float* p = g_sc + (size_t)b * SS * SS + (size_t)i * SS;
    const int L = i + 1;

    __shared__ float red[8], red2[8];
    const int t = threadIdx.x, lane = t & 31, w = t >> 5;

    float m = -1e30f;
    for (int j = t; j < L; j += 256) m = fmaxf(m, p[j]);
    #pragma unroll
    for (int o = 16; o; o >>= 1) m = fmaxf(m, __shfl_xor_sync(~0u, m, o));
    if (lane == 0) red[w] = m;
    __syncthreads();
    m = red[0];
    #pragma unroll
    for (int ww = 1; ww < 8; ww++) m = fmaxf(m, red[ww]);

    float s = 0.0f;
    for (int j = t; j < L; j += 256) s += __expf(p[j] - m);
    #pragma unroll
    for (int o = 16; o; o >>= 1) s += __shfl_xor_sync(~0u, s, o);
    if (lane == 0) red2[w] = s;
    __syncthreads();
    s = red2[0];
    #pragma unroll
    for (int ww = 1; ww < 8; ww++) s += red2[ww];

    if (t == 0) {
        g_m[rowg] = m;
        g_inv[rowg] = 1.0f / s;
    }
}

// ---------------------------------------------------------------------------
// Stage 3: out = P @ vT, single-pass, fused softmax. grid (8, 16, 4)
// P built fp16 in registers -> smem tile 0; vT -> tile 1.
// ---------------------------------------------------------------------------
__global__ void __launch_bounds__(256, 2) av_gemm(float* __restrict__ gout)
{
    extern __shared__ char smc[];
    unsigned smBase = smem_u32(smc);
    const int tid = threadIdx.x, lane = tid & 31, wid = tid >> 5;
    const int wm = wid & 3, wn = wid >> 2;
    const int z = blockIdx.z;
    const int by = 15 - blockIdx.y;            // long CTAs first
    const int rowBase = by * 128, colBase = blockIdx.x * 128;
    const int kTiles = (by + 1) * 4;

    const fp16* Bv = g_vT + (size_t)z * EE * SS;
    const float* sc = g_sc + (size_t)z * SS * SS;

    const int r = tid >> 1, ch = (tid & 1) * 16;
    const int grow = rowBase + r;
    const float rm = g_m[z * SS + grow];
    const float rinv = g_inv[z * SS + grow];
    const float* srow = sc + (size_t)grow * SS + ch;

    auto load_B = [&](int buf, int kt) {
        const unsigned dstb = smBase + buf * STAGE1 + TILE_B;
        const char* sB = (const char*)(Bv + (size_t)colBase * SS + kt);
        const size_t str = (size_t)SS * 2;
        #pragma unroll
        for (int i = 0; i < 2; i++) {
            int within = tid + i * 256;
            int row = within >> 2, c = within & 3;
            cp16(dstb + SWOFF(row, c), sB + row * str + c * 16);
        }
    };
    float4 sreg[4];
    auto ldg_A = [&](int kt) {
        const float* s0 = srow + kt;
        #pragma unroll
        for (int j = 0; j < 4; j++) sreg[j] = *(const float4*)(s0 + j * 4);
    };
    auto sts_A = [&](int buf, int kt) {
        char* base = smc + buf * STAGE1;
        const int sw = ((r >> 1) & 3);
        #pragma unroll
        for (int j = 0; j < 4; j++) {
            float sv[4] = {sreg[j].x, sreg[j].y, sreg[j].z, sreg[j].w};
            float pv[4];
            #pragma unroll
            for (int e = 0; e < 4; e++) {
                int gcol = kt + ch + j * 4 + e;
                pv[e] = (gcol <= grow) ? __expf(sv[e] - rm) * rinv : 0.0f;
            }
            fp16 h0 = __float2half(pv[0]), h1 = __float2half(pv[1]);
            fp16 h2 = __float2half(pv[2]), h3 = __float2half(pv[3]);
            int ccb = ch + j * 4;
            int unit = ccb >> 3;
            int boff = r * 64 + ((unit ^ sw) << 4) + (ccb & 7) * 2;
            *(__half2*)(base + boff)     = __halves2half2(h0, h1);
            *(__half2*)(base + boff + 4) = __halves2half2(h2, h3);
        }
    };

    float acc[2][8][4] = {};

    load_B(0, 0);
    cp_commit();
    ldg_A(0);
    if (kTiles > 1) {
        load_B(1, 32);
        cp_commit();
    }

    int buf = 0;
    for (int it = 0; it < kTiles; ++it) {
        sts_A(buf, it << 5);
        if (it + 1 < kTiles) cp_wait1(); else cp_wait0();
        __syncthreads();
        if (it + 2 < kTiles) {
            int nb = buf + 2; if (nb >= NSTAGE) nb -= NSTAGE;
            load_B(nb, (it + 2) << 5);
            cp_commit();
        }
        if (it + 1 < kTiles) ldg_A((it + 1) << 5);
        compute_1p(smBase, buf, wm, wn, lane, acc);
        if (++buf == NSTAGE) buf = 0;
    }

    float* out = gout + (size_t)z * SS * EE;
    #pragma unroll
    for (int mi = 0; mi < 2; mi++)
        #pragma unroll
        for (int ni = 0; ni < 8; ni++) {
            int col = colBase + wn * 64 + ni * 8 + (lane & 3) * 2;
            #pragma unroll
            for (int h = 0; h < 2; h++) {
                int row = rowBase + wm * 32 + mi * 16 + (lane >> 2) + h * 8;
                *(float2*)(out + (size_t)row * EE + col) =
                    make_float2(acc[mi][ni][2 * h], acc[mi][ni][2 * h + 1]);
            }
        }
}

// ---------------------------------------------------------------------------
// Transpose v (per batch): [S, E] -> [E, S]
// ---------------------------------------------------------------------------
__global__ void transpose_v()
{
    __shared__ fp16 th[32][33];
    const int z = blockIdx.z;
    const int s0 = blockIdx.x * 32, e0 = blockIdx.y * 32;
    const int tx = threadIdx.x, ty = threadIdx.y;
    #pragma unroll
    for (int j = 0; j < 32; j += 8) {
        size_t src = ((size_t)z * SS + s0 + ty + j) * EE + e0 + tx;
        th[ty + j][tx] = g_v[src];
    }
    __syncthreads();
    #pragma unroll
    for (int j = 0; j < 32; j += 8) {
        size_t dst = ((size_t)z * EE + e0 + ty + j) * SS + s0 + tx;
        g_vT[dst] = th[tx][ty + j];
    }
}

// ---------------------------------------------------------------------------
// Launch
// ---------------------------------------------------------------------------
extern "C" void kernel_launch(void* const* d_in, const int* in_sizes, int n_in,
                              void* d_out, int out_size)
{
    const float* x  = (const float*)d_in[0];
    const float* Wq = (const float*)d_in[2];
    const float* bq = (const float*)d_in[3];
    const float* Wk = (const float*)d_in[4];
    const float* bk = (const float*)d_in[5];
    const float* Wv = (const float*)d_in[6];
    const float* bv = (const float*)d_in[7];
    float* out = (float*)d_out;

    static bool attr_done = false;
    if (!attr_done) {
        cudaFuncSetAttribute(qkv_gemm,    cudaFuncAttributeMaxDynamicSharedMemorySize, SMEM1);
        cudaFuncSetAttribute(scores_gemm, cudaFuncAttributeMaxDynamicSharedMemorySize, SMEM2);
        cudaFuncSetAttribute(av_gemm,     cudaFuncAttributeMaxDynamicSharedMemorySize, SMEM1);
        attr_done = true;
    }

    const int splitBlocks = (BB * SS * EE / 4 + 3 * (EE * EE / 4)) / 256;
    split_all<<<splitBlocks, 256>>>(x, Wq, Wk, Wv);

    qkv_gemm<<<dim3(EE / 128, (BB * SS) / 128, 3), 256, SMEM1>>>(bq, bk, bv);

    transpose_v<<<dim3(SS / 32, EE / 32, BB), dim3(32, 8)>>>();

    scores_gemm<<<dim3(136, 1, BB), 256, SMEM2>>>();

    stats_kernel<<<BB * SS, 256>>>();

    av_gemm<<<dim3(EE / 128, SS / 128, BB), 256, SMEM1>>>(out);
}

// round 12
// speedup vs baseline: 2.3660x; 1.1547x over previous
#include <cuda_runtime.h>
#include <cuda_fp16.h>

#define BB 4
#define SS 2048
#define EE 1024

typedef __half fp16;

// ---------------------------------------------------------------------------
// Scratch (device globals — no allocation allowed)
// ---------------------------------------------------------------------------
__device__ float g_sc[(size_t)BB * SS * SS];
__device__ float g_m[BB * SS], g_inv[BB * SS];
__device__ fp16 g_x[(size_t)BB * SS * EE];
__device__ fp16 g_Wf[3 * (size_t)EE * EE];
__device__ fp16 g_q[(size_t)BB * SS * EE];
__device__ fp16 g_k[(size_t)BB * SS * EE];
__device__ fp16 g_v[(size_t)BB * SS * EE];
__device__ fp16 g_vT[(size_t)BB * EE * SS];

// ---------------------------------------------------------------------------
// PTX helpers (baseline sm_80+ features only — plain sm_103 target)
// ---------------------------------------------------------------------------
__device__ __forceinline__ unsigned smem_u32(const void* p) {
    unsigned a;
    asm("{ .reg .u64 t; cvta.to.shared.u64 t, %1; cvt.u32.u64 %0, t; }"
        : "=r"(a) : "l"(p));
    return a;
}
__device__ __forceinline__ void cp16(unsigned dst, const void* src) {
    asm volatile("cp.async.cg.shared.global [%0], [%1], 16;"
                 :: "r"(dst), "l"(src) : "memory");
}
__device__ __forceinline__ void cp_commit() {
    asm volatile("cp.async.commit_group;" ::: "memory");
}
__device__ __forceinline__ void cp_wait1() {
    asm volatile("cp.async.wait_group 1;" ::: "memory");
}
__device__ __forceinline__ void cp_wait0() {
    asm volatile("cp.async.wait_group 0;" ::: "memory");
}
__device__ __forceinline__ void ldsm4(unsigned& r0, unsigned& r1, unsigned& r2,
                                      unsigned& r3, unsigned addr) {
    asm volatile("ldmatrix.sync.aligned.m8n8.x4.shared.b16 {%0,%1,%2,%3}, [%4];"
                 : "=r"(r0), "=r"(r1), "=r"(r2), "=r"(r3) : "r"(addr));
}
__device__ __forceinline__ void mma16816(float* d, const unsigned* a,
                                         unsigned b0, unsigned b1) {
    asm volatile(
        "mma.sync.aligned.m16n8k16.row.col.f32.f16.f16.f32 "
        "{%0,%1,%2,%3}, {%4,%5,%6,%7}, {%8,%9}, {%0,%1,%2,%3};"
        : "+f"(d[0]), "+f"(d[1]), "+f"(d[2]), "+f"(d[3])
        : "r"(a[0]), "r"(a[1]), "r"(a[2]), "r"(a[3]), "r"(b0), "r"(b1));
}

// ---------------------------------------------------------------------------
// Tile: 128 rows x 32 fp16 = 64B rows, XOR-swizzled 16B units.
// Per stage: 2 tiles [A, B] = 16KB. 3 stages = 48KB.
// ---------------------------------------------------------------------------
#define TILE_B 8192
#define NSTAGE 3
#define STAGE1 (2 * TILE_B)
#define SMEM1 (NSTAGE * STAGE1)             // 49152
#define SWOFF(row, c) ((row) * 64 + (((c) ^ (((row) >> 1) & 3)) << 4))

// ---- compute: acc += A * B ------------------------------------------------
__device__ __forceinline__ void compute_1p(unsigned smBase, int buf,
                                           int wm, int wn, int lane,
                                           float acc[2][8][4])
{
    const unsigned tb = smBase + buf * STAGE1;
    const int lrow = lane & 15;
    const int lcu = lane >> 4;
    #pragma unroll
    for (int ks = 0; ks < 2; ks++) {
        const int cu = ks * 2 + lcu;
        unsigned a[2][4], b[4][4];
        #pragma unroll
        for (int mi = 0; mi < 2; mi++) {
            int row = wm * 32 + mi * 16 + lrow;
            ldsm4(a[mi][0], a[mi][1], a[mi][2], a[mi][3],
                  tb + SWOFF(row, cu));
        }
        #pragma unroll
        for (int nj = 0; nj < 4; nj++) {
            int row = wn * 64 + nj * 16 + lrow;
            ldsm4(b[nj][0], b[nj][1], b[nj][2], b[nj][3],
                  tb + TILE_B + SWOFF(row, cu));
        }
        #pragma unroll
        for (int mi = 0; mi < 2; mi++)
            #pragma unroll
            for (int nj = 0; nj < 4; nj++) {
                mma16816(acc[mi][2 * nj],     a[mi], b[nj][0], b[nj][2]);
                mma16816(acc[mi][2 * nj + 1], a[mi], b[nj][1], b[nj][3]);
            }
    }
}

// ---- loader ---------------------------------------------------------------
__device__ __forceinline__ void load_1p(unsigned smBase, int buf,
    const fp16* A, int lda, const fp16* B, int ldb,
    int rowBase, int colBase, int kt, int tid)
{
    const unsigned dstb = smBase + buf * STAGE1;
    const char* srcA = (const char*)(A + (size_t)rowBase * lda + kt);
    const char* srcB = (const char*)(B + (size_t)colBase * ldb + kt);
    const size_t strA = (size_t)lda * 2, strB = (size_t)ldb * 2;
    #pragma unroll
    for (int i = 0; i < 4; i++) {
        const int tile = i >> 1;
        int within = tid + (i & 1) * 256;
        int row = within >> 2, c = within & 3;
        const char* src = (tile == 0) ? srcA + row * strA + c * 16
                                      : srcB + row * strB + c * 16;
        cp16(dstb + tile * TILE_B + SWOFF(row, c), src);
    }
}

// ---- mainloop: 3-stage pipeline, ONE barrier per k-iter --------------------
__device__ __forceinline__ void mainloop_1p(
    const fp16* __restrict__ A, int lda, const fp16* __restrict__ B, int ldb,
    int kEnd, int rowBase, int colBase, unsigned smBase, float acc[2][8][4])
{
    const int tid = threadIdx.x;
    const int lane = tid & 31, wid = tid >> 5;
    const int wm = wid & 3, wn = wid >> 2;
    const int kTiles = kEnd >> 5;

    load_1p(smBase, 0, A, lda, B, ldb, rowBase, colBase, 0, tid);
    cp_commit();
    if (kTiles > 1) {
        load_1p(smBase, 1, A, lda, B, ldb, rowBase, colBase, 32, tid);
        cp_commit();
    }
    int buf = 0;
    for (int it = 0; it < kTiles; ++it) {
        if (it + 1 < kTiles) cp_wait1(); else cp_wait0();
        __syncthreads();
        if (it + 2 < kTiles) {
            int nb = buf + 2; if (nb >= NSTAGE) nb -= NSTAGE;
            load_1p(smBase, nb, A, lda, B, ldb, rowBase, colBase,
                    (it + 2) << 5, tid);
            cp_commit();
        }
        compute_1p(smBase, buf, wm, wn, lane, acc);
        if (++buf == NSTAGE) buf = 0;
    }
}

// ---------------------------------------------------------------------------
// Stage 0: round x and Wq/Wk/Wv to fp16
// ---------------------------------------------------------------------------
__global__ void split_all(const float* __restrict__ x,
                          const float* __restrict__ Wq,
                          const float* __restrict__ Wk,
                          const float* __restrict__ Wv)
{
    const size_t NX4 = (size_t)BB * SS * EE / 4;
    const size_t NW4 = (size_t)EE * EE / 4;
    size_t i4 = (size_t)blockIdx.x * 256 + threadIdx.x;
    const float* src;
    fp16* dst;
    size_t off;
    if (i4 < NX4) {
        off = i4 * 4;
        src = x;
        dst = g_x + off;
    } else {
        size_t j = i4 - NX4;
        int w = (int)(j / NW4);
        off = (j - (size_t)w * NW4) * 4;
        src = (w == 0) ? Wq : (w == 1) ? Wk : Wv;
        dst = g_Wf + (size_t)w * EE * EE + off;
    }
    float4 v = *(const float4*)(src + off);
    *(__half2*)(dst)     = __halves2half2(__float2half(v.x), __float2half(v.y));
    *(__half2*)(dst + 2) = __halves2half2(__float2half(v.z), __float2half(v.w));
}

// ---------------------------------------------------------------------------
// Stage 1: QKV projections, single-pass fp16. grid (8, 64, 3)
// q pre-scaled by 1/32. All outputs single fp16.
// ---------------------------------------------------------------------------
__global__ void __launch_bounds__(256, 2) qkv_gemm(
    const float* __restrict__ bq, const float* __restrict__ bk,
    const float* __restrict__ bv)
{
    extern __shared__ char smc[];
    unsigned smBase = smem_u32(smc);
    const int tid = threadIdx.x, lane = tid & 31, wid = tid >> 5;
    const int wm = wid & 3, wn = wid >> 2;
    const int z = blockIdx.z;
    const int rowBase = blockIdx.y * 128, colBase = blockIdx.x * 128;

    const fp16* Bf = g_Wf + (size_t)z * EE * EE;
    const float* bias = (z == 0) ? bq : (z == 1) ? bk : bv;
    fp16* o = (z == 0) ? g_q : (z == 1) ? g_k : g_v;
    const float alpha = (z == 0) ? 0.03125f : 1.0f;

    float acc[2][8][4] = {};
    mainloop_1p(g_x, EE, Bf, EE, EE, rowBase, colBase, smBase, acc);

    #pragma unroll
    for (int mi = 0; mi < 2; mi++)
        #pragma unroll
        for (int ni = 0; ni < 8; ni++) {
            int col = colBase + wn * 64 + ni * 8 + (lane & 3) * 2;
            float b0 = bias[col], b1 = bias[col + 1];
            #pragma unroll
            for (int h = 0; h < 2; h++) {
                int row = rowBase + wm * 32 + mi * 16 + (lane >> 2) + h * 8;
                float y0 = (acc[mi][ni][2 * h]     + b0) * alpha;
                float y1 = (acc[mi][ni][2 * h + 1] + b1) * alpha;
                size_t off = (size_t)row * EE + col;
                *(__half2*)(o + off) =
                    __halves2half2(__float2half(y0), __float2half(y1));
            }
        }
}

// ---------------------------------------------------------------------------
// Stage 2: scores = q_scaled @ k^T, single-pass. grid (136, 1, 4)
// ---------------------------------------------------------------------------
__global__ void __launch_bounds__(256, 2) scores_gemm()
{
    extern __shared__ char smc[];
    unsigned smBase = smem_u32(smc);
    const int tid = threadIdx.x, lane = tid & 31, wid = tid >> 5;
    const int wm = wid & 3, wn = wid >> 2;
    const int z = blockIdx.z;

    int idx = blockIdx.x;
    int by = (int)((sqrtf(8.0f * idx + 1.0f) - 1.0f) * 0.5f);
    while ((by + 1) * (by + 2) / 2 <= idx) by++;
    while (by * (by + 1) / 2 > idx) by--;
    int bx = idx - by * (by + 1) / 2;

    const int rowBase = by * 128, colBase = bx * 128;

    float acc[2][8][4] = {};
    mainloop_1p(g_q + (size_t)z * SS * EE, EE,
                g_k + (size_t)z * SS * EE, EE,
                EE, rowBase, colBase, smBase, acc);

    float* out = g_sc + (size_t)z * SS * SS;
    #pragma unroll
    for (int mi = 0; mi < 2; mi++)
        #pragma unroll
        for (int ni = 0; ni < 8; ni++) {
            int col = colBase + wn * 64 + ni * 8 + (lane & 3) * 2;
            #pragma unroll
            for (int h = 0; h < 2; h++) {
                int row = rowBase + wm * 32 + mi * 16 + (lane >> 2) + h * 8;
                *(float2*)(out + (size_t)row * SS + col) =
                    make_float2(acc[mi][ni][2 * h], acc[mi][ni][2 * h + 1]);
            }
        }
}

// ---------------------------------------------------------------------------
// Stage 2b: per-row softmax stats (max, 1/sumexp). grid B*S
// ---------------------------------------------------------------------------
__global__ void stats_kernel()
{
    const int rowg = blockIdx.x;
    const int b = rowg >> 11;
    const int i = rowg & (SS - 1);
    const float* p = g_sc + (size_t)b * SS * SS + (size_t)i * SS;
    const int L = i + 1;

    __shared__ float red[8], red2[8];
    const int t = threadIdx.x, lane = t & 31, w = t >> 5;

    float m = -1e30f;
    for (int j = t; j < L; j += 256) m = fmaxf(m, p[j]);
    #pragma unroll
    for (int o = 16; o; o >>= 1) m = fmaxf(m, __shfl_xor_sync(~0u, m, o));
    if (lane == 0) red[w] = m;
    __syncthreads();
    m = red[0];
    #pragma unroll
    for (int ww = 1; ww < 8; ww++) m = fmaxf(m, red[ww]);

    float s = 0.0f;
    for (int j = t; j < L; j += 256) s += __expf(p[j] - m);
    #pragma unroll
    for (int o = 16; o; o >>= 1) s += __shfl_xor_sync(~0u, s, o);
    if (lane == 0) red2[w] = s;
    __syncthreads();
    s = red2[0];
    #pragma unroll
    for (int ww = 1; ww < 8; ww++) s += red2[ww];

    if (t == 0) {
        g_m[rowg] = m;
        g_inv[rowg] = 1.0f / s;
    }
}

// ---------------------------------------------------------------------------
// Stage 3: out = P @ vT, single-pass, fused softmax. grid (8, 16, 4)
// ---------------------------------------------------------------------------
__global__ void __launch_bounds__(256, 2) av_gemm(float* __restrict__ gout)
{
    extern __shared__ char smc[];
    unsigned smBase = smem_u32(smc);
    const int tid = threadIdx.x, lane = tid & 31, wid = tid >> 5;
    const int wm = wid & 3, wn = wid >> 2;
    const int z = blockIdx.z;
    const int by = 15 - blockIdx.y;            // long CTAs first
    const int rowBase = by * 128, colBase = blockIdx.x * 128;
    const int kTiles = (by + 1) * 4;

    const fp16* Bv = g_vT + (size_t)z * EE * SS;
    const float* sc = g_sc + (size_t)z * SS * SS;

    const int r = tid >> 1, ch = (tid & 1) * 16;
    const int grow = rowBase + r;
    const float rm = g_m[z * SS + grow];
    const float rinv = g_inv[z * SS + grow];
    const float* srow = sc + (size_t)grow * SS + ch;

    auto load_B = [&](int buf, int kt) {
        const unsigned dstb = smBase + buf * STAGE1 + TILE_B;
        const char* sB = (const char*)(Bv + (size_t)colBase * SS + kt);
        const size_t str = (size_t)SS * 2;
        #pragma unroll
        for (int i = 0; i < 2; i++) {
            int within = tid + i * 256;
            int row = within >> 2, c = within & 3;
            cp16(dstb + SWOFF(row, c), sB + row * str + c * 16);
        }
    };
    float4 sreg[4];
    auto ldg_A = [&](int kt) {
        const float* s0 = srow + kt;
        #pragma unroll
        for (int j = 0; j < 4; j++) sreg[j] = *(const float4*)(s0 + j * 4);
    };
    auto sts_A = [&](int buf, int kt) {
        char* base = smc + buf * STAGE1;
        const int sw = ((r >> 1) & 3);
        #pragma unroll
        for (int j = 0; j < 4; j++) {
            float sv[4] = {sreg[j].x, sreg[j].y, sreg[j].z, sreg[j].w};
            float pv[4];
            #pragma unroll
            for (int e = 0; e < 4; e++) {
                int gcol = kt + ch + j * 4 + e;
                pv[e] = (gcol <= grow) ? __expf(sv[e] - rm) * rinv : 0.0f;
            }
            fp16 h0 = __float2half(pv[0]), h1 = __float2half(pv[1]);
            fp16 h2 = __float2half(pv[2]), h3 = __float2half(pv[3]);
            int ccb = ch + j * 4;
            int unit = ccb >> 3;
            int boff = r * 64 + ((unit ^ sw) << 4) + (ccb & 7) * 2;
            *(__half2*)(base + boff)     = __halves2half2(h0, h1);
            *(__half2*)(base + boff + 4) = __halves2half2(h2, h3);
        }
    };

    float acc[2][8][4] = {};

    load_B(0, 0);
    cp_commit();
    ldg_A(0);
    if (kTiles > 1) {
        load_B(1, 32);
        cp_commit();
    }

    int buf = 0;
    for (int it = 0; it < kTiles; ++it) {
        sts_A(buf, it << 5);
        if (it + 1 < kTiles) cp_wait1(); else cp_wait0();
        __syncthreads();
        if (it + 2 < kTiles) {
            int nb = buf + 2; if (nb >= NSTAGE) nb -= NSTAGE;
            load_B(nb, (it + 2) << 5);
            cp_commit();
        }
        if (it + 1 < kTiles) ldg_A((it + 1) << 5);
        compute_1p(smBase, buf, wm, wn, lane, acc);
        if (++buf == NSTAGE) buf = 0;
    }

    float* out = gout + (size_t)z * SS * EE;
    #pragma unroll
    for (int mi = 0; mi < 2; mi++)
        #pragma unroll
        for (int ni = 0; ni < 8; ni++) {
            int col = colBase + wn * 64 + ni * 8 + (lane & 3) * 2;
            #pragma unroll
            for (int h = 0; h < 2; h++) {
                int row = rowBase + wm * 32 + mi * 16 + (lane >> 2) + h * 8;
                *(float2*)(out + (size_t)row * EE + col) =
                    make_float2(acc[mi][ni][2 * h], acc[mi][ni][2 * h + 1]);
            }
        }
}

// ---------------------------------------------------------------------------
// Transpose v (per batch): [S, E] -> [E, S]
// ---------------------------------------------------------------------------
__global__ void transpose_v()
{
    __shared__ fp16 th[32][33];
    const int z = blockIdx.z;
    const int s0 = blockIdx.x * 32, e0 = blockIdx.y * 32;
    const int tx = threadIdx.x, ty = threadIdx.y;
    #pragma unroll
    for (int j = 0; j < 32; j += 8) {
        size_t src = ((size_t)z * SS + s0 + ty + j) * EE + e0 + tx;
        th[ty + j][tx] = g_v[src];
    }
    __syncthreads();
    #pragma unroll
    for (int j = 0; j < 32; j += 8) {
        size_t dst = ((size_t)z * EE + e0 + ty + j) * SS + s0 + tx;
        g_vT[dst] = th[tx][ty + j];
    }
}

// ---------------------------------------------------------------------------
// Launch
// ---------------------------------------------------------------------------
extern "C" void kernel_launch(void* const* d_in, const int* in_sizes, int n_in,
                              void* d_out, int out_size)
{
    const float* x  = (const float*)d_in[0];
    const float* Wq = (const float*)d_in[2];
    const float* bq = (const float*)d_in[3];
    const float* Wk = (const float*)d_in[4];
    const float* bk = (const float*)d_in[5];
    const float* Wv = (const float*)d_in[6];
    const float* bv = (const float*)d_in[7];
    float* out = (float*)d_out;

    static bool attr_done = false;
    if (!attr_done) {
        cudaFuncSetAttribute(qkv_gemm,    cudaFuncAttributeMaxDynamicSharedMemorySize, SMEM1);
        cudaFuncSetAttribute(scores_gemm, cudaFuncAttributeMaxDynamicSharedMemorySize, SMEM1);
        cudaFuncSetAttribute(av_gemm,     cudaFuncAttributeMaxDynamicSharedMemorySize, SMEM1);
        attr_done = true;
    }

    const int splitBlocks = (BB * SS * EE / 4 + 3 * (EE * EE / 4)) / 256;
    split_all<<<splitBlocks, 256>>>(x, Wq, Wk, Wv);

    qkv_gemm<<<dim3(EE / 128, (BB * SS) / 128, 3), 256, SMEM1>>>(bq, bk, bv);

    transpose_v<<<dim3(SS / 32, EE / 32, BB), dim3(32, 8)>>>();

    scores_gemm<<<dim3(136, 1, BB), 256, SMEM1>>>();

    stats_kernel<<<BB * SS, 256>>>();

    av_gemm<<<dim3(EE / 128, SS / 128, BB), 256, SMEM1>>>(out);
}

// round 13
// speedup vs baseline: 2.3912x; 1.0107x over previous
#include <cuda_runtime.h>
#include <cuda_fp16.h>

#define BB 4
#define SS 2048
#define EE 1024

typedef __half fp16;

// ---------------------------------------------------------------------------
// Scratch (device globals — no allocation allowed)
// ---------------------------------------------------------------------------
__device__ float g_sc[(size_t)BB * SS * SS];
__device__ float g_m[BB * SS], g_inv[BB * SS];
__device__ float g_pm[(size_t)BB * SS * 16], g_ps[(size_t)BB * SS * 16];
__device__ fp16 g_x[(size_t)BB * SS * EE];
__device__ fp16 g_Wf[3 * (size_t)EE * EE];
__device__ fp16 g_q[(size_t)BB * SS * EE];
__device__ fp16 g_k[(size_t)BB * SS * EE];
__device__ fp16 g_v[(size_t)BB * SS * EE];
__device__ fp16 g_vT[(size_t)BB * EE * SS];

// ---------------------------------------------------------------------------
// PTX helpers (baseline sm_80+ features only — plain sm_103 target)
// ---------------------------------------------------------------------------
__device__ __forceinline__ unsigned smem_u32(const void* p) {
    unsigned a;
    asm("{ .reg .u64 t; cvta.to.shared.u64 t, %1; cvt.u32.u64 %0, t; }"
        : "=r"(a) : "l"(p));
    return a;
}
__device__ __forceinline__ void cp16(unsigned dst, const void* src) {
    asm volatile("cp.async.cg.shared.global [%0], [%1], 16;"
                 :: "r"(dst), "l"(src) : "memory");
}
__device__ __forceinline__ void cp_commit() {
    asm volatile("cp.async.commit_group;" ::: "memory");
}
__device__ __forceinline__ void cp_wait1() {
    asm volatile("cp.async.wait_group 1;" ::: "memory");
}
__device__ __forceinline__ void cp_wait0() {
    asm volatile("cp.async.wait_group 0;" ::: "memory");
}
__device__ __forceinline__ void ldsm4(unsigned& r0, unsigned& r1, unsigned& r2,
                                      unsigned& r3, unsigned addr) {
    asm volatile("ldmatrix.sync.aligned.m8n8.x4.shared.b16 {%0,%1,%2,%3}, [%4];"
                 : "=r"(r0), "=r"(r1), "=r"(r2), "=r"(r3) : "r"(addr));
}
__device__ __forceinline__ void mma16816(float* d, const unsigned* a,
                                         unsigned b0, unsigned b1) {
    asm volatile(
        "mma.sync.aligned.m16n8k16.row.col.f32.f16.f16.f32 "
        "{%0,%1,%2,%3}, {%4,%5,%6,%7}, {%8,%9}, {%0,%1,%2,%3};"
        : "+f"(d[0]), "+f"(d[1]), "+f"(d[2]), "+f"(d[3])
        : "r"(a[0]), "r"(a[1]), "r"(a[2]), "r"(a[3]), "r"(b0), "r"(b1));
}

// ---------------------------------------------------------------------------
// Tile: 128 rows x 32 fp16 = 64B rows, XOR-swizzled 16B units.
// Per stage: 2 tiles [A, B] = 16KB. 3 stages = 48KB.
// ---------------------------------------------------------------------------
#define TILE_B 8192
#define NSTAGE 3
#define STAGE1 (2 * TILE_B)
#define SMEM1 (NSTAGE * STAGE1)             // 49152
#define SWOFF(row, c) ((row) * 64 + (((c) ^ (((row) >> 1) & 3)) << 4))

// ---- compute: acc += A * B ------------------------------------------------
__device__ __forceinline__ void compute_1p(unsigned smBase, int buf,
                                           int wm, int wn, int lane,
                                           float acc[2][8][4])
{
    const unsigned tb = smBase + buf * STAGE1;
    const int lrow = lane & 15;
    const int lcu = lane >> 4;
    #pragma unroll
    for (int ks = 0; ks < 2; ks++) {
        const int cu = ks * 2 + lcu;
        unsigned a[2][4], b[4][4];
        #pragma unroll
        for (int mi = 0; mi < 2; mi++) {
            int row = wm * 32 + mi * 16 + lrow;
            ldsm4(a[mi][0], a[mi][1], a[mi][2], a[mi][3],
                  tb + SWOFF(row, cu));
        }
        #pragma unroll
        for (int nj = 0; nj < 4; nj++) {
            int row = wn * 64 + nj * 16 + lrow;
            ldsm4(b[nj][0], b[nj][1], b[nj][2], b[nj][3],
                  tb + TILE_B + SWOFF(row, cu));
        }
        #pragma unroll
        for (int mi = 0; mi < 2; mi++)
            #pragma unroll
            for (int nj = 0; nj < 4; nj++) {
                mma16816(acc[mi][2 * nj],     a[mi], b[nj][0], b[nj][2]);
                mma16816(acc[mi][2 * nj + 1], a[mi], b[nj][1], b[nj][3]);
            }
    }
}

// ---- loader ---------------------------------------------------------------
__device__ __forceinline__ void load_1p(unsigned smBase, int buf,
    const fp16* A, int lda, const fp16* B, int ldb,
    int rowBase, int colBase, int kt, int tid)
{
    const unsigned dstb = smBase + buf * STAGE1;
    const char* srcA = (const char*)(A + (size_t)rowBase * lda + kt);
    const char* srcB = (const char*)(B + (size_t)colBase * ldb + kt);
    const size_t strA = (size_t)lda * 2, strB = (size_t)ldb * 2;
    #pragma unroll
    for (int i = 0; i < 4; i++) {
        const int tile = i >> 1;
        int within = tid + (i & 1) * 256;
        int row = within >> 2, c = within & 3;
        const char* src = (tile == 0) ? srcA + row * strA + c * 16
                                      : srcB + row * strB + c * 16;
        cp16(dstb + tile * TILE_B + SWOFF(row, c), src);
    }
}

// ---- mainloop: 3-stage pipeline, ONE barrier per k-iter --------------------
__device__ __forceinline__ void mainloop_1p(
    const fp16* __restrict__ A, int lda, const fp16* __restrict__ B, int ldb,
    int kEnd, int rowBase, int colBase, unsigned smBase, float acc[2][8][4])
{
    const int tid = threadIdx.x;
    const int lane = tid & 31, wid = tid >> 5;
    const int wm = wid & 3, wn = wid >> 2;
    const int kTiles = kEnd >> 5;

    load_1p(smBase, 0, A, lda, B, ldb, rowBase, colBase, 0, tid);
    cp_commit();
    if (kTiles > 1) {
        load_1p(smBase, 1, A, lda, B, ldb, rowBase, colBase, 32, tid);
        cp_commit();
    }
    int buf = 0;
    for (int it = 0; it < kTiles; ++it) {
        if (it + 1 < kTiles) cp_wait1(); else cp_wait0();
        __syncthreads();
        if (it + 2 < kTiles) {
            int nb = buf + 2; if (nb >= NSTAGE) nb -= NSTAGE;
            load_1p(smBase, nb, A, lda, B, ldb, rowBase, colBase,
                    (it + 2) << 5, tid);
            cp_commit();
        }
        compute_1p(smBase, buf, wm, wn, lane, acc);
        if (++buf == NSTAGE) buf = 0;
    }
}

// ---------------------------------------------------------------------------
// Stage 0: round x and Wq/Wk/Wv to fp16
// ---------------------------------------------------------------------------
__global__ void split_all(const float* __restrict__ x,
                          const float* __restrict__ Wq,
                          const float* __restrict__ Wk,
                          const float* __restrict__ Wv)
{
    const size_t NX4 = (size_t)BB * SS * EE / 4;
    const size_t NW4 = (size_t)EE * EE / 4;
    size_t i4 = (size_t)blockIdx.x * 256 + threadIdx.x;
    const float* src;
    fp16* dst;
    size_t off;
    if (i4 < NX4) {
        off = i4 * 4;
        src = x;
        dst = g_x + off;
    } else {
        size_t j = i4 - NX4;
        int w = (int)(j / NW4);
        off = (j - (size_t)w * NW4) * 4;
        src = (w == 0) ? Wq : (w == 1) ? Wk : Wv;
        dst = g_Wf + (size_t)w * EE * EE + off;
    }
    float4 v = *(const float4*)(src + off);
    *(__half2*)(dst)     = __halves2half2(__float2half(v.x), __float2half(v.y));
    *(__half2*)(dst + 2) = __halves2half2(__float2half(v.z), __float2half(v.w));
}

// ---------------------------------------------------------------------------
// Stage 1: QKV projections, single-pass fp16. grid (8, 64, 3)
// ---------------------------------------------------------------------------
__global__ void __launch_bounds__(256, 2) qkv_gemm(
    const float* __restrict__ bq, const float* __restrict__ bk,
    const float* __restrict__ bv)
{
    extern __shared__ char smc[];
    unsigned smBase = smem_u32(smc);
    const int tid = threadIdx.x, lane = tid & 31, wid = tid >> 5;
    const int wm = wid & 3, wn = wid >> 2;
    const int z = blockIdx.z;
    const int rowBase = blockIdx.y * 128, colBase = blockIdx.x * 128;

    const fp16* Bf = g_Wf + (size_t)z * EE * EE;
    const float* bias = (z == 0) ? bq : (z == 1) ? bk : bv;
    fp16* o = (z == 0) ? g_q : (z == 1) ? g_k : g_v;
    const float alpha = (z == 0) ? 0.03125f : 1.0f;

    float acc[2][8][4] = {};
    mainloop_1p(g_x, EE, Bf, EE, EE, rowBase, colBase, smBase, acc);

    #pragma unroll
    for (int mi = 0; mi < 2; mi++)
        #pragma unroll
        for (int ni = 0; ni < 8; ni++) {
            int col = colBase + wn * 64 + ni * 8 + (lane & 3) * 2;
            float b0 = bias[col], b1 = bias[col + 1];
            #pragma unroll
            for (int h = 0; h < 2; h++) {
                int row = rowBase + wm * 32 + mi * 16 + (lane >> 2) + h * 8;
                float y0 = (acc[mi][ni][2 * h]     + b0) * alpha;
                float y1 = (acc[mi][ni][2 * h + 1] + b1) * alpha;
                size_t off = (size_t)row * EE + col;
                *(__half2*)(o + off) =
                    __halves2half2(__float2half(y0), __float2half(y1));
            }
        }
}

// ---------------------------------------------------------------------------
// Stage 2: scores = q_scaled @ k^T + fused per-tile softmax partials.
// grid (136, 1, 4). Writes fp32 score tile + per-row (m_t, sum_t) partials.
// ---------------------------------------------------------------------------
__global__ void __launch_bounds__(256, 2) scores_gemm()
{
    extern __shared__ char smc[];
    unsigned smBase = smem_u32(smc);
    const int tid = threadIdx.x, lane = tid & 31, wid = tid >> 5;
    const int wm = wid & 3, wn = wid >> 2;
    const int z = blockIdx.z;

    int idx = blockIdx.x;
    int by = (int)((sqrtf(8.0f * idx + 1.0f) - 1.0f) * 0.5f);
    while ((by + 1) * (by + 2) / 2 <= idx) by++;
    while (by * (by + 1) / 2 > idx) by--;
    int bx = idx - by * (by + 1) / 2;

    const int rowBase = by * 128, colBase = bx * 128;
    const bool diag = (bx == by);

    float acc[2][8][4] = {};
    mainloop_1p(g_q + (size_t)z * SS * EE, EE,
                g_k + (size_t)z * SS * EE, EE,
                EE, rowBase, colBase, smBase, acc);

    // ---- write fp32 tile ----
    float* out = g_sc + (size_t)z * SS * SS;
    #pragma unroll
    for (int mi = 0; mi < 2; mi++)
        #pragma unroll
        for (int ni = 0; ni < 8; ni++) {
            int col = colBase + wn * 64 + ni * 8 + (lane & 3) * 2;
            #pragma unroll
            for (int h = 0; h < 2; h++) {
                int row = rowBase + wm * 32 + mi * 16 + (lane >> 2) + h * 8;
                *(float2*)(out + (size_t)row * SS + col) =
                    make_float2(acc[mi][ni][2 * h], acc[mi][ni][2 * h + 1]);
            }
        }

    // ---- fused per-row partial softmax stats over this 128x128 tile ----
    // thread rows: rloc(mi,h) = wm*32 + mi*16 + (lane>>2) + h*8
    // thread cols: wn*64 + ni*8 + (lane&3)*2 + e   (16 cols)
    __syncthreads();                       // pipeline smem now reusable
    float* rm_ = (float*)smc;              // [128][2]
    float* rs_ = (float*)(smc + 1024);     // [128][2]

    float pm[2][2];
    #pragma unroll
    for (int mi = 0; mi < 2; mi++)
        #pragma unroll
        for (int h = 0; h < 2; h++) {
            int rloc = wm * 32 + mi * 16 + (lane >> 2) + h * 8;
            float m = -1e30f;
            #pragma unroll
            for (int ni = 0; ni < 8; ni++)
                #pragma unroll
                for (int e = 0; e < 2; e++) {
                    int cloc = wn * 64 + ni * 8 + (lane & 3) * 2 + e;
                    float v = acc[mi][ni][2 * h + e];
                    bool ok = !diag || (cloc <= rloc);
                    m = ok ? fmaxf(m, v) : m;
                }
            m = fmaxf(m, __shfl_xor_sync(~0u, m, 1));
            m = fmaxf(m, __shfl_xor_sync(~0u, m, 2));
            pm[mi][h] = m;
        }
    #pragma unroll
    for (int mi = 0; mi < 2; mi++)
        #pragma unroll
        for (int h = 0; h < 2; h++) {
            int rloc = wm * 32 + mi * 16 + (lane >> 2) + h * 8;
            rm_[rloc * 2 + wn] = pm[mi][h];
        }
    __syncthreads();

    float psum[2][2];
    #pragma unroll
    for (int mi = 0; mi < 2; mi++)
        #pragma unroll
        for (int h = 0; h < 2; h++) {
            int rloc = wm * 32 + mi * 16 + (lane >> 2) + h * 8;
            float m = fmaxf(rm_[rloc * 2], rm_[rloc * 2 + 1]);
            pm[mi][h] = m;
            float s = 0.0f;
            #pragma unroll
            for (int ni = 0; ni < 8; ni++)
                #pragma unroll
                for (int e = 0; e < 2; e++) {
                    int cloc = wn * 64 + ni * 8 + (lane & 3) * 2 + e;
                    float v = acc[mi][ni][2 * h + e];
                    bool ok = !diag || (cloc <= rloc);
                    s += ok ? __expf(v - m) : 0.0f;
                }
            s += __shfl_xor_sync(~0u, s, 1);
            s += __shfl_xor_sync(~0u, s, 2);
            psum[mi][h] = s;
        }
    #pragma unroll
    for (int mi = 0; mi < 2; mi++)
        #pragma unroll
        for (int h = 0; h < 2; h++) {
            int rloc = wm * 32 + mi * 16 + (lane >> 2) + h * 8;
            rs_[rloc * 2 + wn] = psum[mi][h];
        }
    __syncthreads();

    if (wn == 0 && (lane & 3) == 0) {
        #pragma unroll
        for (int mi = 0; mi < 2; mi++)
            #pragma unroll
            for (int h = 0; h < 2; h++) {
                int rloc = wm * 32 + mi * 16 + (lane >> 2) + h * 8;
                int grow = rowBase + rloc;
                size_t slot = ((size_t)z * SS + grow) * 16 + bx;
                g_pm[slot] = pm[mi][h];
                g_ps[slot] = rs_[rloc * 2] + rs_[rloc * 2 + 1];
            }
    }
}

// ---------------------------------------------------------------------------
// Stage 2b: combine per-tile partials -> (max, 1/sumexp). 8192 threads.
// ---------------------------------------------------------------------------
__global__ void reduce_stats()
{
    int rowg = blockIdx.x * 256 + threadIdx.x;      // 0 .. B*S-1
    int i = rowg & (SS - 1);
    int nt = (i >> 7) + 1;                          // partial count
    const float* pm = g_pm + (size_t)rowg * 16;
    const float* ps = g_ps + (size_t)rowg * 16;
    float m = -1e30f;
    for (int t = 0; t < nt; t++) m = fmaxf(m, pm[t]);
    float s = 0.0f;
    for (int t = 0; t < nt; t++) s += ps[t] * __expf(pm[t] - m);
    g_m[rowg] = m;
    g_inv[rowg] = 1.0f / s;
}

// ---------------------------------------------------------------------------
// Stage 3: out = P @ vT, single-pass, fused softmax. grid (8, 16, 4)
// ---------------------------------------------------------------------------
__global__ void __launch_bounds__(256, 2) av_gemm(float* __restrict__ gout)
{
    extern __shared__ char smc[];
    unsigned smBase = smem_u32(smc);
    const int tid = threadIdx.x, lane = tid & 31, wid = tid >> 5;
    const int wm = wid & 3, wn = wid >> 2;
    const int z = blockIdx.z;
    const int by = 15 - blockIdx.y;            // long CTAs first
    const int rowBase = by * 128, colBase = blockIdx.x * 128;
    const int kTiles = (by + 1) * 4;

    const fp16* Bv = g_vT + (size_t)z * EE * SS;
    const float* sc = g_sc + (size_t)z * SS * SS;

    const int r = tid >> 1, ch = (tid & 1) * 16;
    const int grow = rowBase + r;
    const float rm = g_m[z * SS + grow];
    const float rinv = g_inv[z * SS + grow];
    const float* srow = sc + (size_t)grow * SS + ch;

    auto load_B = [&](int buf, int kt) {
        const unsigned dstb = smBase + buf * STAGE1 + TILE_B;
        const char* sB = (const char*)(Bv + (size_t)colBase * SS + kt);
        const size_t str = (size_t)SS * 2;
        #pragma unroll
        for (int i = 0; i < 2; i++) {
            int within = tid + i * 256;
            int row = within >> 2, c = within & 3;
            cp16(dstb + SWOFF(row, c), sB + row * str + c * 16);
        }
    };
    float4 sreg[4];
    auto ldg_A = [&](int kt) {
        const float* s0 = srow + kt;
        #pragma unroll
        for (int j = 0; j < 4; j++) sreg[j] = *(const float4*)(s0 + j * 4);
    };
    auto sts_A = [&](int buf, int kt) {
        char* base = smc + buf * STAGE1;
        const int sw = ((r >> 1) & 3);
        #pragma unroll
        for (int j = 0; j < 4; j++) {
            float sv[4] = {sreg[j].x, sreg[j].y, sreg[j].z, sreg[j].w};
            float pv[4];
            #pragma unroll
            for (int e = 0; e < 4; e++) {
                int gcol = kt + ch + j * 4 + e;
                pv[e] = (gcol <= grow) ? __expf(sv[e] - rm) * rinv : 0.0f;
            }
            fp16 h0 = __float2half(pv[0]), h1 = __float2half(pv[1]);
            fp16 h2 = __float2half(pv[2]), h3 = __float2half(pv[3]);
            int ccb = ch + j * 4;
            int unit = ccb >> 3;
            int boff = r * 64 + ((unit ^ sw) << 4) + (ccb & 7) * 2;
            *(__half2*)(base + boff)     = __halves2half2(h0, h1);
            *(__half2*)(base + boff + 4) = __halves2half2(h2, h3);
        }
    };

    float acc[2][8][4] = {};

    load_B(0, 0);
    cp_commit();
    ldg_A(0);
    if (kTiles > 1) {
        load_B(1, 32);
        cp_commit();
    }

    int buf = 0;
    for (int it = 0; it < kTiles; ++it) {
        sts_A(buf, it << 5);
        if (it + 1 < kTiles) cp_wait1(); else cp_wait0();
        __syncthreads();
        if (it + 2 < kTiles) {
            int nb = buf + 2; if (nb >= NSTAGE) nb -= NSTAGE;
            load_B(nb, (it + 2) << 5);
            cp_commit();
        }
        if (it + 1 < kTiles) ldg_A((it + 1) << 5);
        compute_1p(smBase, buf, wm, wn, lane, acc);
        if (++buf == NSTAGE) buf = 0;
    }

    float* out = gout + (size_t)z * SS * EE;
    #pragma unroll
    for (int mi = 0; mi < 2; mi++)
        #pragma unroll
        for (int ni = 0; ni < 8; ni++) {
            int col = colBase + wn * 64 + ni * 8 + (lane & 3) * 2;
            #pragma unroll
            for (int h = 0; h < 2; h++) {
                int row = rowBase + wm * 32 + mi * 16 + (lane >> 2) + h * 8;
                *(float2*)(out + (size_t)row * EE + col) =
                    make_float2(acc[mi][ni][2 * h], acc[mi][ni][2 * h + 1]);
            }
        }
}

// ---------------------------------------------------------------------------
// Transpose v (per batch): [S, E] -> [E, S]
// ---------------------------------------------------------------------------
__global__ void transpose_v()
{
    __shared__ fp16 th[32][33];
    const int z = blockIdx.z;
    const int s0 = blockIdx.x * 32, e0 = blockIdx.y * 32;
    const int tx = threadIdx.x, ty = threadIdx.y;
    #pragma unroll
    for (int j = 0; j < 32; j += 8) {
        size_t src = ((size_t)z * SS + s0 + ty + j) * EE + e0 + tx;
        th[ty + j][tx] = g_v[src];
    }
    __syncthreads();
    #pragma unroll
    for (int j = 0; j < 32; j += 8) {
        size_t dst = ((size_t)z * EE + e0 + ty + j) * SS + s0 + tx;
        g_vT[dst] = th[tx][ty + j];
    }
}

// ---------------------------------------------------------------------------
// Launch
// ---------------------------------------------------------------------------
extern "C" void kernel_launch(void* const* d_in, const int* in_sizes, int n_in,
                              void* d_out, int out_size)
{
    const float* x  = (const float*)d_in[0];
    const float* Wq = (const float*)d_in[2];
    const float* bq = (const float*)d_in[3];
    const float* Wk = (const float*)d_in[4];
    const float* bk = (const float*)d_in[5];
    const float* Wv = (const float*)d_in[6];
    const float* bv = (const float*)d_in[7];
    float* out = (float*)d_out;

    static bool attr_done = false;
    if (!attr_done) {
        cudaFuncSetAttribute(qkv_gemm,    cudaFuncAttributeMaxDynamicSharedMemorySize, SMEM1);
        cudaFuncSetAttribute(scores_gemm, cudaFuncAttributeMaxDynamicSharedMemorySize, SMEM1);
        cudaFuncSetAttribute(av_gemm,     cudaFuncAttributeMaxDynamicSharedMemorySize, SMEM1);
        attr_done = true;
    }

    const int splitBlocks = (BB * SS * EE / 4 + 3 * (EE * EE / 4)) / 256;
    split_all<<<splitBlocks, 256>>>(x, Wq, Wk, Wv);

    qkv_gemm<<<dim3(EE / 128, (BB * SS) / 128, 3), 256, SMEM1>>>(bq, bk, bv);

    transpose_v<<<dim3(SS / 32, EE / 32, BB), dim3(32, 8)>>>();

    scores_gemm<<<dim3(136, 1, BB), 256, SMEM1>>>();

    reduce_stats<<<BB * SS / 256, 256>>>();

    av_gemm<<<dim3(EE / 128, SS / 128, BB), 256, SMEM1>>>(out);
}

// round 14
// speedup vs baseline: 2.6195x; 1.0955x over previous
#include <cuda_runtime.h>
#include <cuda_fp16.h>

#define BB 4
#define SS 2048
#define EE 1024

typedef __half fp16;

// ---------------------------------------------------------------------------
// Scratch (device globals — no allocation allowed)
// ---------------------------------------------------------------------------
__device__ float g_m[BB * SS], g_inv[BB * SS];
__device__ float g_pm[(size_t)BB * SS * 16], g_ps[(size_t)BB * SS * 16];
__device__ fp16 g_p[(size_t)BB * SS * SS];          // P_t = exp(s - m_tile), fp16
__device__ fp16 g_x[(size_t)BB * SS * EE];
__device__ fp16 g_Wf[3 * (size_t)EE * EE];
__device__ fp16 g_q[(size_t)BB * SS * EE];
__device__ fp16 g_k[(size_t)BB * SS * EE];
__device__ fp16 g_v[(size_t)BB * SS * EE];
__device__ fp16 g_vT[(size_t)BB * EE * SS];

// ---------------------------------------------------------------------------
// PTX helpers (baseline sm_80+ features only — plain sm_103 target)
// ---------------------------------------------------------------------------
__device__ __forceinline__ unsigned smem_u32(const void* p) {
    unsigned a;
    asm("{ .reg .u64 t; cvta.to.shared.u64 t, %1; cvt.u32.u64 %0, t; }"
        : "=r"(a) : "l"(p));
    return a;
}
__device__ __forceinline__ void cp16(unsigned dst, const void* src) {
    asm volatile("cp.async.cg.shared.global [%0], [%1], 16;"
                 :: "r"(dst), "l"(src) : "memory");
}
__device__ __forceinline__ void cp_commit() {
    asm volatile("cp.async.commit_group;" ::: "memory");
}
__device__ __forceinline__ void cp_wait1() {
    asm volatile("cp.async.wait_group 1;" ::: "memory");
}
__device__ __forceinline__ void cp_wait0() {
    asm volatile("cp.async.wait_group 0;" ::: "memory");
}
__device__ __forceinline__ void ldsm4(unsigned& r0, unsigned& r1, unsigned& r2,
                                      unsigned& r3, unsigned addr) {
    asm volatile("ldmatrix.sync.aligned.m8n8.x4.shared.b16 {%0,%1,%2,%3}, [%4];"
                 : "=r"(r0), "=r"(r1), "=r"(r2), "=r"(r3) : "r"(addr));
}
__device__ __forceinline__ void mma16816(float* d, const unsigned* a,
                                         unsigned b0, unsigned b1) {
    asm volatile(
        "mma.sync.aligned.m16n8k16.row.col.f32.f16.f16.f32 "
        "{%0,%1,%2,%3}, {%4,%5,%6,%7}, {%8,%9}, {%0,%1,%2,%3};"
        : "+f"(d[0]), "+f"(d[1]), "+f"(d[2]), "+f"(d[3])
        : "r"(a[0]), "r"(a[1]), "r"(a[2]), "r"(a[3]), "r"(b0), "r"(b1));
}

// ---------------------------------------------------------------------------
// Tile: 128 rows x 32 fp16 = 64B rows, XOR-swizzled 16B units.
// Per stage: 2 tiles [A, B] = 16KB. 3 stages = 48KB.
// ---------------------------------------------------------------------------
#define TILE_B 8192
#define NSTAGE 3
#define STAGE1 (2 * TILE_B)
#define SMEM1 (NSTAGE * STAGE1)             // 49152
#define SWOFF(row, c) ((row) * 64 + (((c) ^ (((row) >> 1) & 3)) << 4))

// ---- compute: acc += A * B ------------------------------------------------
__device__ __forceinline__ void compute_1p(unsigned smBase, int buf,
                                           int wm, int wn, int lane,
                                           float acc[2][8][4])
{
    const unsigned tb = smBase + buf * STAGE1;
    const int lrow = lane & 15;
    const int lcu = lane >> 4;
    #pragma unroll
    for (int ks = 0; ks < 2; ks++) {
        const int cu = ks * 2 + lcu;
        unsigned a[2][4], b[4][4];
        #pragma unroll
        for (int mi = 0; mi < 2; mi++) {
            int row = wm * 32 + mi * 16 + lrow;
            ldsm4(a[mi][0], a[mi][1], a[mi][2], a[mi][3],
                  tb + SWOFF(row, cu));
        }
        #pragma unroll
        for (int nj = 0; nj < 4; nj++) {
            int row = wn * 64 + nj * 16 + lrow;
            ldsm4(b[nj][0], b[nj][1], b[nj][2], b[nj][3],
                  tb + TILE_B + SWOFF(row, cu));
        }
        #pragma unroll
        for (int mi = 0; mi < 2; mi++)
            #pragma unroll
            for (int nj = 0; nj < 4; nj++) {
                mma16816(acc[mi][2 * nj],     a[mi], b[nj][0], b[nj][2]);
                mma16816(acc[mi][2 * nj + 1], a[mi], b[nj][1], b[nj][3]);
            }
    }
}

// ---- loader ---------------------------------------------------------------
__device__ __forceinline__ void load_1p(unsigned smBase, int buf,
    const fp16* A, int lda, const fp16* B, int ldb,
    int rowBase, int colBase, int kt, int tid)
{
    const unsigned dstb = smBase + buf * STAGE1;
    const char* srcA = (const char*)(A + (size_t)rowBase * lda + kt);
    const char* srcB = (const char*)(B + (size_t)colBase * ldb + kt);
    const size_t strA = (size_t)lda * 2, strB = (size_t)ldb * 2;
    #pragma unroll
    for (int i = 0; i < 4; i++) {
        const int tile = i >> 1;
        int within = tid + (i & 1) * 256;
        int row = within >> 2, c = within & 3;
        const char* src = (tile == 0) ? srcA + row * strA + c * 16
                                      : srcB + row * strB + c * 16;
        cp16(dstb + tile * TILE_B + SWOFF(row, c), src);
    }
}

// ---- mainloop: 3-stage pipeline, ONE barrier per k-iter --------------------
__device__ __forceinline__ void mainloop_1p(
    const fp16* __restrict__ A, int lda, const fp16* __restrict__ B, int ldb,
    int kEnd, int rowBase, int colBase, unsigned smBase, float acc[2][8][4])
{
    const int tid = threadIdx.x;
    const int lane = tid & 31, wid = tid >> 5;
    const int wm = wid & 3, wn = wid >> 2;
    const int kTiles = kEnd >> 5;

    load_1p(smBase, 0, A, lda, B, ldb, rowBase, colBase, 0, tid);
    cp_commit();
    if (kTiles > 1) {
        load_1p(smBase, 1, A, lda, B, ldb, rowBase, colBase, 32, tid);
        cp_commit();
    }
    int buf = 0;
    for (int it = 0; it < kTiles; ++it) {
        if (it + 1 < kTiles) cp_wait1(); else cp_wait0();
        __syncthreads();
        if (it + 2 < kTiles) {
            int nb = buf + 2; if (nb >= NSTAGE) nb -= NSTAGE;
            load_1p(smBase, nb, A, lda, B, ldb, rowBase, colBase,
                    (it + 2) << 5, tid);
            cp_commit();
        }
        compute_1p(smBase, buf, wm, wn, lane, acc);
        if (++buf == NSTAGE) buf = 0;
    }
}

// ---------------------------------------------------------------------------
// Stage 0: round x and Wq/Wk/Wv to fp16
// ---------------------------------------------------------------------------
__global__ void split_all(const float* __restrict__ x,
                          const float* __restrict__ Wq,
                          const float* __restrict__ Wk,
                          const float* __restrict__ Wv)
{
    const size_t NX4 = (size_t)BB * SS * EE / 4;
    const size_t NW4 = (size_t)EE * EE / 4;
    size_t i4 = (size_t)blockIdx.x * 256 + threadIdx.x;
    const float* src;
    fp16* dst;
    size_t off;
    if (i4 < NX4) {
        off = i4 * 4;
        src = x;
        dst = g_x + off;
    } else {
        size_t j = i4 - NX4;
        int w = (int)(j / NW4);
        off = (j - (size_t)w * NW4) * 4;
        src = (w == 0) ? Wq : (w == 1) ? Wk : Wv;
        dst = g_Wf + (size_t)w * EE * EE + off;
    }
    float4 v = *(const float4*)(src + off);
    *(__half2*)(dst)     = __halves2half2(__float2half(v.x), __float2half(v.y));
    *(__half2*)(dst + 2) = __halves2half2(__float2half(v.z), __float2half(v.w));
}

// ---------------------------------------------------------------------------
// Stage 1: QKV projections, single-pass fp16. grid (8, 64, 3)
// ---------------------------------------------------------------------------
__global__ void __launch_bounds__(256, 2) qkv_gemm(
    const float* __restrict__ bq, const float* __restrict__ bk,
    const float* __restrict__ bv)
{
    extern __shared__ char smc[];
    unsigned smBase = smem_u32(smc);
    const int tid = threadIdx.x, lane = tid & 31, wid = tid >> 5;
    const int wm = wid & 3, wn = wid >> 2;
    const int z = blockIdx.z;
    const int rowBase = blockIdx.y * 128, colBase = blockIdx.x * 128;

    const fp16* Bf = g_Wf + (size_t)z * EE * EE;
    const float* bias = (z == 0) ? bq : (z == 1) ? bk : bv;
    fp16* o = (z == 0) ? g_q : (z == 1) ? g_k : g_v;
    const float alpha = (z == 0) ? 0.03125f : 1.0f;

    float acc[2][8][4] = {};
    mainloop_1p(g_x, EE, Bf, EE, EE, rowBase, colBase, smBase, acc);

    #pragma unroll
    for (int mi = 0; mi < 2; mi++)
        #pragma unroll
        for (int ni = 0; ni < 8; ni++) {
            int col = colBase + wn * 64 + ni * 8 + (lane & 3) * 2;
            float b0 = bias[col], b1 = bias[col + 1];
            #pragma unroll
            for (int h = 0; h < 2; h++) {
                int row = rowBase + wm * 32 + mi * 16 + (lane >> 2) + h * 8;
                float y0 = (acc[mi][ni][2 * h]     + b0) * alpha;
                float y1 = (acc[mi][ni][2 * h + 1] + b1) * alpha;
                size_t off = (size_t)row * EE + col;
                *(__half2*)(o + off) =
                    __halves2half2(__float2half(y0), __float2half(y1));
            }
        }
}

// ---------------------------------------------------------------------------
// Stage 2: scores -> fp16 P_t = exp(s - m_tile) + per-tile partials (m_t, sum_t)
// grid (136, 1, 4)
// ---------------------------------------------------------------------------
__global__ void __launch_bounds__(256, 2) scores_gemm()
{
    extern __shared__ char smc[];
    unsigned smBase = smem_u32(smc);
    const int tid = threadIdx.x, lane = tid & 31, wid = tid >> 5;
    const int wm = wid & 3, wn = wid >> 2;
    const int z = blockIdx.z;

    int idx = blockIdx.x;
    int by = (int)((sqrtf(8.0f * idx + 1.0f) - 1.0f) * 0.5f);
    while ((by + 1) * (by + 2) / 2 <= idx) by++;
    while (by * (by + 1) / 2 > idx) by--;
    int bx = idx - by * (by + 1) / 2;

    const int rowBase = by * 128, colBase = bx * 128;
    const bool diag = (bx == by);

    float acc[2][8][4] = {};
    mainloop_1p(g_q + (size_t)z * SS * EE, EE,
                g_k + (size_t)z * SS * EE, EE,
                EE, rowBase, colBase, smBase, acc);

    // ---- per-row tile max (combine the two wn halves through smem) ----
    __syncthreads();                       // pipeline smem reusable now
    float* rm_ = (float*)smc;              // [128][2]
    float* rs_ = (float*)(smc + 1024);     // [128][2]

    float pm[2][2];
    #pragma unroll
    for (int mi = 0; mi < 2; mi++)
        #pragma unroll
        for (int h = 0; h < 2; h++) {
            int rloc = wm * 32 + mi * 16 + (lane >> 2) + h * 8;
            float m = -1e30f;
            #pragma unroll
            for (int ni = 0; ni < 8; ni++)
                #pragma unroll
                for (int e = 0; e < 2; e++) {
                    int cloc = wn * 64 + ni * 8 + (lane & 3) * 2 + e;
                    float v = acc[mi][ni][2 * h + e];
                    bool ok = !diag || (cloc <= rloc);
                    m = ok ? fmaxf(m, v) : m;
                }
            m = fmaxf(m, __shfl_xor_sync(~0u, m, 1));
            m = fmaxf(m, __shfl_xor_sync(~0u, m, 2));
            pm[mi][h] = m;
        }
    #pragma unroll
    for (int mi = 0; mi < 2; mi++)
        #pragma unroll
        for (int h = 0; h < 2; h++) {
            int rloc = wm * 32 + mi * 16 + (lane >> 2) + h * 8;
            rm_[rloc * 2 + wn] = pm[mi][h];
        }
    __syncthreads();

    // ---- exp + partial sums + fp16 P store ----
    fp16* outP = g_p + (size_t)z * SS * SS;
    float psum[2][2];
    #pragma unroll
    for (int mi = 0; mi < 2; mi++)
        #pragma unroll
        for (int h = 0; h < 2; h++) {
            int rloc = wm * 32 + mi * 16 + (lane >> 2) + h * 8;
            int grow = rowBase + rloc;
            float m = fmaxf(rm_[rloc * 2], rm_[rloc * 2 + 1]);
            pm[mi][h] = m;
            float s = 0.0f;
            #pragma unroll
            for (int ni = 0; ni < 8; ni++) {
                int cloc = wn * 64 + ni * 8 + (lane & 3) * 2;
                float v0 = acc[mi][ni][2 * h], v1 = acc[mi][ni][2 * h + 1];
                bool ok0 = !diag || (cloc     <= rloc);
                bool ok1 = !diag || (cloc + 1 <= rloc);
                float e0 = ok0 ? __expf(v0 - m) : 0.0f;
                float e1 = ok1 ? __expf(v1 - m) : 0.0f;
                s += e0 + e1;
                *(__half2*)(outP + (size_t)grow * SS + colBase + cloc) =
                    __halves2half2(__float2half(e0), __float2half(e1));
            }
            s += __shfl_xor_sync(~0u, s, 1);
            s += __shfl_xor_sync(~0u, s, 2);
            psum[mi][h] = s;
        }
    #pragma unroll
    for (int mi = 0; mi < 2; mi++)
        #pragma unroll
        for (int h = 0; h < 2; h++) {
            int rloc = wm * 32 + mi * 16 + (lane >> 2) + h * 8;
            rs_[rloc * 2 + wn] = psum[mi][h];
        }
    __syncthreads();

    if (wn == 0 && (lane & 3) == 0) {
        #pragma unroll
        for (int mi = 0; mi < 2; mi++)
            #pragma unroll
            for (int h = 0; h < 2; h++) {
                int rloc = wm * 32 + mi * 16 + (lane >> 2) + h * 8;
                int grow = rowBase + rloc;
                size_t slot = ((size_t)z * SS + grow) * 16 + bx;
                g_pm[slot] = pm[mi][h];
                g_ps[slot] = rs_[rloc * 2] + rs_[rloc * 2 + 1];
            }
    }
}

// ---------------------------------------------------------------------------
// Stage 2b: combine per-tile partials -> (max, 1/sumexp). 8192 threads.
// ---------------------------------------------------------------------------
__global__ void reduce_stats()
{
    int rowg = blockIdx.x * 256 + threadIdx.x;
    int i = rowg & (SS - 1);
    int nt = (i >> 7) + 1;
    const float* pm = g_pm + (size_t)rowg * 16;
    const float* ps = g_ps + (size_t)rowg * 16;
    float m = -1e30f;
    for (int t = 0; t < nt; t++) m = fmaxf(m, pm[t]);
    float s = 0.0f;
    for (int t = 0; t < nt; t++) s += ps[t] * __expf(pm[t] - m);
    g_m[rowg] = m;
    g_inv[rowg] = 1.0f / s;
}

// ---------------------------------------------------------------------------
// Stage 3: out = P @ vT; P corrected per tile: p = P_t * exp(m_t - m) * inv
// grid (8, 16, 4)
// ---------------------------------------------------------------------------
__global__ void __launch_bounds__(256, 2) av_gemm(float* __restrict__ gout)
{
    extern __shared__ char smc[];
    unsigned smBase = smem_u32(smc);
    const int tid = threadIdx.x, lane = tid & 31, wid = tid >> 5;
    const int wm = wid & 3, wn = wid >> 2;
    const int z = blockIdx.z;
    const int by = 15 - blockIdx.y;            // long CTAs first
    const int rowBase = by * 128, colBase = blockIdx.x * 128;
    const int kTiles = (by + 1) * 4;

    const fp16* Bv = g_vT + (size_t)z * EE * SS;

    const int r = tid >> 1, ch = (tid & 1) * 16;
    const int grow = rowBase + r;
    const float rm = g_m[z * SS + grow];
    const float rinv = g_inv[z * SS + grow];
    const fp16* prow = g_p + ((size_t)z * SS + grow) * SS + ch;
    const float* pmrow = g_pm + ((size_t)z * SS + grow) * 16;

    auto load_B = [&](int buf, int kt) {
        const unsigned dstb = smBase + buf * STAGE1 + TILE_B;
        const char* sB = (const char*)(Bv + (size_t)colBase * SS + kt);
        const size_t str = (size_t)SS * 2;
        #pragma unroll
        for (int i = 0; i < 2; i++) {
            int within = tid + i * 256;
            int row = within >> 2, c = within & 3;
            cp16(dstb + SWOFF(row, c), sB + row * str + c * 16);
        }
    };
    uint4 sregu[2];
    float fcorr;
    auto ldg_A = [&](int kt) {
        const fp16* s0 = prow + kt;
        sregu[0] = *(const uint4*)(s0);
        sregu[1] = *(const uint4*)(s0 + 8);
        fcorr = pmrow[kt >> 7];
    };
    auto sts_A = [&](int buf) {
        char* base = smc + buf * STAGE1;
        const int sw = ((r >> 1) & 3);
        const float f = __expf(fcorr - rm) * rinv;
        const unsigned* pw = (const unsigned*)sregu;   // 8 half2 words
        #pragma unroll
        for (int j = 0; j < 4; j++) {
            float2 a0 = __half22float2(*(const __half2*)&pw[j * 2]);
            float2 a1 = __half22float2(*(const __half2*)&pw[j * 2 + 1]);
            fp16 h0 = __float2half(a0.x * f), h1 = __float2half(a0.y * f);
            fp16 h2 = __float2half(a1.x * f), h3 = __float2half(a1.y * f);
            int ccb = ch + j * 4;
            int unit = ccb >> 3;
            int boff = r * 64 + ((unit ^ sw) << 4) + (ccb & 7) * 2;
            *(__half2*)(base + boff)     = __halves2half2(h0, h1);
            *(__half2*)(base + boff + 4) = __halves2half2(h2, h3);
        }
    };

    float acc[2][8][4] = {};

    load_B(0, 0);
    cp_commit();
    ldg_A(0);
    if (kTiles > 1) {
        load_B(1, 32);
        cp_commit();
    }

    int buf = 0;
    for (int it = 0; it < kTiles; ++it) {
        sts_A(buf);
        if (it + 1 < kTiles) cp_wait1(); else cp_wait0();
        __syncthreads();
        if (it + 2 < kTiles) {
            int nb = buf + 2; if (nb >= NSTAGE) nb -= NSTAGE;
            load_B(nb, (it + 2) << 5);
            cp_commit();
        }
        if (it + 1 < kTiles) ldg_A((it + 1) << 5);
        compute_1p(smBase, buf, wm, wn, lane, acc);
        if (++buf == NSTAGE) buf = 0;
    }

    float* out = gout + (size_t)z * SS * EE;
    #pragma unroll
    for (int mi = 0; mi < 2; mi++)
        #pragma unroll
        for (int ni = 0; ni < 8; ni++) {
            int col = colBase + wn * 64 + ni * 8 + (lane & 3) * 2;
            #pragma unroll
            for (int h = 0; h < 2; h++) {
                int row = rowBase + wm * 32 + mi * 16 + (lane >> 2) + h * 8;
                *(float2*)(out + (size_t)row * EE + col) =
                    make_float2(acc[mi][ni][2 * h], acc[mi][ni][2 * h + 1]);
            }
        }
}

// ---------------------------------------------------------------------------
// Transpose v (per batch): [S, E] -> [E, S]
// ---------------------------------------------------------------------------
__global__ void transpose_v()
{
    __shared__ fp16 th[32][33];
    const int z = blockIdx.z;
    const int s0 = blockIdx.x * 32, e0 = blockIdx.y * 32;
    const int tx = threadIdx.x, ty = threadIdx.y;
    #pragma unroll
    for (int j = 0; j < 32; j += 8) {
        size_t src = ((size_t)z * SS + s0 + ty + j) * EE + e0 + tx;
        th[ty + j][tx] = g_v[src];
    }
    __syncthreads();
    #pragma unroll
    for (int j = 0; j < 32; j += 8) {
        size_t dst = ((size_t)z * EE + e0 + ty + j) * SS + s0 + tx;
        g_vT[dst] = th[tx][ty + j];
    }
}

// ---------------------------------------------------------------------------
// Launch
// ---------------------------------------------------------------------------
extern "C" void kernel_launch(void* const* d_in, const int* in_sizes, int n_in,
                              void* d_out, int out_size)
{
    const float* x  = (const float*)d_in[0];
    const float* Wq = (const float*)d_in[2];
    const float* bq = (const float*)d_in[3];
    const float* Wk = (const float*)d_in[4];
    const float* bk = (const float*)d_in[5];
    const float* Wv = (const float*)d_in[6];
    const float* bv = (const float*)d_in[7];
    float* out = (float*)d_out;

    static bool attr_done = false;
    if (!attr_done) {
        cudaFuncSetAttribute(qkv_gemm,    cudaFuncAttributeMaxDynamicSharedMemorySize, SMEM1);
        cudaFuncSetAttribute(scores_gemm, cudaFuncAttributeMaxDynamicSharedMemorySize, SMEM1);
        cudaFuncSetAttribute(av_gemm,     cudaFuncAttributeMaxDynamicSharedMemorySize, SMEM1);
        attr_done = true;
    }

    const int splitBlocks = (BB * SS * EE / 4 + 3 * (EE * EE / 4)) / 256;
    split_all<<<splitBlocks, 256>>>(x, Wq, Wk, Wv);

    qkv_gemm<<<dim3(EE / 128, (BB * SS) / 128, 3), 256, SMEM1>>>(bq, bk, bv);

    transpose_v<<<dim3(SS / 32, EE / 32, BB), dim3(32, 8)>>>();

    scores_gemm<<<dim3(136, 1, BB), 256, SMEM1>>>();

    reduce_stats<<<BB * SS / 256, 256>>>();

    av_gemm<<<dim3(EE / 128, SS / 128, BB), 256, SMEM1>>>(out);
}

// round 15
// speedup vs baseline: 2.6340x; 1.0055x over previous
#include <cuda_runtime.h>
#include <cuda_fp16.h>

#define BB 4
#define SS 2048
#define EE 1024

typedef __half fp16;

// ---------------------------------------------------------------------------
// Scratch (device globals — no allocation allowed)
// ---------------------------------------------------------------------------
__device__ float g_pm[(size_t)BB * SS * 16], g_ps[(size_t)BB * SS * 16];
__device__ fp16 g_p[(size_t)BB * SS * SS];          // P_t = exp(s - m_tile), fp16
__device__ fp16 g_x[(size_t)BB * SS * EE];
__device__ fp16 g_Wf[3 * (size_t)EE * EE];
__device__ fp16 g_q[(size_t)BB * SS * EE];
__device__ fp16 g_k[(size_t)BB * SS * EE];
__device__ fp16 g_vT[(size_t)BB * EE * SS];

// ---------------------------------------------------------------------------
// PTX helpers (baseline sm_80+ features only — plain sm_103 target)
// ---------------------------------------------------------------------------
__device__ __forceinline__ unsigned smem_u32(const void* p) {
    unsigned a;
    asm("{ .reg .u64 t; cvta.to.shared.u64 t, %1; cvt.u32.u64 %0, t; }"
        : "=r"(a) : "l"(p));
    return a;
}
__device__ __forceinline__ void cp16(unsigned dst, const void* src) {
    asm volatile("cp.async.cg.shared.global [%0], [%1], 16;"
                 :: "r"(dst), "l"(src) : "memory");
}
__device__ __forceinline__ void cp_commit() {
    asm volatile("cp.async.commit_group;" ::: "memory");
}
__device__ __forceinline__ void cp_wait1() {
    asm volatile("cp.async.wait_group 1;" ::: "memory");
}
__device__ __forceinline__ void cp_wait0() {
    asm volatile("cp.async.wait_group 0;" ::: "memory");
}
__device__ __forceinline__ void ldsm4(unsigned& r0, unsigned& r1, unsigned& r2,
                                      unsigned& r3, unsigned addr) {
    asm volatile("ldmatrix.sync.aligned.m8n8.x4.shared.b16 {%0,%1,%2,%3}, [%4];"
                 : "=r"(r0), "=r"(r1), "=r"(r2), "=r"(r3) : "r"(addr));
}
__device__ __forceinline__ void mma16816(float* d, const unsigned* a,
                                         unsigned b0, unsigned b1) {
    asm volatile(
        "mma.sync.aligned.m16n8k16.row.col.f32.f16.f16.f32 "
        "{%0,%1,%2,%3}, {%4,%5,%6,%7}, {%8,%9}, {%0,%1,%2,%3};"
        : "+f"(d[0]), "+f"(d[1]), "+f"(d[2]), "+f"(d[3])
        : "r"(a[0]), "r"(a[1]), "r"(a[2]), "r"(a[3]), "r"(b0), "r"(b1));
}

// ---------------------------------------------------------------------------
// Tile: 128 rows x 32 fp16 = 64B rows, XOR-swizzled 16B units.
// Per stage: 2 tiles [A, B] = 16KB. 3 stages = 48KB.
// ---------------------------------------------------------------------------
#define TILE_B 8192
#define NSTAGE 3
#define STAGE1 (2 * TILE_B)
#define SMEM1 (NSTAGE * STAGE1)             // 49152
#define SWOFF(row, c) ((row) * 64 + (((c) ^ (((row) >> 1) & 3)) << 4))

// ---- compute: acc += A * B ------------------------------------------------
__device__ __forceinline__ void compute_1p(unsigned smBase, int buf,
                                           int wm, int wn, int lane,
                                           float acc[2][8][4])
{
    const unsigned tb = smBase + buf * STAGE1;
    const int lrow = lane & 15;
    const int lcu = lane >> 4;
    #pragma unroll
    for (int ks = 0; ks < 2; ks++) {
        const int cu = ks * 2 + lcu;
        unsigned a[2][4], b[4][4];
        #pragma unroll
        for (int mi = 0; mi < 2; mi++) {
            int row = wm * 32 + mi * 16 + lrow;
            ldsm4(a[mi][0], a[mi][1], a[mi][2], a[mi][3],
                  tb + SWOFF(row, cu));
        }
        #pragma unroll
        for (int nj = 0; nj < 4; nj++) {
            int row = wn * 64 + nj * 16 + lrow;
            ldsm4(b[nj][0], b[nj][1], b[nj][2], b[nj][3],
                  tb + TILE_B + SWOFF(row, cu));
        }
        #pragma unroll
        for (int mi = 0; mi < 2; mi++)
            #pragma unroll
            for (int nj = 0; nj < 4; nj++) {
                mma16816(acc[mi][2 * nj],     a[mi], b[nj][0], b[nj][2]);
                mma16816(acc[mi][2 * nj + 1], a[mi], b[nj][1], b[nj][3]);
            }
    }
}

// ---- loader ---------------------------------------------------------------
__device__ __forceinline__ void load_1p(unsigned smBase, int buf,
    const fp16* A, int lda, const fp16* B, int ldb,
    int rowBase, int colBase, int kt, int tid)
{
    const unsigned dstb = smBase + buf * STAGE1;
    const char* srcA = (const char*)(A + (size_t)rowBase * lda + kt);
    const char* srcB = (const char*)(B + (size_t)colBase * ldb + kt);
    const size_t strA = (size_t)lda * 2, strB = (size_t)ldb * 2;
    #pragma unroll
    for (int i = 0; i < 4; i++) {
        const int tile = i >> 1;
        int within = tid + (i & 1) * 256;
        int row = within >> 2, c = within & 3;
        const char* src = (tile == 0) ? srcA + row * strA + c * 16
                                      : srcB + row * strB + c * 16;
        cp16(dstb + tile * TILE_B + SWOFF(row, c), src);
    }
}

// ---- mainloop: 3-stage pipeline, ONE barrier per k-iter --------------------
__device__ __forceinline__ void mainloop_1p(
    const fp16* __restrict__ A, int lda, const fp16* __restrict__ B, int ldb,
    int kEnd, int rowBase, int colBase, unsigned smBase, float acc[2][8][4])
{
    const int tid = threadIdx.x;
    const int lane = tid & 31, wid = tid >> 5;
    const int wm = wid & 3, wn = wid >> 2;
    const int kTiles = kEnd >> 5;

    load_1p(smBase, 0, A, lda, B, ldb, rowBase, colBase, 0, tid);
    cp_commit();
    if (kTiles > 1) {
        load_1p(smBase, 1, A, lda, B, ldb, rowBase, colBase, 32, tid);
        cp_commit();
    }
    int buf = 0;
    for (int it = 0; it < kTiles; ++it) {
        if (it + 1 < kTiles) cp_wait1(); else cp_wait0();
        __syncthreads();
        if (it + 2 < kTiles) {
            int nb = buf + 2; if (nb >= NSTAGE) nb -= NSTAGE;
            load_1p(smBase, nb, A, lda, B, ldb, rowBase, colBase,
                    (it + 2) << 5, tid);
            cp_commit();
        }
        compute_1p(smBase, buf, wm, wn, lane, acc);
        if (++buf == NSTAGE) buf = 0;
    }
}

// ---------------------------------------------------------------------------
// Stage 0: round x and Wq/Wk/Wv to fp16
// ---------------------------------------------------------------------------
__global__ void split_all(const float* __restrict__ x,
                          const float* __restrict__ Wq,
                          const float* __restrict__ Wk,
                          const float* __restrict__ Wv)
{
    const size_t NX4 = (size_t)BB * SS * EE / 4;
    const size_t NW4 = (size_t)EE * EE / 4;
    size_t i4 = (size_t)blockIdx.x * 256 + threadIdx.x;
    const float* src;
    fp16* dst;
    size_t off;
    if (i4 < NX4) {
        off = i4 * 4;
        src = x;
        dst = g_x + off;
    } else {
        size_t j = i4 - NX4;
        int w = (int)(j / NW4);
        off = (j - (size_t)w * NW4) * 4;
        src = (w == 0) ? Wq : (w == 1) ? Wk : Wv;
        dst = g_Wf + (size_t)w * EE * EE + off;
    }
    float4 v = *(const float4*)(src + off);
    *(__half2*)(dst)     = __halves2half2(__float2half(v.x), __float2half(v.y));
    *(__half2*)(dst + 2) = __halves2half2(__float2half(v.z), __float2half(v.w));
}

// ---------------------------------------------------------------------------
// Stage 1: QKV projections, single-pass fp16. grid (8, 64, 3)
// z==0 -> g_q (scaled 1/32); z==1 -> g_k; z==2 -> g_vT (transposed in smem).
// ---------------------------------------------------------------------------
__global__ void __launch_bounds__(256, 2) qkv_gemm(
    const float* __restrict__ bq, const float* __restrict__ bk,
    const float* __restrict__ bv)
{
    extern __shared__ char smc[];
    unsigned smBase = smem_u32(smc);
    const int tid = threadIdx.x, lane = tid & 31, wid = tid >> 5;
    const int wm = wid & 3, wn = wid >> 2;
    const int z = blockIdx.z;
    const int rowBase = blockIdx.y * 128, colBase = blockIdx.x * 128;

    const fp16* Bf = g_Wf + (size_t)z * EE * EE;
    const float* bias = (z == 0) ? bq : (z == 1) ? bk : bv;
    const float alpha = (z == 0) ? 0.03125f : 1.0f;

    float acc[2][8][4] = {};
    mainloop_1p(g_x, EE, Bf, EE, EE, rowBase, colBase, smBase, acc);

    if (z < 2) {
        fp16* o = (z == 0) ? g_q : g_k;
        #pragma unroll
        for (int mi = 0; mi < 2; mi++)
            #pragma unroll
            for (int ni = 0; ni < 8; ni++) {
                int col = colBase + wn * 64 + ni * 8 + (lane & 3) * 2;
                float b0 = bias[col], b1 = bias[col + 1];
                #pragma unroll
                for (int h = 0; h < 2; h++) {
                    int row = rowBase + wm * 32 + mi * 16 + (lane >> 2) + h * 8;
                    float y0 = (acc[mi][ni][2 * h]     + b0) * alpha;
                    float y1 = (acc[mi][ni][2 * h + 1] + b1) * alpha;
                    size_t off = (size_t)row * EE + col;
                    *(__half2*)(o + off) =
                        __halves2half2(__float2half(y0), __float2half(y1));
                }
            }
    } else {
        // v: stage transposed tile in smem (pitch 136 fp16 = 272B), then
        // write g_vT[e][s] coalesced.
        __syncthreads();                        // pipeline smem free now
        fp16* st = (fp16*)smc;                  // [128 cols][136]
        #pragma unroll
        for (int mi = 0; mi < 2; mi++)
            #pragma unroll
            for (int ni = 0; ni < 8; ni++) {
                int cloc = wn * 64 + ni * 8 + (lane & 3) * 2;
                float b0 = bias[colBase + cloc], b1 = bias[colBase + cloc + 1];
                #pragma unroll
                for (int h = 0; h < 2; h++) {
                    int rloc = wm * 32 + mi * 16 + (lane >> 2) + h * 8;
                    st[cloc * 136 + rloc]       = __float2half(acc[mi][ni][2 * h]     + b0);
                    st[(cloc + 1) * 136 + rloc] = __float2half(acc[mi][ni][2 * h + 1] + b1);
                }
            }
        __syncthreads();
        const int c = tid >> 1, half = (tid & 1) * 64;
        fp16* dst = g_vT + ((size_t)blockIdx.y /*z-batch? no*/, 0);
        // g_vT layout: [b][e][s]; b index comes from rowBase's batch.
        // rowBase spans all batches: global row = rowBase + s covers b*SS..
        // rows rowBase..rowBase+127 all in batch bidx = rowBase / SS.
        int bidx = rowBase >> 11;               // rowBase / 2048
        int sBase = rowBase & (SS - 1);
        fp16* vrow = g_vT + ((size_t)bidx * EE + colBase + c) * SS + sBase + half;
        const fp16* srow = st + c * 136 + half;
        #pragma unroll
        for (int j = 0; j < 8; j++)
            *(uint4*)(vrow + j * 8) = *(const uint4*)(srow + j * 8);
    }
}

// ---------------------------------------------------------------------------
// Stage 2: scores -> fp16 P_t = exp(s - m_tile) + per-tile partials (m_t, sum_t)
// grid (136, 1, 4)
// ---------------------------------------------------------------------------
__global__ void __launch_bounds__(256, 2) scores_gemm()
{
    extern __shared__ char smc[];
    unsigned smBase = smem_u32(smc);
    const int tid = threadIdx.x, lane = tid & 31, wid = tid >> 5;
    const int wm = wid & 3, wn = wid >> 2;
    const int z = blockIdx.z;

    int idx = blockIdx.x;
    int by = (int)((sqrtf(8.0f * idx + 1.0f) - 1.0f) * 0.5f);
    while ((by + 1) * (by + 2) / 2 <= idx) by++;
    while (by * (by + 1) / 2 > idx) by--;
    int bx = idx - by * (by + 1) / 2;

    const int rowBase = by * 128, colBase = bx * 128;
    const bool diag = (bx == by);

    float acc[2][8][4] = {};
    mainloop_1p(g_q + (size_t)z * SS * EE, EE,
                g_k + (size_t)z * SS * EE, EE,
                EE, rowBase, colBase, smBase, acc);

    __syncthreads();
    float* rm_ = (float*)smc;              // [128][2]
    float* rs_ = (float*)(smc + 1024);     // [128][2]

    float pm[2][2];
    #pragma unroll
    for (int mi = 0; mi < 2; mi++)
        #pragma unroll
        for (int h = 0; h < 2; h++) {
            int rloc = wm * 32 + mi * 16 + (lane >> 2) + h * 8;
            float m = -1e30f;
            #pragma unroll
            for (int ni = 0; ni < 8; ni++)
                #pragma unroll
                for (int e = 0; e < 2; e++) {
                    int cloc = wn * 64 + ni * 8 + (lane & 3) * 2 + e;
                    float v = acc[mi][ni][2 * h + e];
                    bool ok = !diag || (cloc <= rloc);
                    m = ok ? fmaxf(m, v) : m;
                }
            m = fmaxf(m, __shfl_xor_sync(~0u, m, 1));
            m = fmaxf(m, __shfl_xor_sync(~0u, m, 2));
            pm[mi][h] = m;
        }
    #pragma unroll
    for (int mi = 0; mi < 2; mi++)
        #pragma unroll
        for (int h = 0; h < 2; h++) {
            int rloc = wm * 32 + mi * 16 + (lane >> 2) + h * 8;
            rm_[rloc * 2 + wn] = pm[mi][h];
        }
    __syncthreads();

    fp16* outP = g_p + (size_t)z * SS * SS;
    float psum[2][2];
    #pragma unroll
    for (int mi = 0; mi < 2; mi++)
        #pragma unroll
        for (int h = 0; h < 2; h++) {
            int rloc = wm * 32 + mi * 16 + (lane >> 2) + h * 8;
            int grow = rowBase + rloc;
            float m = fmaxf(rm_[rloc * 2], rm_[rloc * 2 + 1]);
            pm[mi][h] = m;
            float s = 0.0f;
            #pragma unroll
            for (int ni = 0; ni < 8; ni++) {
                int cloc = wn * 64 + ni * 8 + (lane & 3) * 2;
                float v0 = acc[mi][ni][2 * h], v1 = acc[mi][ni][2 * h + 1];
                bool ok0 = !diag || (cloc     <= rloc);
                bool ok1 = !diag || (cloc + 1 <= rloc);
                float e0 = ok0 ? __expf(v0 - m) : 0.0f;
                float e1 = ok1 ? __expf(v1 - m) : 0.0f;
                s += e0 + e1;
                *(__half2*)(outP + (size_t)grow * SS + colBase + cloc) =
                    __halves2half2(__float2half(e0), __float2half(e1));
            }
            s += __shfl_xor_sync(~0u, s, 1);
            s += __shfl_xor_sync(~0u, s, 2);
            psum[mi][h] = s;
        }
    #pragma unroll
    for (int mi = 0; mi < 2; mi++)
        #pragma unroll
        for (int h = 0; h < 2; h++) {
            int rloc = wm * 32 + mi * 16 + (lane >> 2) + h * 8;
            rs_[rloc * 2 + wn] = psum[mi][h];
        }
    __syncthreads();

    if (wn == 0 && (lane & 3) == 0) {
        #pragma unroll
        for (int mi = 0; mi < 2; mi++)
            #pragma unroll
            for (int h = 0; h < 2; h++) {
                int rloc = wm * 32 + mi * 16 + (lane >> 2) + h * 8;
                int grow = rowBase + rloc;
                size_t slot = ((size_t)z * SS + grow) * 16 + bx;
                g_pm[slot] = pm[mi][h];
                g_ps[slot] = rs_[rloc * 2] + rs_[rloc * 2 + 1];
            }
    }
}

// ---------------------------------------------------------------------------
// Stage 3: out = P @ vT; stats folded in prologue from per-tile partials.
// p = P_t * exp(m_t - m) * inv. grid (8, 16, 4)
// ---------------------------------------------------------------------------
__global__ void __launch_bounds__(256, 2) av_gemm(float* __restrict__ gout)
{
    extern __shared__ char smc[];
    unsigned smBase = smem_u32(smc);
    const int tid = threadIdx.x, lane = tid & 31, wid = tid >> 5;
    const int wm = wid & 3, wn = wid >> 2;
    const int z = blockIdx.z;
    const int by = 15 - blockIdx.y;            // long CTAs first
    const int rowBase = by * 128, colBase = blockIdx.x * 128;
    const int kTiles = (by + 1) * 4;
    const int nt = by + 1;

    const fp16* Bv = g_vT + (size_t)z * EE * SS;

    const int r = tid >> 1, ch = (tid & 1) * 16;
    const int grow = rowBase + r;
    const fp16* prow = g_p + ((size_t)z * SS + grow) * SS + ch;
    const float* pmrow = g_pm + ((size_t)z * SS + grow) * 16;
    const float* psrow = g_ps + ((size_t)z * SS + grow) * 16;

    // fold per-tile partials -> row stats
    float rm = -1e30f;
    for (int t = 0; t < nt; t++) rm = fmaxf(rm, pmrow[t]);
    float s = 0.0f;
    for (int t = 0; t < nt; t++) s += psrow[t] * __expf(pmrow[t] - rm);
    const float rinv = 1.0f / s;

    auto load_B = [&](int buf, int kt) {
        const unsigned dstb = smBase + buf * STAGE1 + TILE_B;
        const char* sB = (const char*)(Bv + (size_t)colBase * SS + kt);
        const size_t str = (size_t)SS * 2;
        #pragma unroll
        for (int i = 0; i < 2; i++) {
            int within = tid + i * 256;
            int row = within >> 2, c = within & 3;
            cp16(dstb + SWOFF(row, c), sB + row * str + c * 16);
        }
    };
    uint4 sregu[2];
    float fcorr;
    auto ldg_A = [&](int kt) {
        const fp16* s0 = prow + kt;
        sregu[0] = *(const uint4*)(s0);
        sregu[1] = *(const uint4*)(s0 + 8);
        fcorr = pmrow[kt >> 7];
    };
    auto sts_A = [&](int buf) {
        char* base = smc + buf * STAGE1;
        const int sw = ((r >> 1) & 3);
        const float f = __expf(fcorr - rm) * rinv;
        const unsigned* pw = (const unsigned*)sregu;
        #pragma unroll
        for (int j = 0; j < 4; j++) {
            float2 a0 = __half22float2(*(const __half2*)&pw[j * 2]);
            float2 a1 = __half22float2(*(const __half2*)&pw[j * 2 + 1]);
            fp16 h0 = __float2half(a0.x * f), h1 = __float2half(a0.y * f);
            fp16 h2 = __float2half(a1.x * f), h3 = __float2half(a1.y * f);
            int ccb = ch + j * 4;
            int unit = ccb >> 3;
            int boff = r * 64 + ((unit ^ sw) << 4) + (ccb & 7) * 2;
            *(__half2*)(base + boff)     = __halves2half2(h0, h1);
            *(__half2*)(base + boff + 4) = __halves2half2(h2, h3);
        }
    };

    float acc[2][8][4] = {};

    load_B(0, 0);
    cp_commit();
    ldg_A(0);
    if (kTiles > 1) {
        load_B(1, 32);
        cp_commit();
    }

    int buf = 0;
    for (int it = 0; it < kTiles; ++it) {
        sts_A(buf);
        if (it + 1 < kTiles) cp_wait1(); else cp_wait0();
        __syncthreads();
        if (it + 2 < kTiles) {
            int nb = buf + 2; if (nb >= NSTAGE) nb -= NSTAGE;
            load_B(nb, (it + 2) << 5);
            cp_commit();
        }
        if (it + 1 < kTiles) ldg_A((it + 1) << 5);
        compute_1p(smBase, buf, wm, wn, lane, acc);
        if (++buf == NSTAGE) buf = 0;
    }

    float* out = gout + (size_t)z * SS * EE;
    #pragma unroll
    for (int mi = 0; mi < 2; mi++)
        #pragma unroll
        for (int ni = 0; ni < 8; ni++) {
            int col = colBase + wn * 64 + ni * 8 + (lane & 3) * 2;
            #pragma unroll
            for (int h = 0; h < 2; h++) {
                int row = rowBase + wm * 32 + mi * 16 + (lane >> 2) + h * 8;
                *(float2*)(out + (size_t)row * EE + col) =
                    make_float2(acc[mi][ni][2 * h], acc[mi][ni][2 * h + 1]);
            }
        }
}

// ---------------------------------------------------------------------------
// Launch
// ---------------------------------------------------------------------------
extern "C" void kernel_launch(void* const* d_in, const int* in_sizes, int n_in,
                              void* d_out, int out_size)
{
    const float* x  = (const float*)d_in[0];
    const float* Wq = (const float*)d_in[2];
    const float* bq = (const float*)d_in[3];
    const float* Wk = (const float*)d_in[4];
    const float* bk = (const float*)d_in[5];
    const float* Wv = (const float*)d_in[6];
    const float* bv = (const float*)d_in[7];
    float* out = (float*)d_out;

    static bool attr_done = false;
    if (!attr_done) {
        cudaFuncSetAttribute(qkv_gemm,    cudaFuncAttributeMaxDynamicSharedMemorySize, SMEM1);
        cudaFuncSetAttribute(scores_gemm, cudaFuncAttributeMaxDynamicSharedMemorySize, SMEM1);
        cudaFuncSetAttribute(av_gemm,     cudaFuncAttributeMaxDynamicSharedMemorySize, SMEM1);
        attr_done = true;
    }

    const int splitBlocks = (BB * SS * EE / 4 + 3 * (EE * EE / 4)) / 256;
    split_all<<<splitBlocks, 256>>>(x, Wq, Wk, Wv);

    qkv_gemm<<<dim3(EE / 128, (BB * SS) / 128, 3), 256, SMEM1>>>(bq, bk, bv);

    scores_gemm<<<dim3(136, 1, BB), 256, SMEM1>>>();

    av_gemm<<<dim3(EE / 128, SS / 128, BB), 256, SMEM1>>>(out);
}

// round 16
// speedup vs baseline: 2.6382x; 1.0016x over previous
#include <cuda_runtime.h>
#include <cuda_fp16.h>

#define BB 4
#define SS 2048
#define EE 1024

typedef __half fp16;

// ---------------------------------------------------------------------------
// Scratch (device globals — no allocation allowed)
// ---------------------------------------------------------------------------
__device__ float g_pm[(size_t)BB * SS * 16], g_ps[(size_t)BB * SS * 16];
__device__ fp16 g_p[(size_t)BB * SS * SS];          // P_t = exp(s - m_tile), fp16
__device__ fp16 g_x[(size_t)BB * SS * EE];
__device__ fp16 g_Wf[3 * (size_t)EE * EE];
__device__ fp16 g_q[(size_t)BB * SS * EE];
__device__ fp16 g_k[(size_t)BB * SS * EE];
__device__ fp16 g_vT[(size_t)BB * EE * SS];

// ---------------------------------------------------------------------------
// PTX helpers (baseline sm_80+ features only — plain sm_103 target)
// ---------------------------------------------------------------------------
__device__ __forceinline__ unsigned smem_u32(const void* p) {
    unsigned a;
    asm("{ .reg .u64 t; cvta.to.shared.u64 t, %1; cvt.u32.u64 %0, t; }"
        : "=r"(a) : "l"(p));
    return a;
}
__device__ __forceinline__ void cp16(unsigned dst, const void* src) {
    asm volatile("cp.async.cg.shared.global [%0], [%1], 16;"
                 :: "r"(dst), "l"(src) : "memory");
}
__device__ __forceinline__ void cp_commit() {
    asm volatile("cp.async.commit_group;" ::: "memory");
}
__device__ __forceinline__ void cp_wait1() {
    asm volatile("cp.async.wait_group 1;" ::: "memory");
}
__device__ __forceinline__ void cp_wait0() {
    asm volatile("cp.async.wait_group 0;" ::: "memory");
}
__device__ __forceinline__ void ldsm4(unsigned& r0, unsigned& r1, unsigned& r2,
                                      unsigned& r3, unsigned addr) {
    asm volatile("ldmatrix.sync.aligned.m8n8.x4.shared.b16 {%0,%1,%2,%3}, [%4];"
                 : "=r"(r0), "=r"(r1), "=r"(r2), "=r"(r3) : "r"(addr));
}
__device__ __forceinline__ void mma16816(float* d, const unsigned* a,
                                         unsigned b0, unsigned b1) {
    asm volatile(
        "mma.sync.aligned.m16n8k16.row.col.f32.f16.f16.f32 "
        "{%0,%1,%2,%3}, {%4,%5,%6,%7}, {%8,%9}, {%0,%1,%2,%3};"
        : "+f"(d[0]), "+f"(d[1]), "+f"(d[2]), "+f"(d[3])
        : "r"(a[0]), "r"(a[1]), "r"(a[2]), "r"(a[3]), "r"(b0), "r"(b1));
}

// ---------------------------------------------------------------------------
// Tile: 128 rows x 32 fp16 = 64B rows, XOR-swizzled 16B units.
// Per stage: 2 tiles [A, B] = 16KB. 3 stages = 48KB.
// ---------------------------------------------------------------------------
#define TILE_B 8192
#define NSTAGE 3
#define STAGE1 (2 * TILE_B)
#define SMEM1 (NSTAGE * STAGE1)             // 49152
#define SWOFF(row, c) ((row) * 64 + (((c) ^ (((row) >> 1) & 3)) << 4))

// ---- compute: acc += A * B ------------------------------------------------
__device__ __forceinline__ void compute_1p(unsigned smBase, int buf,
                                           int wm, int wn, int lane,
                                           float acc[2][8][4])
{
    const unsigned tb = smBase + buf * STAGE1;
    const int lrow = lane & 15;
    const int lcu = lane >> 4;
    #pragma unroll
    for (int ks = 0; ks < 2; ks++) {
        const int cu = ks * 2 + lcu;
        unsigned a[2][4], b[4][4];
        #pragma unroll
        for (int mi = 0; mi < 2; mi++) {
            int row = wm * 32 + mi * 16 + lrow;
            ldsm4(a[mi][0], a[mi][1], a[mi][2], a[mi][3],
                  tb + SWOFF(row, cu));
        }
        #pragma unroll
        for (int nj = 0; nj < 4; nj++) {
            int row = wn * 64 + nj * 16 + lrow;
            ldsm4(b[nj][0], b[nj][1], b[nj][2], b[nj][3],
                  tb + TILE_B + SWOFF(row, cu));
        }
        #pragma unroll
        for (int mi = 0; mi < 2; mi++)
            #pragma unroll
            for (int nj = 0; nj < 4; nj++) {
                mma16816(acc[mi][2 * nj],     a[mi], b[nj][0], b[nj][2]);
                mma16816(acc[mi][2 * nj + 1], a[mi], b[nj][1], b[nj][3]);
            }
    }
}

// ---- loader ---------------------------------------------------------------
__device__ __forceinline__ void load_1p(unsigned smBase, int buf,
    const fp16* A, int lda, const fp16* B, int ldb,
    int rowBase, int colBase, int kt, int tid)
{
    const unsigned dstb = smBase + buf * STAGE1;
    const char* srcA = (const char*)(A + (size_t)rowBase * lda + kt);
    const char* srcB = (const char*)(B + (size_t)colBase * ldb + kt);
    const size_t strA = (size_t)lda * 2, strB = (size_t)ldb * 2;
    #pragma unroll
    for (int i = 0; i < 4; i++) {
        const int tile = i >> 1;
        int within = tid + (i & 1) * 256;
        int row = within >> 2, c = within & 3;
        const char* src = (tile == 0) ? srcA + row * strA + c * 16
                                      : srcB + row * strB + c * 16;
        cp16(dstb + tile * TILE_B + SWOFF(row, c), src);
    }
}

// ---- mainloop: 3-stage pipeline, ONE barrier per k-iter --------------------
__device__ __forceinline__ void mainloop_1p(
    const fp16* __restrict__ A, int lda, const fp16* __restrict__ B, int ldb,
    int kEnd, int rowBase, int colBase, unsigned smBase, float acc[2][8][4])
{
    const int tid = threadIdx.x;
    const int lane = tid & 31, wid = tid >> 5;
    const int wm = wid & 3, wn = wid >> 2;
    const int kTiles = kEnd >> 5;

    load_1p(smBase, 0, A, lda, B, ldb, rowBase, colBase, 0, tid);
    cp_commit();
    if (kTiles > 1) {
        load_1p(smBase, 1, A, lda, B, ldb, rowBase, colBase, 32, tid);
        cp_commit();
    }
    int buf = 0;
    for (int it = 0; it < kTiles; ++it) {
        if (it + 1 < kTiles) cp_wait1(); else cp_wait0();
        __syncthreads();
        if (it + 2 < kTiles) {
            int nb = buf + 2; if (nb >= NSTAGE) nb -= NSTAGE;
            load_1p(smBase, nb, A, lda, B, ldb, rowBase, colBase,
                    (it + 2) << 5, tid);
            cp_commit();
        }
        compute_1p(smBase, buf, wm, wn, lane, acc);
        if (++buf == NSTAGE) buf = 0;
    }
}

// ---------------------------------------------------------------------------
// Stage 0: round x and Wq/Wk/Wv to fp16
// ---------------------------------------------------------------------------
__global__ void split_all(const float* __restrict__ x,
                          const float* __restrict__ Wq,
                          const float* __restrict__ Wk,
                          const float* __restrict__ Wv)
{
    const size_t NX4 = (size_t)BB * SS * EE / 4;
    const size_t NW4 = (size_t)EE * EE / 4;
    size_t i4 = (size_t)blockIdx.x * 256 + threadIdx.x;
    const float* src;
    fp16* dst;
    size_t off;
    if (i4 < NX4) {
        off = i4 * 4;
        src = x;
        dst = g_x + off;
    } else {
        size_t j = i4 - NX4;
        int w = (int)(j / NW4);
        off = (j - (size_t)w * NW4) * 4;
        src = (w == 0) ? Wq : (w == 1) ? Wk : Wv;
        dst = g_Wf + (size_t)w * EE * EE + off;
    }
    float4 v = *(const float4*)(src + off);
    *(__half2*)(dst)     = __halves2half2(__float2half(v.x), __float2half(v.y));
    *(__half2*)(dst + 2) = __halves2half2(__float2half(v.z), __float2half(v.w));
}

// ---------------------------------------------------------------------------
// Stage 1: QKV projections, single-pass fp16. grid (8, 64, 3)
// z==0 -> g_q (scaled 1/32); z==1 -> g_k; z==2 -> g_vT (transposed in smem).
// ---------------------------------------------------------------------------
__global__ void __launch_bounds__(256, 2) qkv_gemm(
    const float* __restrict__ bq, const float* __restrict__ bk,
    const float* __restrict__ bv)
{
    extern __shared__ char smc[];
    unsigned smBase = smem_u32(smc);
    const int tid = threadIdx.x, lane = tid & 31, wid = tid >> 5;
    const int wm = wid & 3, wn = wid >> 2;
    const int z = blockIdx.z;
    const int rowBase = blockIdx.y * 128, colBase = blockIdx.x * 128;

    const fp16* Bf = g_Wf + (size_t)z * EE * EE;
    const float* bias = (z == 0) ? bq : (z == 1) ? bk : bv;
    const float alpha = (z == 0) ? 0.03125f : 1.0f;

    float acc[2][8][4] = {};
    mainloop_1p(g_x, EE, Bf, EE, EE, rowBase, colBase, smBase, acc);

    if (z < 2) {
        fp16* o = (z == 0) ? g_q : g_k;
        #pragma unroll
        for (int mi = 0; mi < 2; mi++)
            #pragma unroll
            for (int ni = 0; ni < 8; ni++) {
                int col = colBase + wn * 64 + ni * 8 + (lane & 3) * 2;
                float b0 = bias[col], b1 = bias[col + 1];
                #pragma unroll
                for (int h = 0; h < 2; h++) {
                    int row = rowBase + wm * 32 + mi * 16 + (lane >> 2) + h * 8;
                    float y0 = (acc[mi][ni][2 * h]     + b0) * alpha;
                    float y1 = (acc[mi][ni][2 * h + 1] + b1) * alpha;
                    size_t off = (size_t)row * EE + col;
                    *(__half2*)(o + off) =
                        __halves2half2(__float2half(y0), __float2half(y1));
                }
            }
    } else {
        // v: stage transposed tile in smem (pitch 136 fp16), write g_vT coalesced
        __syncthreads();
        fp16* st = (fp16*)smc;                  // [128 cols][136]
        #pragma unroll
        for (int mi = 0; mi < 2; mi++)
            #pragma unroll
            for (int ni = 0; ni < 8; ni++) {
                int cloc = wn * 64 + ni * 8 + (lane & 3) * 2;
                float b0 = bias[colBase + cloc], b1 = bias[colBase + cloc + 1];
                #pragma unroll
                for (int h = 0; h < 2; h++) {
                    int rloc = wm * 32 + mi * 16 + (lane >> 2) + h * 8;
                    st[cloc * 136 + rloc]       = __float2half(acc[mi][ni][2 * h]     + b0);
                    st[(cloc + 1) * 136 + rloc] = __float2half(acc[mi][ni][2 * h + 1] + b1);
                }
            }
        __syncthreads();
        const int c = tid >> 1, half = (tid & 1) * 64;
        int bidx = rowBase >> 11;
        int sBase = rowBase & (SS - 1);
        fp16* vrow = g_vT + ((size_t)bidx * EE + colBase + c) * SS + sBase + half;
        const fp16* srow = st + c * 136 + half;
        #pragma unroll
        for (int j = 0; j < 8; j++)
            *(uint4*)(vrow + j * 8) = *(const uint4*)(srow + j * 8);
    }
}

// ---------------------------------------------------------------------------
// Stage 2: scores -> fp16 P_t = exp(s - m_tile) + per-tile partials (m_t, sum_t)
// grid (136, 1, 4)
// ---------------------------------------------------------------------------
__global__ void __launch_bounds__(256, 2) scores_gemm()
{
    extern __shared__ char smc[];
    unsigned smBase = smem_u32(smc);
    const int tid = threadIdx.x, lane = tid & 31, wid = tid >> 5;
    const int wm = wid & 3, wn = wid >> 2;
    const int z = blockIdx.z;

    int idx = blockIdx.x;
    int by = (int)((sqrtf(8.0f * idx + 1.0f) - 1.0f) * 0.5f);
    while ((by + 1) * (by + 2) / 2 <= idx) by++;
    while (by * (by + 1) / 2 > idx) by--;
    int bx = idx - by * (by + 1) / 2;

    const int rowBase = by * 128, colBase = bx * 128;
    const bool diag = (bx == by);

    float acc[2][8][4] = {};
    mainloop_1p(g_q + (size_t)z * SS * EE, EE,
                g_k + (size_t)z * SS * EE, EE,
                EE, rowBase, colBase, smBase, acc);

    __syncthreads();
    float* rm_ = (float*)smc;              // [128][2]
    float* rs_ = (float*)(smc + 1024);     // [128][2]

    float pm[2][2];
    #pragma unroll
    for (int mi = 0; mi < 2; mi++)
        #pragma unroll
        for (int h = 0; h < 2; h++) {
            int rloc = wm * 32 + mi * 16 + (lane >> 2) + h * 8;
            float m = -1e30f;
            #pragma unroll
            for (int ni = 0; ni < 8; ni++)
                #pragma unroll
                for (int e = 0; e < 2; e++) {
                    int cloc = wn * 64 + ni * 8 + (lane & 3) * 2 + e;
                    float v = acc[mi][ni][2 * h + e];
                    bool ok = !diag || (cloc <= rloc);
                    m = ok ? fmaxf(m, v) : m;
                }
            m = fmaxf(m, __shfl_xor_sync(~0u, m, 1));
            m = fmaxf(m, __shfl_xor_sync(~0u, m, 2));
            pm[mi][h] = m;
        }
    #pragma unroll
    for (int mi = 0; mi < 2; mi++)
        #pragma unroll
        for (int h = 0; h < 2; h++) {
            int rloc = wm * 32 + mi * 16 + (lane >> 2) + h * 8;
            rm_[rloc * 2 + wn] = pm[mi][h];
        }
    __syncthreads();

    fp16* outP = g_p + (size_t)z * SS * SS;
    float psum[2][2];
    #pragma unroll
    for (int mi = 0; mi < 2; mi++)
        #pragma unroll
        for (int h = 0; h < 2; h++) {
            int rloc = wm * 32 + mi * 16 + (lane >> 2) + h * 8;
            int grow = rowBase + rloc;
            float m = fmaxf(rm_[rloc * 2], rm_[rloc * 2 + 1]);
            pm[mi][h] = m;
            float s = 0.0f;
            #pragma unroll
            for (int ni = 0; ni < 8; ni++) {
                int cloc = wn * 64 + ni * 8 + (lane & 3) * 2;
                float v0 = acc[mi][ni][2 * h], v1 = acc[mi][ni][2 * h + 1];
                bool ok0 = !diag || (cloc     <= rloc);
                bool ok1 = !diag || (cloc + 1 <= rloc);
                float e0 = ok0 ? __expf(v0 - m) : 0.0f;
                float e1 = ok1 ? __expf(v1 - m) : 0.0f;
                s += e0 + e1;
                *(__half2*)(outP + (size_t)grow * SS + colBase + cloc) =
                    __halves2half2(__float2half(e0), __float2half(e1));
            }
            s += __shfl_xor_sync(~0u, s, 1);
            s += __shfl_xor_sync(~0u, s, 2);
            psum[mi][h] = s;
        }
    #pragma unroll
    for (int mi = 0; mi < 2; mi++)
        #pragma unroll
        for (int h = 0; h < 2; h++) {
            int rloc = wm * 32 + mi * 16 + (lane >> 2) + h * 8;
            rs_[rloc * 2 + wn] = psum[mi][h];
        }
    __syncthreads();

    if (wn == 0 && (lane & 3) == 0) {
        #pragma unroll
        for (int mi = 0; mi < 2; mi++)
            #pragma unroll
            for (int h = 0; h < 2; h++) {
                int rloc = wm * 32 + mi * 16 + (lane >> 2) + h * 8;
                int grow = rowBase + rloc;
                size_t slot = ((size_t)z * SS + grow) * 16 + bx;
                g_pm[slot] = pm[mi][h];
                g_ps[slot] = rs_[rloc * 2] + rs_[rloc * 2 + 1];
            }
    }
}

// ---------------------------------------------------------------------------
// Stage 3: out = P @ vT; stats folded in prologue; vectorized P staging.
// p = P_t * exp(m_t - m) * inv. grid (8, 16, 4)
// ---------------------------------------------------------------------------
__global__ void __launch_bounds__(256, 2) av_gemm(float* __restrict__ gout)
{
    extern __shared__ char smc[];
    unsigned smBase = smem_u32(smc);
    const int tid = threadIdx.x, lane = tid & 31, wid = tid >> 5;
    const int wm = wid & 3, wn = wid >> 2;
    const int z = blockIdx.z;
    const int by = 15 - blockIdx.y;            // long CTAs first
    const int rowBase = by * 128, colBase = blockIdx.x * 128;
    const int kTiles = (by + 1) * 4;
    const int nt = by + 1;

    const fp16* Bv = g_vT + (size_t)z * EE * SS;

    const int r = tid >> 1, ch = (tid & 1) * 16;
    const int grow = rowBase + r;
    const fp16* prow = g_p + ((size_t)z * SS + grow) * SS + ch;
    const float* pmrow = g_pm + ((size_t)z * SS + grow) * 16;
    const float* psrow = g_ps + ((size_t)z * SS + grow) * 16;

    // fold per-tile partials -> row stats
    float rm = -1e30f;
    for (int t = 0; t < nt; t++) rm = fmaxf(rm, pmrow[t]);
    float s = 0.0f;
    for (int t = 0; t < nt; t++) s += psrow[t] * __expf(pmrow[t] - rm);
    const float rinv = 1.0f / s;

    auto load_B = [&](int buf, int kt) {
        const unsigned dstb = smBase + buf * STAGE1 + TILE_B;
        const char* sB = (const char*)(Bv + (size_t)colBase * SS + kt);
        const size_t str = (size_t)SS * 2;
        #pragma unroll
        for (int i = 0; i < 2; i++) {
            int within = tid + i * 256;
            int row = within >> 2, c = within & 3;
            cp16(dstb + SWOFF(row, c), sB + row * str + c * 16);
        }
    };
    uint4 sregu[2];
    float fcorr;
    auto ldg_A = [&](int kt) {
        const fp16* s0 = prow + kt;
        sregu[0] = *(const uint4*)(s0);
        sregu[1] = *(const uint4*)(s0 + 8);
        fcorr = pmrow[kt >> 7];
    };
    // Vectorized: each thread's 16 fp16 = two full 16B swizzle units of row r
    // -> 2x STS.128 instead of 8x STS.32.
    auto sts_A = [&](int buf) {
        char* base = smc + buf * STAGE1;
        const int sw = ((r >> 1) & 3);
        const float f = __expf(fcorr - rm) * rinv;
        #pragma unroll
        for (int u = 0; u < 2; u++) {
            const __half2* hp = (const __half2*)&sregu[u];
            unsigned w[4];
            #pragma unroll
            for (int j = 0; j < 4; j++) {
                float2 a = __half22float2(hp[j]);
                __half2 hh = __halves2half2(__float2half(a.x * f),
                                            __float2half(a.y * f));
                w[j] = *(unsigned*)&hh;
            }
            int unit = (ch >> 3) + u;
            int boff = r * 64 + ((unit ^ sw) << 4);
            *(uint4*)(base + boff) = make_uint4(w[0], w[1], w[2], w[3]);
        }
    };

    float acc[2][8][4] = {};

    load_B(0, 0);
    cp_commit();
    ldg_A(0);
    if (kTiles > 1) {
        load_B(1, 32);
        cp_commit();
    }

    int buf = 0;
    for (int it = 0; it < kTiles; ++it) {
        sts_A(buf);
        if (it + 1 < kTiles) cp_wait1(); else cp_wait0();
        __syncthreads();
        if (it + 2 < kTiles) {
            int nb = buf + 2; if (nb >= NSTAGE) nb -= NSTAGE;
            load_B(nb, (it + 2) << 5);
            cp_commit();
        }
        if (it + 1 < kTiles) ldg_A((it + 1) << 5);
        compute_1p(smBase, buf, wm, wn, lane, acc);
        if (++buf == NSTAGE) buf = 0;
    }

    float* out = gout + (size_t)z * SS * EE;
    #pragma unroll
    for (int mi = 0; mi < 2; mi++)
        #pragma unroll
        for (int ni = 0; ni < 8; ni++) {
            int col = colBase + wn * 64 + ni * 8 + (lane & 3) * 2;
            #pragma unroll
            for (int h = 0; h < 2; h++) {
                int row = rowBase + wm * 32 + mi * 16 + (lane >> 2) + h * 8;
                *(float2*)(out + (size_t)row * EE + col) =
                    make_float2(acc[mi][ni][2 * h], acc[mi][ni][2 * h + 1]);
            }
        }
}

// ---------------------------------------------------------------------------
// Launch
// ---------------------------------------------------------------------------
extern "C" void kernel_launch(void* const* d_in, const int* in_sizes, int n_in,
                              void* d_out, int out_size)
{
    const float* x  = (const float*)d_in[0];
    const float* Wq = (const float*)d_in[2];
    const float* bq = (const float*)d_in[3];
    const float* Wk = (const float*)d_in[4];
    const float* bk = (const float*)d_in[5];
    const float* Wv = (const float*)d_in[6];
    const float* bv = (const float*)d_in[7];
    float* out = (float*)d_out;

    static bool attr_done = false;
    if (!attr_done) {
        cudaFuncSetAttribute(qkv_gemm,    cudaFuncAttributeMaxDynamicSharedMemorySize, SMEM1);
        cudaFuncSetAttribute(scores_gemm, cudaFuncAttributeMaxDynamicSharedMemorySize, SMEM1);
        cudaFuncSetAttribute(av_gemm,     cudaFuncAttributeMaxDynamicSharedMemorySize, SMEM1);
        attr_done = true;
    }

    const int splitBlocks = (BB * SS * EE / 4 + 3 * (EE * EE / 4)) / 256;
    split_all<<<splitBlocks, 256>>>(x, Wq, Wk, Wv);

    qkv_gemm<<<dim3(EE / 128, (BB * SS) / 128, 3), 256, SMEM1>>>(bq, bk, bv);

    scores_gemm<<<dim3(136, 1, BB), 256, SMEM1>>>();

    av_gemm<<<dim3(EE / 128, SS / 128, BB), 256, SMEM1>>>(out);
}

// round 17
// speedup vs baseline: 2.6492x; 1.0042x over previous
#include <cuda_runtime.h>
#include <cuda_fp16.h>

#define BB 4
#define SS 2048
#define EE 1024

typedef __half fp16;

// ---------------------------------------------------------------------------
// Scratch (device globals — no allocation allowed)
// ---------------------------------------------------------------------------
__device__ float g_pm[(size_t)BB * SS * 16], g_ps[(size_t)BB * SS * 16];
__device__ fp16 g_p[(size_t)BB * SS * SS];          // P_t = exp(s - m_tile), fp16
__device__ fp16 g_x[(size_t)BB * SS * EE];
__device__ fp16 g_Wf[3 * (size_t)EE * EE];
__device__ fp16 g_q[(size_t)BB * SS * EE];
__device__ fp16 g_k[(size_t)BB * SS * EE];
__device__ fp16 g_vT[(size_t)BB * EE * SS];

// ---------------------------------------------------------------------------
// PTX helpers (baseline sm_80+ features only — plain sm_103 target)
// ---------------------------------------------------------------------------
__device__ __forceinline__ unsigned smem_u32(const void* p) {
    unsigned a;
    asm("{ .reg .u64 t; cvta.to.shared.u64 t, %1; cvt.u32.u64 %0, t; }"
        : "=r"(a) : "l"(p));
    return a;
}
__device__ __forceinline__ void cp16(unsigned dst, const void* src) {
    asm volatile("cp.async.cg.shared.global [%0], [%1], 16;"
                 :: "r"(dst), "l"(src) : "memory");
}
__device__ __forceinline__ void cp_commit() {
    asm volatile("cp.async.commit_group;" ::: "memory");
}
__device__ __forceinline__ void cp_wait1() {
    asm volatile("cp.async.wait_group 1;" ::: "memory");
}
__device__ __forceinline__ void cp_wait0() {
    asm volatile("cp.async.wait_group 0;" ::: "memory");
}
__device__ __forceinline__ void ldsm4(unsigned& r0, unsigned& r1, unsigned& r2,
                                      unsigned& r3, unsigned addr) {
    asm volatile("ldmatrix.sync.aligned.m8n8.x4.shared.b16 {%0,%1,%2,%3}, [%4];"
                 : "=r"(r0), "=r"(r1), "=r"(r2), "=r"(r3) : "r"(addr));
}
__device__ __forceinline__ void mma16816(float* d, const unsigned* a,
                                         unsigned b0, unsigned b1) {
    asm volatile(
        "mma.sync.aligned.m16n8k16.row.col.f32.f16.f16.f32 "
        "{%0,%1,%2,%3}, {%4,%5,%6,%7}, {%8,%9}, {%0,%1,%2,%3};"
        : "+f"(d[0]), "+f"(d[1]), "+f"(d[2]), "+f"(d[3])
        : "r"(a[0]), "r"(a[1]), "r"(a[2]), "r"(a[3]), "r"(b0), "r"(b1));
}

// ---------------------------------------------------------------------------
// Tile: rows x 32 fp16 = 64B rows, XOR-swizzled 16B units.
// GEMM stages (qkv/scores): [A(128), B(128)] = 16KB/stage, 3 stages = 48KB.
// AV stages: [A(128) 8KB, B(256) 16KB] = 24KB/stage, 3 stages = 72KB.
// ---------------------------------------------------------------------------
#define TILE_B 8192
#define NSTAGE 3
#define STAGE1 (2 * TILE_B)
#define SMEM1 (NSTAGE * STAGE1)             // 49152
#define TILE_BV 16384
#define STAGE_AV (TILE_B + TILE_BV)         // 24576
#define SMEM_AV (NSTAGE * STAGE_AV)         // 73728
#define SWOFF(row, c) ((row) * 64 + (((c) ^ (((row) >> 1) & 3)) << 4))

// ---- compute: acc += A * B (128x128 tile pair, 8 warps) --------------------
__device__ __forceinline__ void compute_1p(unsigned smBase, int buf,
                                           int wm, int wn, int lane,
                                           float acc[2][8][4])
{
    const unsigned tb = smBase + buf * STAGE1;
    const int lrow = lane & 15;
    const int lcu = lane >> 4;
    #pragma unroll
    for (int ks = 0; ks < 2; ks++) {
        const int cu = ks * 2 + lcu;
        unsigned a[2][4], b[4][4];
        #pragma unroll
        for (int mi = 0; mi < 2; mi++) {
            int row = wm * 32 + mi * 16 + lrow;
            ldsm4(a[mi][0], a[mi][1], a[mi][2], a[mi][3],
                  tb + SWOFF(row, cu));
        }
        #pragma unroll
        for (int nj = 0; nj < 4; nj++) {
            int row = wn * 64 + nj * 16 + lrow;
            ldsm4(b[nj][0], b[nj][1], b[nj][2], b[nj][3],
                  tb + TILE_B + SWOFF(row, cu));
        }
        #pragma unroll
        for (int mi = 0; mi < 2; mi++)
            #pragma unroll
            for (int nj = 0; nj < 4; nj++) {
                mma16816(acc[mi][2 * nj],     a[mi], b[nj][0], b[nj][2]);
                mma16816(acc[mi][2 * nj + 1], a[mi], b[nj][1], b[nj][3]);
            }
    }
}

// ---- compute for AV: A 128 rows, B 256 rows, 16 warps ----------------------
__device__ __forceinline__ void compute_av(unsigned smBase, int buf,
                                           int wm, int wn, int lane,
                                           float acc[2][8][4])
{
    const unsigned tb = smBase + buf * STAGE_AV;
    const int lrow = lane & 15;
    const int lcu = lane >> 4;
    #pragma unroll
    for (int ks = 0; ks < 2; ks++) {
        const int cu = ks * 2 + lcu;
        unsigned a[2][4], b[4][4];
        #pragma unroll
        for (int mi = 0; mi < 2; mi++) {
            int row = wm * 32 + mi * 16 + lrow;
            ldsm4(a[mi][0], a[mi][1], a[mi][2], a[mi][3],
                  tb + SWOFF(row, cu));
        }
        #pragma unroll
        for (int nj = 0; nj < 4; nj++) {
            int row = wn * 64 + nj * 16 + lrow;
            ldsm4(b[nj][0], b[nj][1], b[nj][2], b[nj][3],
                  tb + TILE_B + SWOFF(row, cu));
        }
        #pragma unroll
        for (int mi = 0; mi < 2; mi++)
            #pragma unroll
            for (int nj = 0; nj < 4; nj++) {
                mma16816(acc[mi][2 * nj],     a[mi], b[nj][0], b[nj][2]);
                mma16816(acc[mi][2 * nj + 1], a[mi], b[nj][1], b[nj][3]);
            }
    }
}

// ---- loader (qkv/scores) ----------------------------------------------------
__device__ __forceinline__ void load_1p(unsigned smBase, int buf,
    const fp16* A, int lda, const fp16* B, int ldb,
    int rowBase, int colBase, int kt, int tid)
{
    const unsigned dstb = smBase + buf * STAGE1;
    const char* srcA = (const char*)(A + (size_t)rowBase * lda + kt);
    const char* srcB = (const char*)(B + (size_t)colBase * ldb + kt);
    const size_t strA = (size_t)lda * 2, strB = (size_t)ldb * 2;
    #pragma unroll
    for (int i = 0; i < 4; i++) {
        const int tile = i >> 1;
        int within = tid + (i & 1) * 256;
        int row = within >> 2, c = within & 3;
        const char* src = (tile == 0) ? srcA + row * strA + c * 16
                                      : srcB + row * strB + c * 16;
        cp16(dstb + tile * TILE_B + SWOFF(row, c), src);
    }
}

// ---- mainloop (qkv/scores): 3-stage pipeline, ONE barrier per k-iter --------
__device__ __forceinline__ void mainloop_1p(
    const fp16* __restrict__ A, int lda, const fp16* __restrict__ B, int ldb,
    int kEnd, int rowBase, int colBase, unsigned smBase, float acc[2][8][4])
{
    const int tid = threadIdx.x;
    const int lane = tid & 31, wid = tid >> 5;
    const int wm = wid & 3, wn = wid >> 2;
    const int kTiles = kEnd >> 5;

    load_1p(smBase, 0, A, lda, B, ldb, rowBase, colBase, 0, tid);
    cp_commit();
    if (kTiles > 1) {
        load_1p(smBase, 1, A, lda, B, ldb, rowBase, colBase, 32, tid);
        cp_commit();
    }
    int buf = 0;
    for (int it = 0; it < kTiles; ++it) {
        if (it + 1 < kTiles) cp_wait1(); else cp_wait0();
        __syncthreads();
        if (it + 2 < kTiles) {
            int nb = buf + 2; if (nb >= NSTAGE) nb -= NSTAGE;
            load_1p(smBase, nb, A, lda, B, ldb, rowBase, colBase,
                    (it + 2) << 5, tid);
            cp_commit();
        }
        compute_1p(smBase, buf, wm, wn, lane, acc);
        if (++buf == NSTAGE) buf = 0;
    }
}

// ---------------------------------------------------------------------------
// Stage 0: round x and Wq/Wk/Wv to fp16
// ---------------------------------------------------------------------------
__global__ void split_all(const float* __restrict__ x,
                          const float* __restrict__ Wq,
                          const float* __restrict__ Wk,
                          const float* __restrict__ Wv)
{
    const size_t NX4 = (size_t)BB * SS * EE / 4;
    const size_t NW4 = (size_t)EE * EE / 4;
    size_t i4 = (size_t)blockIdx.x * 256 + threadIdx.x;
    const float* src;
    fp16* dst;
    size_t off;
    if (i4 < NX4) {
        off = i4 * 4;
        src = x;
        dst = g_x + off;
    } else {
        size_t j = i4 - NX4;
        int w = (int)(j / NW4);
        off = (j - (size_t)w * NW4) * 4;
        src = (w == 0) ? Wq : (w == 1) ? Wk : Wv;
        dst = g_Wf + (size_t)w * EE * EE + off;
    }
    float4 v = *(const float4*)(src + off);
    *(__half2*)(dst)     = __halves2half2(__float2half(v.x), __float2half(v.y));
    *(__half2*)(dst + 2) = __halves2half2(__float2half(v.z), __float2half(v.w));
}

// ---------------------------------------------------------------------------
// Stage 1: QKV projections, single-pass fp16. grid (8, 64, 3)
// z==0 -> g_q (scaled 1/32); z==1 -> g_k; z==2 -> g_vT (transposed in smem).
// ---------------------------------------------------------------------------
__global__ void __launch_bounds__(256, 2) qkv_gemm(
    const float* __restrict__ bq, const float* __restrict__ bk,
    const float* __restrict__ bv)
{
    extern __shared__ char smc[];
    unsigned smBase = smem_u32(smc);
    const int tid = threadIdx.x, lane = tid & 31, wid = tid >> 5;
    const int wm = wid & 3, wn = wid >> 2;
    const int z = blockIdx.z;
    const int rowBase = blockIdx.y * 128, colBase = blockIdx.x * 128;

    const fp16* Bf = g_Wf + (size_t)z * EE * EE;
    const float* bias = (z == 0) ? bq : (z == 1) ? bk : bv;
    const float alpha = (z == 0) ? 0.03125f : 1.0f;

    float acc[2][8][4] = {};
    mainloop_1p(g_x, EE, Bf, EE, EE, rowBase, colBase, smBase, acc);

    if (z < 2) {
        fp16* o = (z == 0) ? g_q : g_k;
        #pragma unroll
        for (int mi = 0; mi < 2; mi++)
            #pragma unroll
            for (int ni = 0; ni < 8; ni++) {
                int col = colBase + wn * 64 + ni * 8 + (lane & 3) * 2;
                float b0 = bias[col], b1 = bias[col + 1];
                #pragma unroll
                for (int h = 0; h < 2; h++) {
                    int row = rowBase + wm * 32 + mi * 16 + (lane >> 2) + h * 8;
                    float y0 = (acc[mi][ni][2 * h]     + b0) * alpha;
                    float y1 = (acc[mi][ni][2 * h + 1] + b1) * alpha;
                    size_t off = (size_t)row * EE + col;
                    *(__half2*)(o + off) =
                        __halves2half2(__float2half(y0), __float2half(y1));
                }
            }
    } else {
        __syncthreads();
        fp16* st = (fp16*)smc;                  // [128 cols][136]
        #pragma unroll
        for (int mi = 0; mi < 2; mi++)
            #pragma unroll
            for (int ni = 0; ni < 8; ni++) {
                int cloc = wn * 64 + ni * 8 + (lane & 3) * 2;
                float b0 = bias[colBase + cloc], b1 = bias[colBase + cloc + 1];
                #pragma unroll
                for (int h = 0; h < 2; h++) {
                    int rloc = wm * 32 + mi * 16 + (lane >> 2) + h * 8;
                    st[cloc * 136 + rloc]       = __float2half(acc[mi][ni][2 * h]     + b0);
                    st[(cloc + 1) * 136 + rloc] = __float2half(acc[mi][ni][2 * h + 1] + b1);
                }
            }
        __syncthreads();
        const int c = tid >> 1, half = (tid & 1) * 64;
        int bidx = rowBase >> 11;
        int sBase = rowBase & (SS - 1);
        fp16* vrow = g_vT + ((size_t)bidx * EE + colBase + c) * SS + sBase + half;
        const fp16* srow = st + c * 136 + half;
        #pragma unroll
        for (int j = 0; j < 8; j++)
            *(uint4*)(vrow + j * 8) = *(const uint4*)(srow + j * 8);
    }
}

// ---------------------------------------------------------------------------
// Stage 2: scores -> fp16 P_t = exp(s - m_tile) + per-tile partials (m_t, sum_t)
// grid (136, 1, 4)
// ---------------------------------------------------------------------------
__global__ void __launch_bounds__(256, 2) scores_gemm()
{
    extern __shared__ char smc[];
    unsigned smBase = smem_u32(smc);
    const int tid = threadIdx.x, lane = tid & 31, wid = tid >> 5;
    const int wm = wid & 3, wn = wid >> 2;
    const int z = blockIdx.z;

    int idx = blockIdx.x;
    int by = (int)((sqrtf(8.0f * idx + 1.0f) - 1.0f) * 0.5f);
    while ((by + 1) * (by + 2) / 2 <= idx) by++;
    while (by * (by + 1) / 2 > idx) by--;
    int bx = idx - by * (by + 1) / 2;

    const int rowBase = by * 128, colBase = bx * 128;
    const bool diag = (bx == by);

    float acc[2][8][4] = {};
    mainloop_1p(g_q + (size_t)z * SS * EE, EE,
                g_k + (size_t)z * SS * EE, EE,
                EE, rowBase, colBase, smBase, acc);

    __syncthreads();
    float* rm_ = (float*)smc;
    float* rs_ = (float*)(smc + 1024);

    float pm[2][2];
    #pragma unroll
    for (int mi = 0; mi < 2; mi++)
        #pragma unroll
        for (int h = 0; h < 2; h++) {
            int rloc = wm * 32 + mi * 16 + (lane >> 2) + h * 8;
            float m = -1e30f;
            #pragma unroll
            for (int ni = 0; ni < 8; ni++)
                #pragma unroll
                for (int e = 0; e < 2; e++) {
                    int cloc = wn * 64 + ni * 8 + (lane & 3) * 2 + e;
                    float v = acc[mi][ni][2 * h + e];
                    bool ok = !diag || (cloc <= rloc);
                    m = ok ? fmaxf(m, v) : m;
                }
            m = fmaxf(m, __shfl_xor_sync(~0u, m, 1));
            m = fmaxf(m, __shfl_xor_sync(~0u, m, 2));
            pm[mi][h] = m;
        }
    #pragma unroll
    for (int mi = 0; mi < 2; mi++)
        #pragma unroll
        for (int h = 0; h < 2; h++) {
            int rloc = wm * 32 + mi * 16 + (lane >> 2) + h * 8;
            rm_[rloc * 2 + wn] = pm[mi][h];
        }
    __syncthreads();

    fp16* outP = g_p + (size_t)z * SS * SS;
    float psum[2][2];
    #pragma unroll
    for (int mi = 0; mi < 2; mi++)
        #pragma unroll
        for (int h = 0; h < 2; h++) {
            int rloc = wm * 32 + mi * 16 + (lane >> 2) + h * 8;
            int grow = rowBase + rloc;
            float m = fmaxf(rm_[rloc * 2], rm_[rloc * 2 + 1]);
            pm[mi][h] = m;
            float s = 0.0f;
            #pragma unroll
            for (int ni = 0; ni < 8; ni++) {
                int cloc = wn * 64 + ni * 8 + (lane & 3) * 2;
                float v0 = acc[mi][ni][2 * h], v1 = acc[mi][ni][2 * h + 1];
                bool ok0 = !diag || (cloc     <= rloc);
                bool ok1 = !diag || (cloc + 1 <= rloc);
                float e0 = ok0 ? __expf(v0 - m) : 0.0f;
                float e1 = ok1 ? __expf(v1 - m) : 0.0f;
                s += e0 + e1;
                *(__half2*)(outP + (size_t)grow * SS + colBase + cloc) =
                    __halves2half2(__float2half(e0), __float2half(e1));
            }
            s += __shfl_xor_sync(~0u, s, 1);
            s += __shfl_xor_sync(~0u, s, 2);
            psum[mi][h] = s;
        }
    #pragma unroll
    for (int mi = 0; mi < 2; mi++)
        #pragma unroll
        for (int h = 0; h < 2; h++) {
            int rloc = wm * 32 + mi * 16 + (lane >> 2) + h * 8;
            rs_[rloc * 2 + wn] = psum[mi][h];
        }
    __syncthreads();

    if (wn == 0 && (lane & 3) == 0) {
        #pragma unroll
        for (int mi = 0; mi < 2; mi++)
            #pragma unroll
            for (int h = 0; h < 2; h++) {
                int rloc = wm * 32 + mi * 16 + (lane >> 2) + h * 8;
                int grow = rowBase + rloc;
                size_t slot = ((size_t)z * SS + grow) * 16 + bx;
                g_pm[slot] = pm[mi][h];
                g_ps[slot] = rs_[rloc * 2] + rs_[rloc * 2 + 1];
            }
    }
}

// ---------------------------------------------------------------------------
// Stage 3: out = P @ vT, 512 threads, BN=256. grid (4, 16, 4)
// Warps 4(M) x 4(N), each 32x64. P staged once per CTA (halved overhead/MMA).
// ---------------------------------------------------------------------------
__global__ void __launch_bounds__(512, 1) av_gemm(float* __restrict__ gout)
{
    extern __shared__ char smc[];
    unsigned smBase = smem_u32(smc);
    const int tid = threadIdx.x, lane = tid & 31, wid = tid >> 5;
    const int wm = wid & 3, wn = wid >> 2;      // wn 0..3 over 256 cols
    const int z = blockIdx.z;
    const int by = 15 - blockIdx.y;             // long CTAs first
    const int rowBase = by * 128, colBase = blockIdx.x * 256;
    const int kTiles = (by + 1) * 4;
    const int nt = by + 1;

    const fp16* Bv = g_vT + (size_t)z * EE * SS;

    // P staging: 128 rows x 32 cols by 512 threads -> 1 x 16B unit each
    const int r = tid >> 2, cu_ = tid & 3;      // row, 16B-unit (8 fp16)
    const int grow = rowBase + r;
    const fp16* prow = g_p + ((size_t)z * SS + grow) * SS + cu_ * 8;
    const float* pmrow = g_pm + ((size_t)z * SS + grow) * 16;
    const float* psrow = g_ps + ((size_t)z * SS + grow) * 16;

    float rm = -1e30f;
    for (int t = 0; t < nt; t++) rm = fmaxf(rm, pmrow[t]);
    float s = 0.0f;
    for (int t = 0; t < nt; t++) s += psrow[t] * __expf(pmrow[t] - rm);
    const float rinv = 1.0f / s;

    auto load_B = [&](int buf, int kt) {
        const unsigned dstb = smBase + buf * STAGE_AV + TILE_B;
        const char* sB = (const char*)(Bv + (size_t)colBase * SS + kt);
        const size_t str = (size_t)SS * 2;
        #pragma unroll
        for (int i = 0; i < 2; i++) {
            int within = tid + i * 512;
            int row = within >> 2, c = within & 3;
            cp16(dstb + SWOFF(row, c), sB + row * str + c * 16);
        }
    };
    uint4 sregu;
    float fcorr;
    auto ldg_A = [&](int kt) {
        sregu = *(const uint4*)(prow + kt);
        fcorr = pmrow[kt >> 7];
    };
    auto sts_A = [&](int buf) {
        char* base = smc + buf * STAGE_AV;
        const int sw = ((r >> 1) & 3);
        const float f = __expf(fcorr - rm) * rinv;
        const __half2* hp = (const __half2*)&sregu;
        unsigned w[4];
        #pragma unroll
        for (int j = 0; j < 4; j++) {
            float2 a = __half22float2(hp[j]);
            __half2 hh = __halves2half2(__float2half(a.x * f),
                                        __float2half(a.y * f));
            w[j] = *(unsigned*)&hh;
        }
        int boff = r * 64 + ((cu_ ^ sw) << 4);
        *(uint4*)(base + boff) = make_uint4(w[0], w[1], w[2], w[3]);
    };

    float acc[2][8][4] = {};

    load_B(0, 0);
    cp_commit();
    ldg_A(0);
    if (kTiles > 1) {
        load_B(1, 32);
        cp_commit();
    }

    int buf = 0;
    for (int it = 0; it < kTiles; ++it) {
        sts_A(buf);
        if (it + 1 < kTiles) cp_wait1(); else cp_wait0();
        __syncthreads();
        if (it + 2 < kTiles) {
            int nb = buf + 2; if (nb >= NSTAGE) nb -= NSTAGE;
            load_B(nb, (it + 2) << 5);
            cp_commit();
        }
        if (it + 1 < kTiles) ldg_A((it + 1) << 5);
        compute_av(smBase, buf, wm, wn, lane, acc);
        if (++buf == NSTAGE) buf = 0;
    }

    float* out = gout + (size_t)z * SS * EE;
    #pragma unroll
    for (int mi = 0; mi < 2; mi++)
        #pragma unroll
        for (int ni = 0; ni < 8; ni++) {
            int col = colBase + wn * 64 + ni * 8 + (lane & 3) * 2;
            #pragma unroll
            for (int h = 0; h < 2; h++) {
                int row = rowBase + wm * 32 + mi * 16 + (lane >> 2) + h * 8;
                *(float2*)(out + (size_t)row * EE + col) =
                    make_float2(acc[mi][ni][2 * h], acc[mi][ni][2 * h + 1]);
            }
        }
}

// ---------------------------------------------------------------------------
// Launch
// ---------------------------------------------------------------------------
extern "C" void kernel_launch(void* const* d_in, const int* in_sizes, int n_in,
                              void* d_out, int out_size)
{
    const float* x  = (const float*)d_in[0];
    const float* Wq = (const float*)d_in[2];
    const float* bq = (const float*)d_in[3];
    const float* Wk = (const float*)d_in[4];
    const float* bk = (const float*)d_in[5];
    const float* Wv = (const float*)d_in[6];
    const float* bv = (const float*)d_in[7];
    float* out = (float*)d_out;

    static bool attr_done = false;
    if (!attr_done) {
        cudaFuncSetAttribute(qkv_gemm,    cudaFuncAttributeMaxDynamicSharedMemorySize, SMEM1);
        cudaFuncSetAttribute(scores_gemm, cudaFuncAttributeMaxDynamicSharedMemorySize, SMEM1);
        cudaFuncSetAttribute(av_gemm,     cudaFuncAttributeMaxDynamicSharedMemorySize, SMEM_AV);
        attr_done = true;
    }

    const int splitBlocks = (BB * SS * EE / 4 + 3 * (EE * EE / 4)) / 256;
    split_all<<<splitBlocks, 256>>>(x, Wq, Wk, Wv);

    qkv_gemm<<<dim3(EE / 128, (BB * SS) / 128, 3), 256, SMEM1>>>(bq, bk, bv);

    scores_gemm<<<dim3(136, 1, BB), 256, SMEM1>>>();

    av_gemm<<<dim3(EE / 256, SS / 128, BB), 512, SMEM_AV>>>(out);
}